// round 7
// baseline (speedup 1.0000x reference)
#include <cuda_runtime.h>
#include <cuda_bf16.h>
#include <math.h>
#include <stdint.h>

// Problem constants (fixed shapes from the reference)
#define Bdim 4
#define Hdim 8
#define Tdim 512
#define Ddim 512
#define DhD  64
#define NL   64     // number of lag candidates
#define KTOP 18     // top-k lags = 2*ceil(log2(512)) = 18
#define NSLOT 19    // 1 (lag 0 / instantaneous) + KTOP
#define BH   (Bdim*Hdim)

// lags for T=512, LMAX=64: step=7 -> 1,8,...,442 then last forced to 511
__device__ __forceinline__ int lag_of(int l) { return (l == NL-1) ? (Tdim-1) : (1 + 7*l); }

// ---------------- mma.sync helpers (sm_80-era, compiles at compute_103) ------
__device__ __forceinline__ uint32_t smem_u32(const void* p) {
    uint32_t a;
    asm("{ .reg .u64 t; cvta.to.shared.u64 t, %1; cvt.u32.u64 %0, t; }" : "=r"(a) : "l"(p));
    return a;
}
__device__ __forceinline__ void ldsm4(uint32_t r[4], uint32_t addr) {
    asm volatile("ldmatrix.sync.aligned.m8n8.x4.shared.b16 {%0,%1,%2,%3}, [%4];"
        : "=r"(r[0]), "=r"(r[1]), "=r"(r[2]), "=r"(r[3]) : "r"(addr));
}
__device__ __forceinline__ void mma16816(float d[4], const uint32_t a[4], const uint32_t b[2]) {
    asm volatile("mma.sync.aligned.m16n8k16.row.col.f32.bf16.bf16.f32 "
        "{%0,%1,%2,%3},{%4,%5,%6,%7},{%8,%9},{%0,%1,%2,%3};"
        : "+f"(d[0]), "+f"(d[1]), "+f"(d[2]), "+f"(d[3])
        : "r"(a[0]), "r"(a[1]), "r"(a[2]), "r"(a[3]), "r"(b[0]), "r"(b[1]));
}

// ---------------- scratch (static device memory; no runtime allocation) ----
__device__ float g_Q[BH*Tdim*DhD];                 // 4 MB, normalized in place
__device__ float g_K[BH*Tdim*DhD];                 // 4 MB
__device__ float g_V[BH*Tdim*DhD];                 // 4 MB
__device__ uint32_t g_KTi[BH*DhD*1024];            // 8 MB: [bh][d][t doubled], (hi,lo) bf16 packed
__device__ uint32_t g_QTi[BH*DhD*1024];            // 8 MB
__device__ float g_cov[(size_t)BH*(NL+1)*DhD*DhD]; // 34 MB (slot NL = lag 0)
__device__ float g_score[BH*NL];
__device__ int   g_shift[BH*NSLOT];
__device__ float g_wslot[BH*NSLOT];
__device__ int   g_covsel[BH*NSLOT];
__device__ float g_attw[(size_t)BH*NSLOT*DhD*DhD]; // 10 MB
__device__ float g_outh[Bdim*Tdim*Ddim];           // 4 MB, [B,T,D] layout

// ---------------- QKV GEMM: one launch, z selects Q/K/V (R3 scalar) ---------
__global__ void gemm_qkv(const float* __restrict__ x,
                         const float* __restrict__ Wq, const float* __restrict__ bq,
                         const float* __restrict__ Wk, const float* __restrict__ bk,
                         const float* __restrict__ Wv, const float* __restrict__ bv)
{
    __shared__ float As[32][68];
    __shared__ float Bs[32][68];
    const int z = blockIdx.z;
    const float* W    = (z == 0) ? Wq : (z == 1) ? Wk : Wv;
    const float* bias = (z == 0) ? bq : (z == 1) ? bk : bv;
    float* C          = (z == 0) ? g_Q : (z == 1) ? g_K : g_V;
    const int tid = threadIdx.x;
    const int tx = tid & 15, ty = tid >> 4;
    const int m0 = blockIdx.x * 64, n0 = blockIdx.y * 64;
    float acc[4][4] = {};
    for (int k0 = 0; k0 < Ddim; k0 += 32) {
        #pragma unroll
        for (int p = tid; p < 512; p += 256) {
            int arow = p >> 3, ak = (p & 7) << 2;
            float4 v = *(const float4*)(x + (size_t)(m0 + arow)*Ddim + k0 + ak);
            As[ak+0][arow] = v.x; As[ak+1][arow] = v.y;
            As[ak+2][arow] = v.z; As[ak+3][arow] = v.w;
            int brow = p >> 4, bn = (p & 15) << 2;
            *(float4*)&Bs[brow][bn] = *(const float4*)(W + (size_t)(k0 + brow)*Ddim + n0 + bn);
        }
        __syncthreads();
        #pragma unroll 16
        for (int kk = 0; kk < 32; kk++) {
            float a[4], b[4];
            #pragma unroll
            for (int i = 0; i < 4; i++) a[i] = As[kk][ty + 16*i];
            #pragma unroll
            for (int j = 0; j < 4; j++) b[j] = Bs[kk][tx + 16*j];
            #pragma unroll
            for (int i = 0; i < 4; i++)
                #pragma unroll
                for (int j = 0; j < 4; j++)
                    acc[i][j] = fmaf(a[i], b[j], acc[i][j]);
        }
        __syncthreads();
    }
    #pragma unroll
    for (int i = 0; i < 4; i++) {
        int m = m0 + ty + 16*i;
        int b = m >> 9, t = m & (Tdim-1);
        #pragma unroll
        for (int j = 0; j < 4; j++) {
            int n = n0 + tx + 16*j;
            int h = n >> 6, c = n & (DhD-1);
            C[(((size_t)(b*Hdim + h))*Tdim + t)*DhD + c] = acc[i][j] + bias[n];
        }
    }
}

// ---------------- output GEMM (R3 scalar) ------------------------------------
__global__ void gemm_out(const float* __restrict__ Wo, const float* __restrict__ bo,
                         float* __restrict__ out)
{
    __shared__ float As[32][68];
    __shared__ float Bs[32][68];
    const int tid = threadIdx.x;
    const int tx = tid & 15, ty = tid >> 4;
    const int m0 = blockIdx.x * 64, n0 = blockIdx.y * 64;
    float acc[4][4] = {};
    for (int k0 = 0; k0 < Ddim; k0 += 32) {
        #pragma unroll
        for (int p = tid; p < 512; p += 256) {
            int arow = p >> 3, ak = (p & 7) << 2;
            float4 v = *(const float4*)(g_outh + (size_t)(m0 + arow)*Ddim + k0 + ak);
            As[ak+0][arow] = v.x; As[ak+1][arow] = v.y;
            As[ak+2][arow] = v.z; As[ak+3][arow] = v.w;
            int brow = p >> 4, bn = (p & 15) << 2;
            *(float4*)&Bs[brow][bn] = *(const float4*)(Wo + (size_t)(k0 + brow)*Ddim + n0 + bn);
        }
        __syncthreads();
        #pragma unroll 16
        for (int kk = 0; kk < 32; kk++) {
            float a[4], b[4];
            #pragma unroll
            for (int i = 0; i < 4; i++) a[i] = As[kk][ty + 16*i];
            #pragma unroll
            for (int j = 0; j < 4; j++) b[j] = Bs[kk][tx + 16*j];
            #pragma unroll
            for (int i = 0; i < 4; i++)
                #pragma unroll
                for (int j = 0; j < 4; j++)
                    acc[i][j] = fmaf(a[i], b[j], acc[i][j]);
        }
        __syncthreads();
    }
    #pragma unroll
    for (int i = 0; i < 4; i++) {
        int m = m0 + ty + 16*i;
        #pragma unroll
        for (int j = 0; j < 4; j++) {
            int n = n0 + tx + 16*j;
            out[(size_t)m*Ddim + n] = acc[i][j] + bo[n];
        }
    }
}

// ---------------- L2-normalize Q and K over the time axis --------------------
__global__ void normalize_kernel()
{
    __shared__ float part[512];
    __shared__ float sinv[DhD];
    int bh = blockIdx.x;
    float* base = (blockIdx.y ? g_K : g_Q) + (size_t)bh*Tdim*DhD;
    int d = threadIdx.x & 63, g = threadIdx.x >> 6;
    float s = 0.f;
    for (int t = g*64; t < (g+1)*64; t++) {
        float v = base[t*DhD + d]; s = fmaf(v, v, s);
    }
    part[threadIdx.x] = s;
    __syncthreads();
    if (threadIdx.x < 64) {
        float tot = 0.f;
        #pragma unroll
        for (int g2 = 0; g2 < 8; g2++) tot += part[d + g2*64];
        sinv[d] = 1.0f / sqrtf(fmaxf(tot, 1e-8f));
    }
    __syncthreads();
    float inv = sinv[d];
    for (int t = g*64; t < (g+1)*64; t++) base[t*DhD + d] *= inv;
}

// ---------------- prep: transpose + bf16 hi/lo split + period-double ---------
// src [t][d] fp32 -> dst[bh][d][t] u32 (hi bf16 in bytes 0-1, lo bf16 in 2-3),
// duplicated at t and t+512 so lag-shifted 64-slices never wrap.
__global__ void prep_kernel()
{
    __shared__ uint32_t s[64][65];
    const int bh = blockIdx.x;
    const float* src = (blockIdx.y ? g_Q : g_K) + (size_t)bh*Tdim*DhD;
    uint32_t* dst = (blockIdx.y ? g_QTi : g_KTi) + (size_t)bh*DhD*1024;
    const int tid = threadIdx.x;
    for (int tile = 0; tile < 8; tile++) {
        int t0 = tile * 64;
        #pragma unroll
        for (int p = tid; p < 4096; p += 256) {
            int r = p >> 6, d = p & 63;
            float v = src[(t0 + r)*DhD + d];
            __nv_bfloat16 h = __float2bfloat16(v);
            float hf = __bfloat162float(h);
            __nv_bfloat16 l = __float2bfloat16(v - hf);
            uint32_t w = (uint32_t)(*(unsigned short*)&h) |
                         ((uint32_t)(*(unsigned short*)&l) << 16);
            s[d][r] = w;
        }
        __syncthreads();
        #pragma unroll
        for (int p = tid; p < 4096; p += 256) {
            int d = p >> 6, t = p & 63;
            uint32_t w = s[d][t];
            dst[(size_t)d*1024 + t0 + t]       = w;
            dst[(size_t)d*1024 + t0 + t + 512] = w;
        }
        __syncthreads();
    }
}

// ---------------- cov via HMMA: one slot per block (M=64,N=64,K=512) ---------
// cov[slot][d][c] = sum_t K[(t-lag)%T][d] * Q[t][c], split bf16 (3 mma terms).
// Block 128 threads = 4 warps; warp w owns output rows 16w..16w+15.
__global__ void __launch_bounds__(128) cov_mma_kernel(const float* __restrict__ lam_ptr)
{
    __shared__ __align__(16) __nv_bfloat16 Ahi[64][72];
    __shared__ __align__(16) __nv_bfloat16 Alo[64][72];
    __shared__ __align__(16) __nv_bfloat16 Bhi[64][72];
    __shared__ __align__(16) __nv_bfloat16 Blo[64][72];
    __shared__ float s_tot[4], s_dia[4];

    const int slot = blockIdx.x, bh = blockIdx.y;
    const int lag = (slot == NL) ? 0 : lag_of(slot);
    const int tid = threadIdx.x, wid = tid >> 5, lane = tid & 31;
    const uint32_t* KT = g_KTi + (size_t)bh*DhD*1024;
    const uint32_t* QT = g_QTi + (size_t)bh*DhD*1024;
    const int m0 = wid * 16;

    float acc[8][4] = {};

    const int lrow = tid >> 1, lhalf = tid & 1;      // tile-load assignment
    const int arow_ld = m0 + (lane & 15), acol_ld = (lane >> 4) * 8;

    for (int chunk = 0; chunk < 8; chunk++) {
        const int t0 = chunk * 64;
        // ---- stage A (K shifted) and B (Q) tiles: hi/lo planes --------------
        {
            // A start offset is lag-shifted: only 4-byte aligned -> scalar u32 loads.
            const uint32_t* sa = KT + (size_t)lrow*1024 + (((t0 - lag) & (Tdim-1)) + lhalf*32);
            const uint32_t* sb = QT + (size_t)lrow*1024 + (t0 + lhalf*32);
            #pragma unroll
            for (int i = 0; i < 16; i++) {
                uint32_t w0 = sa[2*i], w1 = sa[2*i + 1];
                int c = lhalf*32 + 2*i;
                *(uint32_t*)&Ahi[lrow][c] = __byte_perm(w0, w1, 0x5410);
                *(uint32_t*)&Alo[lrow][c] = __byte_perm(w0, w1, 0x7632);
            }
            #pragma unroll
            for (int i = 0; i < 8; i++) {
                uint4 w = *(const uint4*)(sb + 4*i);
                int c = lhalf*32 + 4*i;
                *(uint32_t*)&Bhi[lrow][c]   = __byte_perm(w.x, w.y, 0x5410);
                *(uint32_t*)&Blo[lrow][c]   = __byte_perm(w.x, w.y, 0x7632);
                *(uint32_t*)&Bhi[lrow][c+2] = __byte_perm(w.z, w.w, 0x5410);
                *(uint32_t*)&Blo[lrow][c+2] = __byte_perm(w.z, w.w, 0x7632);
            }
        }
        __syncthreads();
        // ---- 4 k16 steps of mma ---------------------------------------------
        #pragma unroll
        for (int ks = 0; ks < 4; ks++) {
            const int k0 = ks * 16;
            uint32_t ahi[4], alo[4];
            ldsm4(ahi, smem_u32(&Ahi[arow_ld][k0 + acol_ld]));
            ldsm4(alo, smem_u32(&Alo[arow_ld][k0 + acol_ld]));
            #pragma unroll
            for (int jt = 0; jt < 4; jt++) {
                const int brow = 16*jt + (lane >> 4)*8 + (lane & 7);
                const int bcol = k0 + ((lane >> 3) & 1)*8;
                uint32_t bh4[4], bl4[4];
                ldsm4(bh4, smem_u32(&Bhi[brow][bcol]));
                ldsm4(bl4, smem_u32(&Blo[brow][bcol]));
                mma16816(acc[2*jt],   ahi, bh4);
                mma16816(acc[2*jt],   ahi, bl4);
                mma16816(acc[2*jt],   alo, bh4);
                mma16816(acc[2*jt+1], ahi, bh4 + 2);
                mma16816(acc[2*jt+1], ahi, bl4 + 2);
                mma16816(acc[2*jt+1], alo, bh4 + 2);
            }
        }
        __syncthreads();
    }

    // ---- epilogue: store cov, fused score -----------------------------------
    const int g = lane >> 2, tig = lane & 3;
    float tot = 0.f, dia = 0.f;
    float* covp = g_cov + ((size_t)bh*(NL+1) + slot)*(DhD*DhD);
    const int r0 = m0 + g, r1 = m0 + g + 8;
    #pragma unroll
    for (int j = 0; j < 8; j++) {
        const int c0 = 8*j + 2*tig;
        *(float2*)(covp + r0*DhD + c0) = make_float2(acc[j][0], acc[j][1]);
        *(float2*)(covp + r1*DhD + c0) = make_float2(acc[j][2], acc[j][3]);
        tot += fabsf(acc[j][0]) + fabsf(acc[j][1]) + fabsf(acc[j][2]) + fabsf(acc[j][3]);
        if (r0 == c0)     dia += fabsf(acc[j][0]);
        if (r0 == c0 + 1) dia += fabsf(acc[j][1]);
        if (r1 == c0)     dia += fabsf(acc[j][2]);
        if (r1 == c0 + 1) dia += fabsf(acc[j][3]);
    }
    if (slot < NL) {
        #pragma unroll
        for (int o = 16; o > 0; o >>= 1) {
            tot += __shfl_xor_sync(0xffffffffu, tot, o);
            dia += __shfl_xor_sync(0xffffffffu, dia, o);
        }
        if (lane == 0) { s_tot[wid] = tot; s_dia[wid] = dia; }
        __syncthreads();
        if (tid == 0) {
            float T = s_tot[0] + s_tot[1] + s_tot[2] + s_tot[3];
            float D = s_dia[0] + s_dia[1] + s_dia[2] + s_dia[3];
            float lam = fminf(fmaxf(*lam_ptr, 0.f), 1.f);
            g_score[bh*NL + slot] = lam*D + (1.f - lam)*(T - D);
        }
    }
}

// ---------------- top-18 lag selection: one warp per bh, shuffle argmax ------
__global__ void topk_kernel(const float* __restrict__ lt_lag,
                            const float* __restrict__ beta_ptr)
{
    const int bh = blockIdx.x, l = threadIdx.x; // 32 threads
    float v0 = g_score[bh*NL + l];
    float v1 = g_score[bh*NL + l + 32];
    float selV[KTOP]; int selI[KTOP];
    #pragma unroll
    for (int k = 0; k < KTOP; k++) {
        float bv; int bi;
        if (v0 >= v1) { bv = v0; bi = l; } else { bv = v1; bi = l + 32; }
        #pragma unroll
        for (int o = 16; o > 0; o >>= 1) {
            float ov = __shfl_xor_sync(0xffffffffu, bv, o);
            int   oi = __shfl_xor_sync(0xffffffffu, bi, o);
            if (ov > bv || (ov == bv && oi < bi)) { bv = ov; bi = oi; }
        }
        selV[k] = bv; selI[k] = bi;
        if (bi == l)      v0 = -3.4e38f;
        if (bi == l + 32) v1 = -3.4e38f;
    }
    if (l == 0) {
        float tl = fmaxf(expf(*lt_lag), 1e-4f);
        float mx = selV[0];
        float e[KTOP], esum = 0.f;
        #pragma unroll
        for (int k = 0; k < KTOP; k++) { e[k] = expf((selV[k] - mx)/tl); esum += e[k]; }
        float beta = fminf(fmaxf(*beta_ptr, 0.f), 1.f);
        g_shift[bh*NSLOT]  = 0;
        g_wslot[bh*NSLOT]  = 1.f - beta;
        g_covsel[bh*NSLOT] = NL;
        #pragma unroll
        for (int k = 0; k < KTOP; k++) {
            g_shift[bh*NSLOT + 1 + k]  = lag_of(selI[k]);
            g_wslot[bh*NSLOT + 1 + k]  = beta * e[k] / esum;
            g_covsel[bh*NSLOT + 1 + k] = selI[k];
        }
    }
}

// ---------------- attw[s] = weight_s * softmax_c(cov_sel / tau) --------------
__global__ void att_kernel(const float* __restrict__ log_tau_ptr)
{
    const int s = blockIdx.x, bh = blockIdx.y;
    const int l = g_covsel[bh*NSLOT + s];
    const float w = g_wslot[bh*NSLOT + s];
    const float invtau = 1.0f / fmaxf(expf(*log_tau_ptr), 1e-4f);
    const float* covp = g_cov + ((size_t)bh*(NL+1) + l)*(DhD*DhD);
    float* outp = g_attw + ((size_t)bh*NSLOT + s)*(DhD*DhD);
    int warp = threadIdx.x >> 5, lane = threadIdx.x & 31;
    for (int d = warp; d < DhD; d += 8) {
        float v0 = covp[d*DhD + lane]      * invtau;
        float v1 = covp[d*DhD + lane + 32] * invtau;
        float m = fmaxf(v0, v1);
        #pragma unroll
        for (int o = 16; o > 0; o >>= 1) m = fmaxf(m, __shfl_xor_sync(0xffffffffu, m, o));
        float e0 = expf(v0 - m), e1 = expf(v1 - m);
        float ss = e0 + e1;
        #pragma unroll
        for (int o = 16; o > 0; o >>= 1) ss += __shfl_xor_sync(0xffffffffu, ss, o);
        float f = w / ss;
        outp[d*DhD + lane]      = e0 * f;
        outp[d*DhD + lane + 32] = e1 * f;
    }
}

// ---------------- out_h: sum_s V shifted @ attw_s (R3 scalar) ----------------
__global__ void contrib_kernel()
{
    __shared__ float Att[64][68];
    __shared__ float Vs[64][68];
    const int bh = blockIdx.y, t0 = blockIdx.x * 64;
    const int bb = bh >> 3, hh = bh & 7;
    const float* Vb = g_V + (size_t)bh*Tdim*DhD;
    const int tid = threadIdx.x, tx = tid & 15, ty = tid >> 4;
    float acc[4][4] = {};
    for (int s = 0; s < NSLOT; s++) {
        const int shift = g_shift[bh*NSLOT + s];
        const float* ap = g_attw + ((size_t)bh*NSLOT + s)*(DhD*DhD);
        #pragma unroll
        for (int p = tid; p < 1024; p += 256) {
            int row = p >> 4, c4 = (p & 15) << 2;
            *(float4*)&Att[row][c4] = *(const float4*)(ap + row*DhD + c4);
            int src = (t0 + row - shift + Tdim) & (Tdim - 1);
            *(float4*)&Vs[row][c4] = *(const float4*)(Vb + src*DhD + c4);
        }
        __syncthreads();
        #pragma unroll 16
        for (int dd = 0; dd < 64; dd++) {
            float a[4], b[4];
            #pragma unroll
            for (int i = 0; i < 4; i++) a[i] = Vs[ty + 16*i][dd];
            #pragma unroll
            for (int j = 0; j < 4; j++) b[j] = Att[dd][tx + 16*j];
            #pragma unroll
            for (int i = 0; i < 4; i++)
                #pragma unroll
                for (int j = 0; j < 4; j++)
                    acc[i][j] = fmaf(a[i], b[j], acc[i][j]);
        }
        __syncthreads();
    }
    #pragma unroll
    for (int i = 0; i < 4; i++) {
        int t = t0 + ty + 16*i;
        #pragma unroll
        for (int j = 0; j < 4; j++) {
            int c = tx + 16*j;
            g_outh[((size_t)(bb*Tdim + t))*Ddim + hh*DhD + c] = acc[i][j];
        }
    }
}

// ---------------- launch ------------------------------------------------------
extern "C" void kernel_launch(void* const* d_in, const int* in_sizes, int n_in,
                              void* d_out, int out_size)
{
    const float* x           = (const float*)d_in[0];
    const float* Wq          = (const float*)d_in[1];
    const float* bq          = (const float*)d_in[2];
    const float* Wk          = (const float*)d_in[3];
    const float* bk          = (const float*)d_in[4];
    const float* Wv          = (const float*)d_in[5];
    const float* bv          = (const float*)d_in[6];
    const float* Wo          = (const float*)d_in[7];
    const float* bo          = (const float*)d_in[8];
    const float* log_tau     = (const float*)d_in[9];
    const float* lambda_auto = (const float*)d_in[10];
    const float* beta_lag    = (const float*)d_in[11];
    const float* log_tau_lag = (const float*)d_in[12];
    float* out = (float*)d_out;

    gemm_qkv<<<dim3(Bdim*Tdim/64, Ddim/64, 3), 256>>>(x, Wq, bq, Wk, bk, Wv, bv);
    normalize_kernel<<<dim3(BH, 2), 512>>>();
    prep_kernel<<<dim3(BH, 2), 256>>>();
    cov_mma_kernel<<<dim3(NL+1, BH), 128>>>(lambda_auto);
    topk_kernel<<<BH, 32>>>(log_tau_lag, beta_lag);
    att_kernel<<<dim3(NSLOT, BH), 256>>>(log_tau);
    contrib_kernel<<<dim3(Tdim/64, BH), 256>>>();
    gemm_out<<<dim3(Bdim*Tdim/64, Ddim/64), 256>>>(Wo, bo, out);
}

// round 8
// speedup vs baseline: 1.2566x; 1.2566x over previous
#include <cuda_runtime.h>
#include <cuda_bf16.h>
#include <math.h>
#include <stdint.h>

// Problem constants (fixed shapes from the reference)
#define Bdim 4
#define Hdim 8
#define Tdim 512
#define Ddim 512
#define DhD  64
#define NL   64     // number of lag candidates
#define KTOP 18     // top-k lags = 2*ceil(log2(512)) = 18
#define NSLOT 19    // 1 (lag 0 / instantaneous) + KTOP
#define BH   (Bdim*Hdim)

// lags for T=512, LMAX=64: step=7 -> 1,8,...,442 then last forced to 511
__device__ __forceinline__ int lag_of(int l) { return (l == NL-1) ? (Tdim-1) : (1 + 7*l); }

// ---------------- mma.sync helpers ------------------------------------------
__device__ __forceinline__ uint32_t smem_u32(const void* p) {
    uint32_t a;
    asm("{ .reg .u64 t; cvta.to.shared.u64 t, %1; cvt.u32.u64 %0, t; }" : "=r"(a) : "l"(p));
    return a;
}
__device__ __forceinline__ void ldsm4(uint32_t r[4], uint32_t addr) {
    asm volatile("ldmatrix.sync.aligned.m8n8.x4.shared.b16 {%0,%1,%2,%3}, [%4];"
        : "=r"(r[0]), "=r"(r[1]), "=r"(r[2]), "=r"(r[3]) : "r"(addr));
}
__device__ __forceinline__ void mma16816(float d[4], const uint32_t a[4], const uint32_t b[2]) {
    asm volatile("mma.sync.aligned.m16n8k16.row.col.f32.bf16.bf16.f32 "
        "{%0,%1,%2,%3},{%4,%5,%6,%7},{%8,%9},{%0,%1,%2,%3};"
        : "+f"(d[0]), "+f"(d[1]), "+f"(d[2]), "+f"(d[3])
        : "r"(a[0]), "r"(a[1]), "r"(a[2]), "r"(a[3]), "r"(b[0]), "r"(b[1]));
}

// ---------------- scratch (static device memory; no runtime allocation) ----
__device__ float g_Q[BH*Tdim*DhD];                 // 4 MB, normalized in place
__device__ float g_K[BH*Tdim*DhD];                 // 4 MB
__device__ float g_V[BH*Tdim*DhD];                 // 4 MB
__device__ uint32_t g_Kph[(size_t)BH*4*DhD*1024];  // 33.5 MB: 4 pre-shift phases, doubled
__device__ uint32_t g_QT[(size_t)BH*DhD*512];      // 4.2 MB: [bh][c][t], (hi,lo) packed
__device__ float g_cov[(size_t)BH*(NL+1)*DhD*DhD]; // 34 MB (slot NL = lag 0)
__device__ float g_score[BH*NL];
__device__ int   g_shift[BH*NSLOT];
__device__ float g_wslot[BH*NSLOT];
__device__ int   g_covsel[BH*NSLOT];
__device__ float g_attw[(size_t)BH*NSLOT*DhD*DhD]; // 10 MB
__device__ float g_outh[Bdim*Tdim*Ddim];           // 4 MB, [B,T,D] layout

// ---------------- QKV GEMM: one launch, z selects Q/K/V (R3 scalar) ---------
__global__ void gemm_qkv(const float* __restrict__ x,
                         const float* __restrict__ Wq, const float* __restrict__ bq,
                         const float* __restrict__ Wk, const float* __restrict__ bk,
                         const float* __restrict__ Wv, const float* __restrict__ bv)
{
    __shared__ float As[32][68];
    __shared__ float Bs[32][68];
    const int z = blockIdx.z;
    const float* W    = (z == 0) ? Wq : (z == 1) ? Wk : Wv;
    const float* bias = (z == 0) ? bq : (z == 1) ? bk : bv;
    float* C          = (z == 0) ? g_Q : (z == 1) ? g_K : g_V;
    const int tid = threadIdx.x;
    const int tx = tid & 15, ty = tid >> 4;
    const int m0 = blockIdx.x * 64, n0 = blockIdx.y * 64;
    float acc[4][4] = {};
    for (int k0 = 0; k0 < Ddim; k0 += 32) {
        #pragma unroll
        for (int p = tid; p < 512; p += 256) {
            int arow = p >> 3, ak = (p & 7) << 2;
            float4 v = *(const float4*)(x + (size_t)(m0 + arow)*Ddim + k0 + ak);
            As[ak+0][arow] = v.x; As[ak+1][arow] = v.y;
            As[ak+2][arow] = v.z; As[ak+3][arow] = v.w;
            int brow = p >> 4, bn = (p & 15) << 2;
            *(float4*)&Bs[brow][bn] = *(const float4*)(W + (size_t)(k0 + brow)*Ddim + n0 + bn);
        }
        __syncthreads();
        #pragma unroll 16
        for (int kk = 0; kk < 32; kk++) {
            float a[4], b[4];
            #pragma unroll
            for (int i = 0; i < 4; i++) a[i] = As[kk][ty + 16*i];
            #pragma unroll
            for (int j = 0; j < 4; j++) b[j] = Bs[kk][tx + 16*j];
            #pragma unroll
            for (int i = 0; i < 4; i++)
                #pragma unroll
                for (int j = 0; j < 4; j++)
                    acc[i][j] = fmaf(a[i], b[j], acc[i][j]);
        }
        __syncthreads();
    }
    #pragma unroll
    for (int i = 0; i < 4; i++) {
        int m = m0 + ty + 16*i;
        int b = m >> 9, t = m & (Tdim-1);
        #pragma unroll
        for (int j = 0; j < 4; j++) {
            int n = n0 + tx + 16*j;
            int h = n >> 6, c = n & (DhD-1);
            C[(((size_t)(b*Hdim + h))*Tdim + t)*DhD + c] = acc[i][j] + bias[n];
        }
    }
}

// ---------------- output GEMM (R3 scalar) ------------------------------------
__global__ void gemm_out(const float* __restrict__ Wo, const float* __restrict__ bo,
                         float* __restrict__ out)
{
    __shared__ float As[32][68];
    __shared__ float Bs[32][68];
    const int tid = threadIdx.x;
    const int tx = tid & 15, ty = tid >> 4;
    const int m0 = blockIdx.x * 64, n0 = blockIdx.y * 64;
    float acc[4][4] = {};
    for (int k0 = 0; k0 < Ddim; k0 += 32) {
        #pragma unroll
        for (int p = tid; p < 512; p += 256) {
            int arow = p >> 3, ak = (p & 7) << 2;
            float4 v = *(const float4*)(g_outh + (size_t)(m0 + arow)*Ddim + k0 + ak);
            As[ak+0][arow] = v.x; As[ak+1][arow] = v.y;
            As[ak+2][arow] = v.z; As[ak+3][arow] = v.w;
            int brow = p >> 4, bn = (p & 15) << 2;
            *(float4*)&Bs[brow][bn] = *(const float4*)(Wo + (size_t)(k0 + brow)*Ddim + n0 + bn);
        }
        __syncthreads();
        #pragma unroll 16
        for (int kk = 0; kk < 32; kk++) {
            float a[4], b[4];
            #pragma unroll
            for (int i = 0; i < 4; i++) a[i] = As[kk][ty + 16*i];
            #pragma unroll
            for (int j = 0; j < 4; j++) b[j] = Bs[kk][tx + 16*j];
            #pragma unroll
            for (int i = 0; i < 4; i++)
                #pragma unroll
                for (int j = 0; j < 4; j++)
                    acc[i][j] = fmaf(a[i], b[j], acc[i][j]);
        }
        __syncthreads();
    }
    #pragma unroll
    for (int i = 0; i < 4; i++) {
        int m = m0 + ty + 16*i;
        #pragma unroll
        for (int j = 0; j < 4; j++) {
            int n = n0 + tx + 16*j;
            out[(size_t)m*Ddim + n] = acc[i][j] + bo[n];
        }
    }
}

// ---------------- L2-normalize Q and K over the time axis --------------------
__global__ void normalize_kernel()
{
    __shared__ float part[512];
    __shared__ float sinv[DhD];
    int bh = blockIdx.x;
    float* base = (blockIdx.y ? g_K : g_Q) + (size_t)bh*Tdim*DhD;
    int d = threadIdx.x & 63, g = threadIdx.x >> 6;
    float s = 0.f;
    for (int t = g*64; t < (g+1)*64; t++) {
        float v = base[t*DhD + d]; s = fmaf(v, v, s);
    }
    part[threadIdx.x] = s;
    __syncthreads();
    if (threadIdx.x < 64) {
        float tot = 0.f;
        #pragma unroll
        for (int g2 = 0; g2 < 8; g2++) tot += part[d + g2*64];
        sinv[d] = 1.0f / sqrtf(fmaxf(tot, 1e-8f));
    }
    __syncthreads();
    float inv = sinv[d];
    for (int t = g*64; t < (g+1)*64; t++) base[t*DhD + d] *= inv;
}

// ---------------- pack helper: fp32 -> (hi bf16, lo bf16) u32 ----------------
__device__ __forceinline__ uint32_t pack_hilo(float v) {
    __nv_bfloat16 h = __float2bfloat16(v);
    float hf = __bfloat162float(h);
    __nv_bfloat16 l = __float2bfloat16(v - hf);
    return (uint32_t)(*(unsigned short*)&h) | ((uint32_t)(*(unsigned short*)&l) << 16);
}

// ---------------- prep_q: Q transpose + pack -> g_QT[bh][c][512] -------------
__global__ void prep_q_kernel()
{
    __shared__ uint32_t s[64][65];
    const int bh = blockIdx.x;
    const float* src = g_Q + (size_t)bh*Tdim*DhD;
    uint32_t* dst = g_QT + (size_t)bh*DhD*512;
    const int tid = threadIdx.x;
    for (int tile = 0; tile < 8; tile++) {
        int t0 = tile * 64;
        #pragma unroll
        for (int p = tid; p < 4096; p += 256) {
            int r = p >> 6, d = p & 63;
            s[d][r] = pack_hilo(src[(t0 + r)*DhD + d]);
        }
        __syncthreads();
        #pragma unroll
        for (int p = tid; p < 4096; p += 256) {
            int d = p >> 6, t = p & 63;
            dst[(size_t)d*512 + t0 + t] = s[d][t];
        }
        __syncthreads();
    }
}

// ---------------- prep_k: K transpose + pack + 4 shift-phases, doubled -------
// g_Kph[bh][p][d][t'] = pack(K[(t'+p) mod 512][d]); t' in [0,1023] (doubled).
__global__ void prep_k_kernel()
{
    __shared__ uint32_t s[64][65];
    const int bh = blockIdx.x;
    const float* src = g_K + (size_t)bh*Tdim*DhD;
    uint32_t* dst = g_Kph + (size_t)bh*4*DhD*1024;
    const int tid = threadIdx.x;
    for (int tile = 0; tile < 8; tile++) {
        int t0 = tile * 64;
        #pragma unroll
        for (int p = tid; p < 4096; p += 256) {
            int r = p >> 6, d = p & 63;
            s[d][r] = pack_hilo(src[(t0 + r)*DhD + d]);
        }
        __syncthreads();
        #pragma unroll
        for (int ph = 0; ph < 4; ph++) {
            for (int p = tid; p < 4096; p += 256) {
                int d = p >> 6, t = p & 63;
                uint32_t w = s[d][t];
                int tp = (t0 + t - ph) & (Tdim - 1);
                uint32_t* row = dst + ((size_t)ph*DhD + d)*1024;
                row[tp]       = w;
                row[tp + 512] = w;
            }
        }
        __syncthreads();
    }
}

// ---------------- cov via HMMA, interleaved hi/lo (virtual K = 2T) -----------
// cov[slot][d][c] = sum_t K[(t-lag)%T][d] * Q[t][c], full (hi+lo)*(hi+lo) via
// two mma passes per b-frag: mma(a,b) + mma(a, halfword_swap(b)).
// Tiles: [64 rows][128 vk] bf16, row stride 272B (conflict-free ldmatrix).
#define TSTRIDE 272
__global__ void __launch_bounds__(128) cov_mma_kernel(const float* __restrict__ lam_ptr)
{
    __shared__ __align__(16) char sA[64*TSTRIDE];
    __shared__ __align__(16) char sB[64*TSTRIDE];
    __shared__ float s_tot[4], s_dia[4];

    const int slot = blockIdx.x, bh = blockIdx.y;
    const int lag = (slot == NL) ? 0 : lag_of(slot);
    const int tid = threadIdx.x, wid = tid >> 5, lane = tid & 31;
    const int m0 = wid * 16;

    float acc[8][4] = {};

    const int lrow = tid >> 1, lhalf = tid & 1;
    const int arow_ld = m0 + (lane & 15), acol_ld = (lane >> 4) * 8; // bf16 (vk) units
    const uint32_t sAb = smem_u32(sA), sBb = smem_u32(sB);

    // A source: phase-shifted plane, 16B-aligned uint4 reads
    const int start = (0 - lag) & (Tdim - 1);  // start for t0=0; add t0 per chunk
    const int ph = start & 3;
    const uint32_t* KTp = g_Kph + (((size_t)bh*4 + ph)*DhD + lrow)*1024;
    const uint32_t* QTr = g_QT + ((size_t)bh*DhD + lrow)*512;

    for (int chunk = 0; chunk < 8; chunk++) {
        const int t0 = chunk * 64;
        {
            // A: u32 index base..base+63 in phase plane (base mod 4 == 0)
            const int st = (t0 - lag) & (Tdim - 1);
            const uint32_t* srcA = KTp + (st - ph) + lhalf*32;      // st & 3 == ph
            uint32_t* dstA = (uint32_t*)(sA + lrow*TSTRIDE) + lhalf*32;
            #pragma unroll
            for (int i = 0; i < 8; i++)
                *(uint4*)(dstA + 4*i) = *(const uint4*)(srcA + 4*i);
            // B: aligned window [t0 .. t0+63]
            const uint32_t* srcB = QTr + t0 + lhalf*32;
            uint32_t* dstB = (uint32_t*)(sB + lrow*TSTRIDE) + lhalf*32;
            #pragma unroll
            for (int i = 0; i < 8; i++)
                *(uint4*)(dstB + 4*i) = *(const uint4*)(srcB + 4*i);
        }
        __syncthreads();
        #pragma unroll
        for (int ks = 0; ks < 8; ks++) {
            const int k0 = ks * 16;  // virtual-k (bf16 units)
            uint32_t a4[4];
            ldsm4(a4, sAb + arow_ld*TSTRIDE + (k0 + acol_ld)*2);
            #pragma unroll
            for (int jt = 0; jt < 4; jt++) {
                const int brow = 16*jt + (lane >> 4)*8 + (lane & 7);
                const int bcol = k0 + ((lane >> 3) & 1)*8;
                uint32_t b4[4];
                ldsm4(b4, sBb + brow*TSTRIDE + bcol*2);
                mma16816(acc[2*jt],   a4, b4);
                mma16816(acc[2*jt+1], a4, b4 + 2);
                uint32_t bs[4];
                #pragma unroll
                for (int i = 0; i < 4; i++) bs[i] = __byte_perm(b4[i], 0, 0x1032);
                mma16816(acc[2*jt],   a4, bs);
                mma16816(acc[2*jt+1], a4, bs + 2);
            }
        }
        __syncthreads();
    }

    // ---- epilogue: store cov, fused score (identical mapping to R7) ---------
    const int g = lane >> 2, tig = lane & 3;
    float tot = 0.f, dia = 0.f;
    float* covp = g_cov + ((size_t)bh*(NL+1) + slot)*(DhD*DhD);
    const int r0 = m0 + g, r1 = m0 + g + 8;
    #pragma unroll
    for (int j = 0; j < 8; j++) {
        const int c0 = 8*j + 2*tig;
        *(float2*)(covp + r0*DhD + c0) = make_float2(acc[j][0], acc[j][1]);
        *(float2*)(covp + r1*DhD + c0) = make_float2(acc[j][2], acc[j][3]);
        tot += fabsf(acc[j][0]) + fabsf(acc[j][1]) + fabsf(acc[j][2]) + fabsf(acc[j][3]);
        if (r0 == c0)     dia += fabsf(acc[j][0]);
        if (r0 == c0 + 1) dia += fabsf(acc[j][1]);
        if (r1 == c0)     dia += fabsf(acc[j][2]);
        if (r1 == c0 + 1) dia += fabsf(acc[j][3]);
    }
    if (slot < NL) {
        #pragma unroll
        for (int o = 16; o > 0; o >>= 1) {
            tot += __shfl_xor_sync(0xffffffffu, tot, o);
            dia += __shfl_xor_sync(0xffffffffu, dia, o);
        }
        if (lane == 0) { s_tot[wid] = tot; s_dia[wid] = dia; }
        __syncthreads();
        if (tid == 0) {
            float T = s_tot[0] + s_tot[1] + s_tot[2] + s_tot[3];
            float D = s_dia[0] + s_dia[1] + s_dia[2] + s_dia[3];
            float lam = fminf(fmaxf(*lam_ptr, 0.f), 1.f);
            g_score[bh*NL + slot] = lam*D + (1.f - lam)*(T - D);
        }
    }
}

// ---------------- top-18 lag selection: one warp per bh, shuffle argmax ------
__global__ void topk_kernel(const float* __restrict__ lt_lag,
                            const float* __restrict__ beta_ptr)
{
    const int bh = blockIdx.x, l = threadIdx.x; // 32 threads
    float v0 = g_score[bh*NL + l];
    float v1 = g_score[bh*NL + l + 32];
    float selV[KTOP]; int selI[KTOP];
    #pragma unroll
    for (int k = 0; k < KTOP; k++) {
        float bv; int bi;
        if (v0 >= v1) { bv = v0; bi = l; } else { bv = v1; bi = l + 32; }
        #pragma unroll
        for (int o = 16; o > 0; o >>= 1) {
            float ov = __shfl_xor_sync(0xffffffffu, bv, o);
            int   oi = __shfl_xor_sync(0xffffffffu, bi, o);
            if (ov > bv || (ov == bv && oi < bi)) { bv = ov; bi = oi; }
        }
        selV[k] = bv; selI[k] = bi;
        if (bi == l)      v0 = -3.4e38f;
        if (bi == l + 32) v1 = -3.4e38f;
    }
    if (l == 0) {
        float tl = fmaxf(expf(*lt_lag), 1e-4f);
        float mx = selV[0];
        float e[KTOP], esum = 0.f;
        #pragma unroll
        for (int k = 0; k < KTOP; k++) { e[k] = expf((selV[k] - mx)/tl); esum += e[k]; }
        float beta = fminf(fmaxf(*beta_ptr, 0.f), 1.f);
        g_shift[bh*NSLOT]  = 0;
        g_wslot[bh*NSLOT]  = 1.f - beta;
        g_covsel[bh*NSLOT] = NL;
        #pragma unroll
        for (int k = 0; k < KTOP; k++) {
            g_shift[bh*NSLOT + 1 + k]  = lag_of(selI[k]);
            g_wslot[bh*NSLOT + 1 + k]  = beta * e[k] / esum;
            g_covsel[bh*NSLOT + 1 + k] = selI[k];
        }
    }
}

// ---------------- attw[s] = weight_s * softmax_c(cov_sel / tau) --------------
__global__ void att_kernel(const float* __restrict__ log_tau_ptr)
{
    const int s = blockIdx.x, bh = blockIdx.y;
    const int l = g_covsel[bh*NSLOT + s];
    const float w = g_wslot[bh*NSLOT + s];
    const float invtau = 1.0f / fmaxf(expf(*log_tau_ptr), 1e-4f);
    const float* covp = g_cov + ((size_t)bh*(NL+1) + l)*(DhD*DhD);
    float* outp = g_attw + ((size_t)bh*NSLOT + s)*(DhD*DhD);
    int warp = threadIdx.x >> 5, lane = threadIdx.x & 31;
    for (int d = warp; d < DhD; d += 8) {
        float v0 = covp[d*DhD + lane]      * invtau;
        float v1 = covp[d*DhD + lane + 32] * invtau;
        float m = fmaxf(v0, v1);
        #pragma unroll
        for (int o = 16; o > 0; o >>= 1) m = fmaxf(m, __shfl_xor_sync(0xffffffffu, m, o));
        float e0 = expf(v0 - m), e1 = expf(v1 - m);
        float ss = e0 + e1;
        #pragma unroll
        for (int o = 16; o > 0; o >>= 1) ss += __shfl_xor_sync(0xffffffffu, ss, o);
        float f = w / ss;
        outp[d*DhD + lane]      = e0 * f;
        outp[d*DhD + lane + 32] = e1 * f;
    }
}

// ---------------- out_h: sum_s V shifted @ attw_s (R3 scalar) ----------------
__global__ void contrib_kernel()
{
    __shared__ float Att[64][68];
    __shared__ float Vs[64][68];
    const int bh = blockIdx.y, t0 = blockIdx.x * 64;
    const int bb = bh >> 3, hh = bh & 7;
    const float* Vb = g_V + (size_t)bh*Tdim*DhD;
    const int tid = threadIdx.x, tx = tid & 15, ty = tid >> 4;
    float acc[4][4] = {};
    for (int s = 0; s < NSLOT; s++) {
        const int shift = g_shift[bh*NSLOT + s];
        const float* ap = g_attw + ((size_t)bh*NSLOT + s)*(DhD*DhD);
        #pragma unroll
        for (int p = tid; p < 1024; p += 256) {
            int row = p >> 4, c4 = (p & 15) << 2;
            *(float4*)&Att[row][c4] = *(const float4*)(ap + row*DhD + c4);
            int src = (t0 + row - shift + Tdim) & (Tdim - 1);
            *(float4*)&Vs[row][c4] = *(const float4*)(Vb + src*DhD + c4);
        }
        __syncthreads();
        #pragma unroll 16
        for (int dd = 0; dd < 64; dd++) {
            float a[4], b[4];
            #pragma unroll
            for (int i = 0; i < 4; i++) a[i] = Vs[ty + 16*i][dd];
            #pragma unroll
            for (int j = 0; j < 4; j++) b[j] = Att[dd][tx + 16*j];
            #pragma unroll
            for (int i = 0; i < 4; i++)
                #pragma unroll
                for (int j = 0; j < 4; j++)
                    acc[i][j] = fmaf(a[i], b[j], acc[i][j]);
        }
        __syncthreads();
    }
    #pragma unroll
    for (int i = 0; i < 4; i++) {
        int t = t0 + ty + 16*i;
        #pragma unroll
        for (int j = 0; j < 4; j++) {
            int c = tx + 16*j;
            g_outh[((size_t)(bb*Tdim + t))*Ddim + hh*DhD + c] = acc[i][j];
        }
    }
}

// ---------------- launch ------------------------------------------------------
extern "C" void kernel_launch(void* const* d_in, const int* in_sizes, int n_in,
                              void* d_out, int out_size)
{
    const float* x           = (const float*)d_in[0];
    const float* Wq          = (const float*)d_in[1];
    const float* bq          = (const float*)d_in[2];
    const float* Wk          = (const float*)d_in[3];
    const float* bk          = (const float*)d_in[4];
    const float* Wv          = (const float*)d_in[5];
    const float* bv          = (const float*)d_in[6];
    const float* Wo          = (const float*)d_in[7];
    const float* bo          = (const float*)d_in[8];
    const float* log_tau     = (const float*)d_in[9];
    const float* lambda_auto = (const float*)d_in[10];
    const float* beta_lag    = (const float*)d_in[11];
    const float* log_tau_lag = (const float*)d_in[12];
    float* out = (float*)d_out;

    gemm_qkv<<<dim3(Bdim*Tdim/64, Ddim/64, 3), 256>>>(x, Wq, bq, Wk, bk, Wv, bv);
    normalize_kernel<<<dim3(BH, 2), 512>>>();
    prep_q_kernel<<<BH, 256>>>();
    prep_k_kernel<<<BH, 256>>>();
    cov_mma_kernel<<<dim3(NL+1, BH), 128>>>(lambda_auto);
    topk_kernel<<<BH, 32>>>(log_tau_lag, beta_lag);
    att_kernel<<<dim3(NSLOT, BH), 256>>>(log_tau);
    contrib_kernel<<<dim3(Tdim/64, BH), 256>>>();
    gemm_out<<<dim3(Bdim*Tdim/64, Ddim/64), 256>>>(Wo, bo, out);
}

// round 9
// speedup vs baseline: 1.4986x; 1.1926x over previous
#include <cuda_runtime.h>
#include <cuda_bf16.h>
#include <math.h>
#include <stdint.h>

// Problem constants (fixed shapes from the reference)
#define Bdim 4
#define Hdim 8
#define Tdim 512
#define Ddim 512
#define DhD  64
#define NL   64     // number of lag candidates
#define KTOP 18     // top-k lags = 2*ceil(log2(512)) = 18
#define NSLOT 19    // 1 (lag 0 / instantaneous) + KTOP
#define BH   (Bdim*Hdim)

// lags for T=512, LMAX=64: step=7 -> 1,8,...,442 then last forced to 511
__device__ __forceinline__ int lag_of(int l) { return (l == NL-1) ? (Tdim-1) : (1 + 7*l); }

// ---------------- mma.sync helpers ------------------------------------------
__device__ __forceinline__ uint32_t smem_u32(const void* p) {
    uint32_t a;
    asm("{ .reg .u64 t; cvta.to.shared.u64 t, %1; cvt.u32.u64 %0, t; }" : "=r"(a) : "l"(p));
    return a;
}
__device__ __forceinline__ void ldsm4(uint32_t r[4], uint32_t addr) {
    asm volatile("ldmatrix.sync.aligned.m8n8.x4.shared.b16 {%0,%1,%2,%3}, [%4];"
        : "=r"(r[0]), "=r"(r[1]), "=r"(r[2]), "=r"(r[3]) : "r"(addr));
}
__device__ __forceinline__ void mma16816(float d[4], const uint32_t a[4], const uint32_t b[2]) {
    asm volatile("mma.sync.aligned.m16n8k16.row.col.f32.bf16.bf16.f32 "
        "{%0,%1,%2,%3},{%4,%5,%6,%7},{%8,%9},{%0,%1,%2,%3};"
        : "+f"(d[0]), "+f"(d[1]), "+f"(d[2]), "+f"(d[3])
        : "r"(a[0]), "r"(a[1]), "r"(a[2]), "r"(a[3]), "r"(b[0]), "r"(b[1]));
}

// ---------------- scratch (static device memory; no runtime allocation) ----
__device__ float g_Q[BH*Tdim*DhD];                 // 4 MB, normalized in place
__device__ float g_K[BH*Tdim*DhD];                 // 4 MB
__device__ float g_V[BH*Tdim*DhD];                 // 4 MB
__device__ uint32_t g_Kph[(size_t)BH*4*DhD*1024];  // 33.5 MB: 4 pre-shift phases, doubled
__device__ uint32_t g_QT[(size_t)BH*DhD*512];      // 4.2 MB: [bh][c][t], (hi,lo) packed
__device__ float g_cov[(size_t)BH*(NL+1)*DhD*DhD]; // 34 MB (slot NL = lag 0)
__device__ float g_score[BH*NL];
__device__ int   g_shift[BH*NSLOT];
__device__ float g_wslot[BH*NSLOT];
__device__ int   g_covsel[BH*NSLOT];
__device__ float g_attw[(size_t)BH*NSLOT*DhD*DhD]; // 10 MB
__device__ float g_outh[Bdim*Tdim*Ddim];           // 4 MB, [B,T,D] layout

// ---------------- QKV GEMM: one launch, z selects Q/K/V (R3 scalar) ---------
__global__ void gemm_qkv(const float* __restrict__ x,
                         const float* __restrict__ Wq, const float* __restrict__ bq,
                         const float* __restrict__ Wk, const float* __restrict__ bk,
                         const float* __restrict__ Wv, const float* __restrict__ bv)
{
    __shared__ float As[32][68];
    __shared__ float Bs[32][68];
    const int z = blockIdx.z;
    const float* W    = (z == 0) ? Wq : (z == 1) ? Wk : Wv;
    const float* bias = (z == 0) ? bq : (z == 1) ? bk : bv;
    float* C          = (z == 0) ? g_Q : (z == 1) ? g_K : g_V;
    const int tid = threadIdx.x;
    const int tx = tid & 15, ty = tid >> 4;
    const int m0 = blockIdx.x * 64, n0 = blockIdx.y * 64;
    float acc[4][4] = {};
    for (int k0 = 0; k0 < Ddim; k0 += 32) {
        #pragma unroll
        for (int p = tid; p < 512; p += 256) {
            int arow = p >> 3, ak = (p & 7) << 2;
            float4 v = *(const float4*)(x + (size_t)(m0 + arow)*Ddim + k0 + ak);
            As[ak+0][arow] = v.x; As[ak+1][arow] = v.y;
            As[ak+2][arow] = v.z; As[ak+3][arow] = v.w;
            int brow = p >> 4, bn = (p & 15) << 2;
            *(float4*)&Bs[brow][bn] = *(const float4*)(W + (size_t)(k0 + brow)*Ddim + n0 + bn);
        }
        __syncthreads();
        #pragma unroll 16
        for (int kk = 0; kk < 32; kk++) {
            float a[4], b[4];
            #pragma unroll
            for (int i = 0; i < 4; i++) a[i] = As[kk][ty + 16*i];
            #pragma unroll
            for (int j = 0; j < 4; j++) b[j] = Bs[kk][tx + 16*j];
            #pragma unroll
            for (int i = 0; i < 4; i++)
                #pragma unroll
                for (int j = 0; j < 4; j++)
                    acc[i][j] = fmaf(a[i], b[j], acc[i][j]);
        }
        __syncthreads();
    }
    #pragma unroll
    for (int i = 0; i < 4; i++) {
        int m = m0 + ty + 16*i;
        int b = m >> 9, t = m & (Tdim-1);
        #pragma unroll
        for (int j = 0; j < 4; j++) {
            int n = n0 + tx + 16*j;
            int h = n >> 6, c = n & (DhD-1);
            C[(((size_t)(b*Hdim + h))*Tdim + t)*DhD + c] = acc[i][j] + bias[n];
        }
    }
}

// ---------------- output GEMM (R3 scalar) ------------------------------------
__global__ void gemm_out(const float* __restrict__ Wo, const float* __restrict__ bo,
                         float* __restrict__ out)
{
    __shared__ float As[32][68];
    __shared__ float Bs[32][68];
    const int tid = threadIdx.x;
    const int tx = tid & 15, ty = tid >> 4;
    const int m0 = blockIdx.x * 64, n0 = blockIdx.y * 64;
    float acc[4][4] = {};
    for (int k0 = 0; k0 < Ddim; k0 += 32) {
        #pragma unroll
        for (int p = tid; p < 512; p += 256) {
            int arow = p >> 3, ak = (p & 7) << 2;
            float4 v = *(const float4*)(g_outh + (size_t)(m0 + arow)*Ddim + k0 + ak);
            As[ak+0][arow] = v.x; As[ak+1][arow] = v.y;
            As[ak+2][arow] = v.z; As[ak+3][arow] = v.w;
            int brow = p >> 4, bn = (p & 15) << 2;
            *(float4*)&Bs[brow][bn] = *(const float4*)(Wo + (size_t)(k0 + brow)*Ddim + n0 + bn);
        }
        __syncthreads();
        #pragma unroll 16
        for (int kk = 0; kk < 32; kk++) {
            float a[4], b[4];
            #pragma unroll
            for (int i = 0; i < 4; i++) a[i] = As[kk][ty + 16*i];
            #pragma unroll
            for (int j = 0; j < 4; j++) b[j] = Bs[kk][tx + 16*j];
            #pragma unroll
            for (int i = 0; i < 4; i++)
                #pragma unroll
                for (int j = 0; j < 4; j++)
                    acc[i][j] = fmaf(a[i], b[j], acc[i][j]);
        }
        __syncthreads();
    }
    #pragma unroll
    for (int i = 0; i < 4; i++) {
        int m = m0 + ty + 16*i;
        #pragma unroll
        for (int j = 0; j < 4; j++) {
            int n = n0 + tx + 16*j;
            out[(size_t)m*Ddim + n] = acc[i][j] + bo[n];
        }
    }
}

// ---------------- L2-normalize Q and K over the time axis --------------------
__global__ void normalize_kernel()
{
    __shared__ float part[512];
    __shared__ float sinv[DhD];
    int bh = blockIdx.x;
    float* base = (blockIdx.y ? g_K : g_Q) + (size_t)bh*Tdim*DhD;
    int d = threadIdx.x & 63, g = threadIdx.x >> 6;
    float s = 0.f;
    for (int t = g*64; t < (g+1)*64; t++) {
        float v = base[t*DhD + d]; s = fmaf(v, v, s);
    }
    part[threadIdx.x] = s;
    __syncthreads();
    if (threadIdx.x < 64) {
        float tot = 0.f;
        #pragma unroll
        for (int g2 = 0; g2 < 8; g2++) tot += part[d + g2*64];
        sinv[d] = 1.0f / sqrtf(fmaxf(tot, 1e-8f));
    }
    __syncthreads();
    float inv = sinv[d];
    for (int t = g*64; t < (g+1)*64; t++) base[t*DhD + d] *= inv;
}

// ---------------- pack helper: fp32 -> (hi bf16, lo bf16) u32 ----------------
__device__ __forceinline__ uint32_t pack_hilo(float v) {
    __nv_bfloat16 h = __float2bfloat16(v);
    float hf = __bfloat162float(h);
    __nv_bfloat16 l = __float2bfloat16(v - hf);
    return (uint32_t)(*(unsigned short*)&h) | ((uint32_t)(*(unsigned short*)&l) << 16);
}

// ---------------- prep_q: Q transpose + pack -> g_QT[bh][c][512] -------------
// grid (BH, 8): one 64-t tile per block.
__global__ void prep_q_kernel()
{
    __shared__ uint32_t s[64][65];
    const int bh = blockIdx.x, t0 = blockIdx.y * 64;
    const float* src = g_Q + (size_t)bh*Tdim*DhD;
    uint32_t* dst = g_QT + (size_t)bh*DhD*512;
    const int tid = threadIdx.x;
    #pragma unroll
    for (int p = tid; p < 4096; p += 256) {
        int r = p >> 6, d = p & 63;
        s[d][r] = pack_hilo(src[(t0 + r)*DhD + d]);
    }
    __syncthreads();
    #pragma unroll
    for (int p = tid; p < 4096; p += 256) {
        int d = p >> 6, t = p & 63;
        dst[(size_t)d*512 + t0 + t] = s[d][t];
    }
}

// ---------------- prep_k: K transpose + pack + 4 shift-phases, doubled -------
// g_Kph[bh][p][d][t'] = pack(K[(t'+p) mod 512][d]); t' in [0,1023] (doubled).
// grid (BH, 8): one 64-t tile per block.
__global__ void prep_k_kernel()
{
    __shared__ uint32_t s[64][65];
    const int bh = blockIdx.x, t0 = blockIdx.y * 64;
    const float* src = g_K + (size_t)bh*Tdim*DhD;
    uint32_t* dst = g_Kph + (size_t)bh*4*DhD*1024;
    const int tid = threadIdx.x;
    #pragma unroll
    for (int p = tid; p < 4096; p += 256) {
        int r = p >> 6, d = p & 63;
        s[d][r] = pack_hilo(src[(t0 + r)*DhD + d]);
    }
    __syncthreads();
    #pragma unroll
    for (int ph = 0; ph < 4; ph++) {
        for (int p = tid; p < 4096; p += 256) {
            int d = p >> 6, t = p & 63;
            uint32_t w = s[d][t];
            int tp = (t0 + t - ph) & (Tdim - 1);
            uint32_t* row = dst + ((size_t)ph*DhD + d)*1024;
            row[tp]       = w;
            row[tp + 512] = w;
        }
    }
}

// ---------------- cov via HMMA, interleaved hi/lo (virtual K = 2T) -----------
// cov[slot][d][c] = sum_t K[(t-lag)%T][d] * Q[t][c], full (hi+lo)*(hi+lo) via
// two mma passes per b-frag: mma(a,b) + mma(a, halfword_swap(b)).
// 256 threads = 8 warps: warp = (row-strip 0-3, col-half 0-1); each warp does
// 16 rows x 32 cols. Tiles [64 rows][128 vk] bf16, row stride 272B.
#define TSTRIDE 272
__global__ void __launch_bounds__(256) cov_mma_kernel(const float* __restrict__ lam_ptr)
{
    __shared__ __align__(16) char sA[64*TSTRIDE];
    __shared__ __align__(16) char sB[64*TSTRIDE];
    __shared__ float s_tot[8], s_dia[8];

    const int slot = blockIdx.x, bh = blockIdx.y;
    const int lag = (slot == NL) ? 0 : lag_of(slot);
    const int tid = threadIdx.x, wid = tid >> 5, lane = tid & 31;
    const int rowstrip = wid & 3, colhalf = wid >> 2;
    const int m0 = rowstrip * 16;

    float acc[4][4] = {};

    // staging: thread -> (row, 64B segment)
    const int srow = tid >> 2, sseg = tid & 3;
    const int arow_ld = m0 + (lane & 15), acol_ld = (lane >> 4) * 8; // bf16 (vk) units
    const uint32_t sAb = smem_u32(sA), sBb = smem_u32(sB);

    const int ph = (Tdim - lag) & 3;  // (t0 - lag) mod 4, t0 multiple of 64
    const uint32_t* KTp = g_Kph + (((size_t)bh*4 + ph)*DhD + srow)*1024;
    const uint32_t* QTr = g_QT + ((size_t)bh*DhD + srow)*512;
    uint32_t* dstA = (uint32_t*)(sA + srow*TSTRIDE) + sseg*4*4;
    uint32_t* dstB = (uint32_t*)(sB + srow*TSTRIDE) + sseg*4*4;

    for (int chunk = 0; chunk < 8; chunk++) {
        const int t0 = chunk * 64;
        {
            const int st = (t0 - lag) & (Tdim - 1);
            const uint32_t* srcA = KTp + (st - ph) + sseg*16;
            const uint32_t* srcB = QTr + t0 + sseg*16;
            #pragma unroll
            for (int i = 0; i < 4; i++)
                *(uint4*)(dstA + 4*i) = *(const uint4*)(srcA + 4*i);
            #pragma unroll
            for (int i = 0; i < 4; i++)
                *(uint4*)(dstB + 4*i) = *(const uint4*)(srcB + 4*i);
        }
        __syncthreads();
        #pragma unroll
        for (int ks = 0; ks < 8; ks++) {
            const int k0 = ks * 16;  // virtual-k (bf16 units)
            uint32_t a4[4];
            ldsm4(a4, sAb + arow_ld*TSTRIDE + (k0 + acol_ld)*2);
            #pragma unroll
            for (int jt2 = 0; jt2 < 2; jt2++) {
                const int jt = colhalf*2 + jt2;
                const int brow = 16*jt + (lane >> 4)*8 + (lane & 7);
                const int bcol = k0 + ((lane >> 3) & 1)*8;
                uint32_t b4[4];
                ldsm4(b4, sBb + brow*TSTRIDE + bcol*2);
                mma16816(acc[2*jt2],   a4, b4);
                mma16816(acc[2*jt2+1], a4, b4 + 2);
                uint32_t bs[4];
                #pragma unroll
                for (int i = 0; i < 4; i++) bs[i] = __byte_perm(b4[i], 0, 0x1032);
                mma16816(acc[2*jt2],   a4, bs);
                mma16816(acc[2*jt2+1], a4, bs + 2);
            }
        }
        __syncthreads();
    }

    // ---- epilogue: store cov, fused score -----------------------------------
    const int g = lane >> 2, tig = lane & 3;
    float tot = 0.f, dia = 0.f;
    float* covp = g_cov + ((size_t)bh*(NL+1) + slot)*(DhD*DhD);
    const int r0 = m0 + g, r1 = m0 + g + 8;
    #pragma unroll
    for (int j = 0; j < 4; j++) {
        const int c0 = colhalf*32 + 8*j + 2*tig;
        *(float2*)(covp + r0*DhD + c0) = make_float2(acc[j][0], acc[j][1]);
        *(float2*)(covp + r1*DhD + c0) = make_float2(acc[j][2], acc[j][3]);
        tot += fabsf(acc[j][0]) + fabsf(acc[j][1]) + fabsf(acc[j][2]) + fabsf(acc[j][3]);
        if (r0 == c0)     dia += fabsf(acc[j][0]);
        if (r0 == c0 + 1) dia += fabsf(acc[j][1]);
        if (r1 == c0)     dia += fabsf(acc[j][2]);
        if (r1 == c0 + 1) dia += fabsf(acc[j][3]);
    }
    if (slot < NL) {
        #pragma unroll
        for (int o = 16; o > 0; o >>= 1) {
            tot += __shfl_xor_sync(0xffffffffu, tot, o);
            dia += __shfl_xor_sync(0xffffffffu, dia, o);
        }
        if (lane == 0) { s_tot[wid] = tot; s_dia[wid] = dia; }
        __syncthreads();
        if (tid == 0) {
            float T = 0.f, D = 0.f;
            #pragma unroll
            for (int w = 0; w < 8; w++) { T += s_tot[w]; D += s_dia[w]; }
            float lam = fminf(fmaxf(*lam_ptr, 0.f), 1.f);
            g_score[bh*NL + slot] = lam*D + (1.f - lam)*(T - D);
        }
    }
}

// ---------------- top-18 lag selection: one warp per bh, shuffle argmax ------
__global__ void topk_kernel(const float* __restrict__ lt_lag,
                            const float* __restrict__ beta_ptr)
{
    const int bh = blockIdx.x, l = threadIdx.x; // 32 threads
    float v0 = g_score[bh*NL + l];
    float v1 = g_score[bh*NL + l + 32];
    float selV[KTOP]; int selI[KTOP];
    #pragma unroll
    for (int k = 0; k < KTOP; k++) {
        float bv; int bi;
        if (v0 >= v1) { bv = v0; bi = l; } else { bv = v1; bi = l + 32; }
        #pragma unroll
        for (int o = 16; o > 0; o >>= 1) {
            float ov = __shfl_xor_sync(0xffffffffu, bv, o);
            int   oi = __shfl_xor_sync(0xffffffffu, bi, o);
            if (ov > bv || (ov == bv && oi < bi)) { bv = ov; bi = oi; }
        }
        selV[k] = bv; selI[k] = bi;
        if (bi == l)      v0 = -3.4e38f;
        if (bi == l + 32) v1 = -3.4e38f;
    }
    if (l == 0) {
        float tl = fmaxf(expf(*lt_lag), 1e-4f);
        float mx = selV[0];
        float e[KTOP], esum = 0.f;
        #pragma unroll
        for (int k = 0; k < KTOP; k++) { e[k] = expf((selV[k] - mx)/tl); esum += e[k]; }
        float beta = fminf(fmaxf(*beta_ptr, 0.f), 1.f);
        g_shift[bh*NSLOT]  = 0;
        g_wslot[bh*NSLOT]  = 1.f - beta;
        g_covsel[bh*NSLOT] = NL;
        #pragma unroll
        for (int k = 0; k < KTOP; k++) {
            g_shift[bh*NSLOT + 1 + k]  = lag_of(selI[k]);
            g_wslot[bh*NSLOT + 1 + k]  = beta * e[k] / esum;
            g_covsel[bh*NSLOT + 1 + k] = selI[k];
        }
    }
}

// ---------------- attw[s] = weight_s * softmax_c(cov_sel / tau) --------------
__global__ void att_kernel(const float* __restrict__ log_tau_ptr)
{
    const int s = blockIdx.x, bh = blockIdx.y;
    const int l = g_covsel[bh*NSLOT + s];
    const float w = g_wslot[bh*NSLOT + s];
    const float invtau = 1.0f / fmaxf(expf(*log_tau_ptr), 1e-4f);
    const float* covp = g_cov + ((size_t)bh*(NL+1) + l)*(DhD*DhD);
    float* outp = g_attw + ((size_t)bh*NSLOT + s)*(DhD*DhD);
    int warp = threadIdx.x >> 5, lane = threadIdx.x & 31;
    for (int d = warp; d < DhD; d += 8) {
        float v0 = covp[d*DhD + lane]      * invtau;
        float v1 = covp[d*DhD + lane + 32] * invtau;
        float m = fmaxf(v0, v1);
        #pragma unroll
        for (int o = 16; o > 0; o >>= 1) m = fmaxf(m, __shfl_xor_sync(0xffffffffu, m, o));
        float e0 = expf(v0 - m), e1 = expf(v1 - m);
        float ss = e0 + e1;
        #pragma unroll
        for (int o = 16; o > 0; o >>= 1) ss += __shfl_xor_sync(0xffffffffu, ss, o);
        float f = w / ss;
        outp[d*DhD + lane]      = e0 * f;
        outp[d*DhD + lane + 32] = e1 * f;
    }
}

// ---------------- out_h: sum_s V shifted @ attw_s (R3 scalar) ----------------
__global__ void contrib_kernel()
{
    __shared__ float Att[64][68];
    __shared__ float Vs[64][68];
    const int bh = blockIdx.y, t0 = blockIdx.x * 64;
    const int bb = bh >> 3, hh = bh & 7;
    const float* Vb = g_V + (size_t)bh*Tdim*DhD;
    const int tid = threadIdx.x, tx = tid & 15, ty = tid >> 4;
    float acc[4][4] = {};
    for (int s = 0; s < NSLOT; s++) {
        const int shift = g_shift[bh*NSLOT + s];
        const float* ap = g_attw + ((size_t)bh*NSLOT + s)*(DhD*DhD);
        #pragma unroll
        for (int p = tid; p < 1024; p += 256) {
            int row = p >> 4, c4 = (p & 15) << 2;
            *(float4*)&Att[row][c4] = *(const float4*)(ap + row*DhD + c4);
            int src = (t0 + row - shift + Tdim) & (Tdim - 1);
            *(float4*)&Vs[row][c4] = *(const float4*)(Vb + src*DhD + c4);
        }
        __syncthreads();
        #pragma unroll 16
        for (int dd = 0; dd < 64; dd++) {
            float a[4], b[4];
            #pragma unroll
            for (int i = 0; i < 4; i++) a[i] = Vs[ty + 16*i][dd];
            #pragma unroll
            for (int j = 0; j < 4; j++) b[j] = Att[dd][tx + 16*j];
            #pragma unroll
            for (int i = 0; i < 4; i++)
                #pragma unroll
                for (int j = 0; j < 4; j++)
                    acc[i][j] = fmaf(a[i], b[j], acc[i][j]);
        }
        __syncthreads();
    }
    #pragma unroll
    for (int i = 0; i < 4; i++) {
        int t = t0 + ty + 16*i;
        #pragma unroll
        for (int j = 0; j < 4; j++) {
            int c = tx + 16*j;
            g_outh[((size_t)(bb*Tdim + t))*Ddim + hh*DhD + c] = acc[i][j];
        }
    }
}

// ---------------- launch ------------------------------------------------------
extern "C" void kernel_launch(void* const* d_in, const int* in_sizes, int n_in,
                              void* d_out, int out_size)
{
    const float* x           = (const float*)d_in[0];
    const float* Wq          = (const float*)d_in[1];
    const float* bq          = (const float*)d_in[2];
    const float* Wk          = (const float*)d_in[3];
    const float* bk          = (const float*)d_in[4];
    const float* Wv          = (const float*)d_in[5];
    const float* bv          = (const float*)d_in[6];
    const float* Wo          = (const float*)d_in[7];
    const float* bo          = (const float*)d_in[8];
    const float* log_tau     = (const float*)d_in[9];
    const float* lambda_auto = (const float*)d_in[10];
    const float* beta_lag    = (const float*)d_in[11];
    const float* log_tau_lag = (const float*)d_in[12];
    float* out = (float*)d_out;

    gemm_qkv<<<dim3(Bdim*Tdim/64, Ddim/64, 3), 256>>>(x, Wq, bq, Wk, bk, Wv, bv);
    normalize_kernel<<<dim3(BH, 2), 512>>>();
    prep_q_kernel<<<dim3(BH, 8), 256>>>();
    prep_k_kernel<<<dim3(BH, 8), 256>>>();
    cov_mma_kernel<<<dim3(NL+1, BH), 256>>>(lambda_auto);
    topk_kernel<<<BH, 32>>>(log_tau_lag, beta_lag);
    att_kernel<<<dim3(NSLOT, BH), 256>>>(log_tau);
    contrib_kernel<<<dim3(Tdim/64, BH), 256>>>();
    gemm_out<<<dim3(Bdim*Tdim/64, Ddim/64), 256>>>(Wo, bo, out);
}

// round 10
// speedup vs baseline: 1.7975x; 1.1994x over previous
#include <cuda_runtime.h>
#include <cuda_bf16.h>
#include <math.h>
#include <stdint.h>

// Problem constants (fixed shapes from the reference)
#define Bdim 4
#define Hdim 8
#define Tdim 512
#define Ddim 512
#define DhD  64
#define NL   64     // number of lag candidates
#define KTOP 18     // top-k lags = 2*ceil(log2(512)) = 18
#define NSLOT 19    // 1 (lag 0 / instantaneous) + KTOP
#define BH   (Bdim*Hdim)

// lags for T=512, LMAX=64: step=7 -> 1,8,...,442 then last forced to 511
__device__ __forceinline__ int lag_of(int l) { return (l == NL-1) ? (Tdim-1) : (1 + 7*l); }

// ---------------- mma.sync helpers ------------------------------------------
__device__ __forceinline__ uint32_t smem_u32(const void* p) {
    uint32_t a;
    asm("{ .reg .u64 t; cvta.to.shared.u64 t, %1; cvt.u32.u64 %0, t; }" : "=r"(a) : "l"(p));
    return a;
}
__device__ __forceinline__ void ldsm4(uint32_t r[4], uint32_t addr) {
    asm volatile("ldmatrix.sync.aligned.m8n8.x4.shared.b16 {%0,%1,%2,%3}, [%4];"
        : "=r"(r[0]), "=r"(r[1]), "=r"(r[2]), "=r"(r[3]) : "r"(addr));
}
__device__ __forceinline__ void mma16816(float d[4], const uint32_t a[4], const uint32_t b[2]) {
    asm volatile("mma.sync.aligned.m16n8k16.row.col.f32.bf16.bf16.f32 "
        "{%0,%1,%2,%3},{%4,%5,%6,%7},{%8,%9},{%0,%1,%2,%3};"
        : "+f"(d[0]), "+f"(d[1]), "+f"(d[2]), "+f"(d[3])
        : "r"(a[0]), "r"(a[1]), "r"(a[2]), "r"(a[3]), "r"(b[0]), "r"(b[1]));
}

// ---------------- pack helper: fp32 -> (hi bf16, lo bf16) u32 ----------------
__device__ __forceinline__ uint32_t pack_hilo(float v) {
    __nv_bfloat16 h = __float2bfloat16(v);
    float hf = __bfloat162float(h);
    __nv_bfloat16 l = __float2bfloat16(v - hf);
    return (uint32_t)(*(unsigned short*)&h) | ((uint32_t)(*(unsigned short*)&l) << 16);
}

// ---------------- scratch (static device memory; no runtime allocation) ----
__device__ float g_Q[BH*Tdim*DhD];                 // 4 MB, normalized in place
__device__ float g_K[BH*Tdim*DhD];                 // 4 MB
__device__ float g_V[BH*Tdim*DhD];                 // 4 MB
__device__ uint32_t g_xP[Bdim*Tdim*Ddim];          // 4 MB: x packed (hi,lo), row-major
__device__ uint32_t g_WP[4*Ddim*Ddim];             // 4 MB: W^T packed, z = q,k,v,o
__device__ uint32_t g_oP[Bdim*Tdim*Ddim];          // 4 MB: out_h packed (from contrib)
__device__ uint32_t g_Kph[(size_t)BH*4*DhD*1024];  // 33.5 MB: 4 pre-shift phases, doubled
__device__ uint32_t g_QT[(size_t)BH*DhD*512];      // 4.2 MB: [bh][c][t], (hi,lo) packed
__device__ float g_cov[(size_t)BH*(NL+1)*DhD*DhD]; // 34 MB (slot NL = lag 0)
__device__ float g_score[BH*NL];
__device__ int   g_shift[BH*NSLOT];
__device__ float g_wslot[BH*NSLOT];
__device__ int   g_covsel[BH*NSLOT];
__device__ float g_attw[(size_t)BH*NSLOT*DhD*DhD]; // 10 MB

// ---------------- prep_x: pack x -> g_xP (row-major, k-contig) ---------------
__global__ void prep_x_kernel(const float* __restrict__ x)
{
    int i = (blockIdx.x * 256 + threadIdx.x) * 4;
    float4 v = *(const float4*)(x + i);
    uint4 o;
    o.x = pack_hilo(v.x); o.y = pack_hilo(v.y);
    o.z = pack_hilo(v.z); o.w = pack_hilo(v.w);
    *(uint4*)(g_xP + i) = o;
}

// ---------------- prep_w: transpose + pack all 4 weights -> g_WP[z][n][k] ----
__global__ void prep_w_kernel(const float* __restrict__ Wq, const float* __restrict__ Wk,
                              const float* __restrict__ Wv, const float* __restrict__ Wo)
{
    __shared__ uint32_t s[64][65];
    const int z = blockIdx.z;
    const float* W = (z == 0) ? Wq : (z == 1) ? Wk : (z == 2) ? Wv : Wo;
    uint32_t* dst = g_WP + (size_t)z*Ddim*Ddim;
    const int k0 = blockIdx.x * 64, n0 = blockIdx.y * 64;
    const int tid = threadIdx.x;
    #pragma unroll
    for (int p = tid; p < 4096; p += 256) {
        int r = p >> 6, c = p & 63;   // r: k idx, c: n idx
        s[c][r] = pack_hilo(W[(size_t)(k0 + r)*Ddim + n0 + c]);
    }
    __syncthreads();
    #pragma unroll
    for (int p = tid; p < 4096; p += 256) {
        int n = p >> 6, k = p & 63;
        dst[(size_t)(n0 + n)*Ddim + k0 + k] = s[n][k];
    }
}

// ---------------- QKV GEMM via HMMA (cov template) ---------------------------
// C = x @ W + bias, scattered head-major; z selects Q/K/V.
#define TSTRIDE 272
__global__ void __launch_bounds__(256) gemm_qkv_mma(const float* __restrict__ bq,
                                                    const float* __restrict__ bk,
                                                    const float* __restrict__ bv)
{
    __shared__ __align__(16) char sA[64*TSTRIDE];
    __shared__ __align__(16) char sB[64*TSTRIDE];
    const int z = blockIdx.z;
    const float* bias = (z == 0) ? bq : (z == 1) ? bk : bv;
    float* C          = (z == 0) ? g_Q : (z == 1) ? g_K : g_V;
    const uint32_t* BP = g_WP + (size_t)z*Ddim*Ddim;
    const int m0 = blockIdx.x * 64, n0 = blockIdx.y * 64;
    const int tid = threadIdx.x, wid = tid >> 5, lane = tid & 31;
    const int rowstrip = wid & 3, colhalf = wid >> 2;
    const int mw = rowstrip * 16;

    float acc[4][4] = {};

    const int srow = tid >> 2, sseg = tid & 3;
    const int arow_ld = mw + (lane & 15), acol_ld = (lane >> 4) * 8;
    const uint32_t sAb = smem_u32(sA), sBb = smem_u32(sB);

    const uint32_t* srcA0 = g_xP + (size_t)(m0 + srow)*Ddim + sseg*16;
    const uint32_t* srcB0 = BP + (size_t)(n0 + srow)*Ddim + sseg*16;
    uint32_t* dstA = (uint32_t*)(sA + srow*TSTRIDE) + sseg*16;
    uint32_t* dstB = (uint32_t*)(sB + srow*TSTRIDE) + sseg*16;

    for (int chunk = 0; chunk < 8; chunk++) {
        {
            const uint32_t* srcA = srcA0 + chunk*64;
            const uint32_t* srcB = srcB0 + chunk*64;
            #pragma unroll
            for (int i = 0; i < 4; i++)
                *(uint4*)(dstA + 4*i) = *(const uint4*)(srcA + 4*i);
            #pragma unroll
            for (int i = 0; i < 4; i++)
                *(uint4*)(dstB + 4*i) = *(const uint4*)(srcB + 4*i);
        }
        __syncthreads();
        #pragma unroll
        for (int ks = 0; ks < 8; ks++) {
            const int k0 = ks * 16;
            uint32_t a4[4];
            ldsm4(a4, sAb + arow_ld*TSTRIDE + (k0 + acol_ld)*2);
            #pragma unroll
            for (int jt2 = 0; jt2 < 2; jt2++) {
                const int jt = colhalf*2 + jt2;
                const int brow = 16*jt + (lane >> 4)*8 + (lane & 7);
                const int bcol = k0 + ((lane >> 3) & 1)*8;
                uint32_t b4[4];
                ldsm4(b4, sBb + brow*TSTRIDE + bcol*2);
                mma16816(acc[2*jt2],   a4, b4);
                mma16816(acc[2*jt2+1], a4, b4 + 2);
                uint32_t bs[4];
                #pragma unroll
                for (int i = 0; i < 4; i++) bs[i] = __byte_perm(b4[i], 0, 0x1032);
                mma16816(acc[2*jt2],   a4, bs);
                mma16816(acc[2*jt2+1], a4, bs + 2);
            }
        }
        __syncthreads();
    }

    const int g = lane >> 2, tig = lane & 3;
    #pragma unroll
    for (int j = 0; j < 4; j++) {
        const int c0 = colhalf*32 + 8*j + 2*tig;
        #pragma unroll
        for (int half = 0; half < 2; half++) {
            int m = m0 + mw + g + 8*half;
            int b = m >> 9, t = m & (Tdim-1);
            #pragma unroll
            for (int e = 0; e < 2; e++) {
                int n = n0 + c0 + e;
                int h = n >> 6, c = n & (DhD-1);
                C[(((size_t)(b*Hdim + h))*Tdim + t)*DhD + c] = acc[j][2*half + e] + bias[n];
            }
        }
    }
}

// ---------------- output GEMM via HMMA: out = out_h @ Wo + bo ----------------
__global__ void __launch_bounds__(256) gemm_out_mma(const float* __restrict__ bo,
                                                    float* __restrict__ out)
{
    __shared__ __align__(16) char sA[64*TSTRIDE];
    __shared__ __align__(16) char sB[64*TSTRIDE];
    const uint32_t* BP = g_WP + (size_t)3*Ddim*Ddim;
    const int m0 = blockIdx.x * 64, n0 = blockIdx.y * 64;
    const int tid = threadIdx.x, wid = tid >> 5, lane = tid & 31;
    const int rowstrip = wid & 3, colhalf = wid >> 2;
    const int mw = rowstrip * 16;

    float acc[4][4] = {};

    const int srow = tid >> 2, sseg = tid & 3;
    const int arow_ld = mw + (lane & 15), acol_ld = (lane >> 4) * 8;
    const uint32_t sAb = smem_u32(sA), sBb = smem_u32(sB);

    const uint32_t* srcA0 = g_oP + (size_t)(m0 + srow)*Ddim + sseg*16;
    const uint32_t* srcB0 = BP + (size_t)(n0 + srow)*Ddim + sseg*16;
    uint32_t* dstA = (uint32_t*)(sA + srow*TSTRIDE) + sseg*16;
    uint32_t* dstB = (uint32_t*)(sB + srow*TSTRIDE) + sseg*16;

    for (int chunk = 0; chunk < 8; chunk++) {
        {
            const uint32_t* srcA = srcA0 + chunk*64;
            const uint32_t* srcB = srcB0 + chunk*64;
            #pragma unroll
            for (int i = 0; i < 4; i++)
                *(uint4*)(dstA + 4*i) = *(const uint4*)(srcA + 4*i);
            #pragma unroll
            for (int i = 0; i < 4; i++)
                *(uint4*)(dstB + 4*i) = *(const uint4*)(srcB + 4*i);
        }
        __syncthreads();
        #pragma unroll
        for (int ks = 0; ks < 8; ks++) {
            const int k0 = ks * 16;
            uint32_t a4[4];
            ldsm4(a4, sAb + arow_ld*TSTRIDE + (k0 + acol_ld)*2);
            #pragma unroll
            for (int jt2 = 0; jt2 < 2; jt2++) {
                const int jt = colhalf*2 + jt2;
                const int brow = 16*jt + (lane >> 4)*8 + (lane & 7);
                const int bcol = k0 + ((lane >> 3) & 1)*8;
                uint32_t b4[4];
                ldsm4(b4, sBb + brow*TSTRIDE + bcol*2);
                mma16816(acc[2*jt2],   a4, b4);
                mma16816(acc[2*jt2+1], a4, b4 + 2);
                uint32_t bs[4];
                #pragma unroll
                for (int i = 0; i < 4; i++) bs[i] = __byte_perm(b4[i], 0, 0x1032);
                mma16816(acc[2*jt2],   a4, bs);
                mma16816(acc[2*jt2+1], a4, bs + 2);
            }
        }
        __syncthreads();
    }

    const int g = lane >> 2, tig = lane & 3;
    #pragma unroll
    for (int j = 0; j < 4; j++) {
        const int c0 = colhalf*32 + 8*j + 2*tig;
        const int n = n0 + c0;
        const int r0 = m0 + mw + g, r1 = r0 + 8;
        *(float2*)(out + (size_t)r0*Ddim + n) = make_float2(acc[j][0] + bo[n], acc[j][1] + bo[n+1]);
        *(float2*)(out + (size_t)r1*Ddim + n) = make_float2(acc[j][2] + bo[n], acc[j][3] + bo[n+1]);
    }
}

// ---------------- L2-normalize Q and K over the time axis --------------------
__global__ void normalize_kernel()
{
    __shared__ float part[512];
    __shared__ float sinv[DhD];
    int bh = blockIdx.x;
    float* base = (blockIdx.y ? g_K : g_Q) + (size_t)bh*Tdim*DhD;
    int d = threadIdx.x & 63, g = threadIdx.x >> 6;
    float s = 0.f;
    for (int t = g*64; t < (g+1)*64; t++) {
        float v = base[t*DhD + d]; s = fmaf(v, v, s);
    }
    part[threadIdx.x] = s;
    __syncthreads();
    if (threadIdx.x < 64) {
        float tot = 0.f;
        #pragma unroll
        for (int g2 = 0; g2 < 8; g2++) tot += part[d + g2*64];
        sinv[d] = 1.0f / sqrtf(fmaxf(tot, 1e-8f));
    }
    __syncthreads();
    float inv = sinv[d];
    for (int t = g*64; t < (g+1)*64; t++) base[t*DhD + d] *= inv;
}

// ---------------- prep_q: Q transpose + pack -> g_QT[bh][c][512] -------------
__global__ void prep_q_kernel()
{
    __shared__ uint32_t s[64][65];
    const int bh = blockIdx.x, t0 = blockIdx.y * 64;
    const float* src = g_Q + (size_t)bh*Tdim*DhD;
    uint32_t* dst = g_QT + (size_t)bh*DhD*512;
    const int tid = threadIdx.x;
    #pragma unroll
    for (int p = tid; p < 4096; p += 256) {
        int r = p >> 6, d = p & 63;
        s[d][r] = pack_hilo(src[(t0 + r)*DhD + d]);
    }
    __syncthreads();
    #pragma unroll
    for (int p = tid; p < 4096; p += 256) {
        int d = p >> 6, t = p & 63;
        dst[(size_t)d*512 + t0 + t] = s[d][t];
    }
}

// ---------------- prep_k: K transpose + pack + 4 shift-phases, doubled -------
__global__ void prep_k_kernel()
{
    __shared__ uint32_t s[64][65];
    const int bh = blockIdx.x, t0 = blockIdx.y * 64;
    const float* src = g_K + (size_t)bh*Tdim*DhD;
    uint32_t* dst = g_Kph + (size_t)bh*4*DhD*1024;
    const int tid = threadIdx.x;
    #pragma unroll
    for (int p = tid; p < 4096; p += 256) {
        int r = p >> 6, d = p & 63;
        s[d][r] = pack_hilo(src[(t0 + r)*DhD + d]);
    }
    __syncthreads();
    #pragma unroll
    for (int ph = 0; ph < 4; ph++) {
        for (int p = tid; p < 4096; p += 256) {
            int d = p >> 6, t = p & 63;
            uint32_t w = s[d][t];
            int tp = (t0 + t - ph) & (Tdim - 1);
            uint32_t* row = dst + ((size_t)ph*DhD + d)*1024;
            row[tp]       = w;
            row[tp + 512] = w;
        }
    }
}

// ---------------- cov via HMMA, interleaved hi/lo (R9, unchanged) ------------
__global__ void __launch_bounds__(256) cov_mma_kernel(const float* __restrict__ lam_ptr)
{
    __shared__ __align__(16) char sA[64*TSTRIDE];
    __shared__ __align__(16) char sB[64*TSTRIDE];
    __shared__ float s_tot[8], s_dia[8];

    const int slot = blockIdx.x, bh = blockIdx.y;
    const int lag = (slot == NL) ? 0 : lag_of(slot);
    const int tid = threadIdx.x, wid = tid >> 5, lane = tid & 31;
    const int rowstrip = wid & 3, colhalf = wid >> 2;
    const int m0 = rowstrip * 16;

    float acc[4][4] = {};

    const int srow = tid >> 2, sseg = tid & 3;
    const int arow_ld = m0 + (lane & 15), acol_ld = (lane >> 4) * 8;
    const uint32_t sAb = smem_u32(sA), sBb = smem_u32(sB);

    const int ph = (Tdim - lag) & 3;
    const uint32_t* KTp = g_Kph + (((size_t)bh*4 + ph)*DhD + srow)*1024;
    const uint32_t* QTr = g_QT + ((size_t)bh*DhD + srow)*512;
    uint32_t* dstA = (uint32_t*)(sA + srow*TSTRIDE) + sseg*16;
    uint32_t* dstB = (uint32_t*)(sB + srow*TSTRIDE) + sseg*16;

    for (int chunk = 0; chunk < 8; chunk++) {
        const int t0 = chunk * 64;
        {
            const int st = (t0 - lag) & (Tdim - 1);
            const uint32_t* srcA = KTp + (st - ph) + sseg*16;
            const uint32_t* srcB = QTr + t0 + sseg*16;
            #pragma unroll
            for (int i = 0; i < 4; i++)
                *(uint4*)(dstA + 4*i) = *(const uint4*)(srcA + 4*i);
            #pragma unroll
            for (int i = 0; i < 4; i++)
                *(uint4*)(dstB + 4*i) = *(const uint4*)(srcB + 4*i);
        }
        __syncthreads();
        #pragma unroll
        for (int ks = 0; ks < 8; ks++) {
            const int k0 = ks * 16;
            uint32_t a4[4];
            ldsm4(a4, sAb + arow_ld*TSTRIDE + (k0 + acol_ld)*2);
            #pragma unroll
            for (int jt2 = 0; jt2 < 2; jt2++) {
                const int jt = colhalf*2 + jt2;
                const int brow = 16*jt + (lane >> 4)*8 + (lane & 7);
                const int bcol = k0 + ((lane >> 3) & 1)*8;
                uint32_t b4[4];
                ldsm4(b4, sBb + brow*TSTRIDE + bcol*2);
                mma16816(acc[2*jt2],   a4, b4);
                mma16816(acc[2*jt2+1], a4, b4 + 2);
                uint32_t bs[4];
                #pragma unroll
                for (int i = 0; i < 4; i++) bs[i] = __byte_perm(b4[i], 0, 0x1032);
                mma16816(acc[2*jt2],   a4, bs);
                mma16816(acc[2*jt2+1], a4, bs + 2);
            }
        }
        __syncthreads();
    }

    const int g = lane >> 2, tig = lane & 3;
    float tot = 0.f, dia = 0.f;
    float* covp = g_cov + ((size_t)bh*(NL+1) + slot)*(DhD*DhD);
    const int r0 = m0 + g, r1 = m0 + g + 8;
    #pragma unroll
    for (int j = 0; j < 4; j++) {
        const int c0 = colhalf*32 + 8*j + 2*tig;
        *(float2*)(covp + r0*DhD + c0) = make_float2(acc[j][0], acc[j][1]);
        *(float2*)(covp + r1*DhD + c0) = make_float2(acc[j][2], acc[j][3]);
        tot += fabsf(acc[j][0]) + fabsf(acc[j][1]) + fabsf(acc[j][2]) + fabsf(acc[j][3]);
        if (r0 == c0)     dia += fabsf(acc[j][0]);
        if (r0 == c0 + 1) dia += fabsf(acc[j][1]);
        if (r1 == c0)     dia += fabsf(acc[j][2]);
        if (r1 == c0 + 1) dia += fabsf(acc[j][3]);
    }
    if (slot < NL) {
        #pragma unroll
        for (int o = 16; o > 0; o >>= 1) {
            tot += __shfl_xor_sync(0xffffffffu, tot, o);
            dia += __shfl_xor_sync(0xffffffffu, dia, o);
        }
        if (lane == 0) { s_tot[wid] = tot; s_dia[wid] = dia; }
        __syncthreads();
        if (tid == 0) {
            float T = 0.f, D = 0.f;
            #pragma unroll
            for (int w = 0; w < 8; w++) { T += s_tot[w]; D += s_dia[w]; }
            float lam = fminf(fmaxf(*lam_ptr, 0.f), 1.f);
            g_score[bh*NL + slot] = lam*D + (1.f - lam)*(T - D);
        }
    }
}

// ---------------- top-18 lag selection: one warp per bh, shuffle argmax ------
__global__ void topk_kernel(const float* __restrict__ lt_lag,
                            const float* __restrict__ beta_ptr)
{
    const int bh = blockIdx.x, l = threadIdx.x; // 32 threads
    float v0 = g_score[bh*NL + l];
    float v1 = g_score[bh*NL + l + 32];
    float selV[KTOP]; int selI[KTOP];
    #pragma unroll
    for (int k = 0; k < KTOP; k++) {
        float bv; int bi;
        if (v0 >= v1) { bv = v0; bi = l; } else { bv = v1; bi = l + 32; }
        #pragma unroll
        for (int o = 16; o > 0; o >>= 1) {
            float ov = __shfl_xor_sync(0xffffffffu, bv, o);
            int   oi = __shfl_xor_sync(0xffffffffu, bi, o);
            if (ov > bv || (ov == bv && oi < bi)) { bv = ov; bi = oi; }
        }
        selV[k] = bv; selI[k] = bi;
        if (bi == l)      v0 = -3.4e38f;
        if (bi == l + 32) v1 = -3.4e38f;
    }
    if (l == 0) {
        float tl = fmaxf(expf(*lt_lag), 1e-4f);
        float mx = selV[0];
        float e[KTOP], esum = 0.f;
        #pragma unroll
        for (int k = 0; k < KTOP; k++) { e[k] = expf((selV[k] - mx)/tl); esum += e[k]; }
        float beta = fminf(fmaxf(*beta_ptr, 0.f), 1.f);
        g_shift[bh*NSLOT]  = 0;
        g_wslot[bh*NSLOT]  = 1.f - beta;
        g_covsel[bh*NSLOT] = NL;
        #pragma unroll
        for (int k = 0; k < KTOP; k++) {
            g_shift[bh*NSLOT + 1 + k]  = lag_of(selI[k]);
            g_wslot[bh*NSLOT + 1 + k]  = beta * e[k] / esum;
            g_covsel[bh*NSLOT + 1 + k] = selI[k];
        }
    }
}

// ---------------- attw[s] = weight_s * softmax_c(cov_sel / tau) --------------
__global__ void att_kernel(const float* __restrict__ log_tau_ptr)
{
    const int s = blockIdx.x, bh = blockIdx.y;
    const int l = g_covsel[bh*NSLOT + s];
    const float w = g_wslot[bh*NSLOT + s];
    const float invtau = 1.0f / fmaxf(expf(*log_tau_ptr), 1e-4f);
    const float* covp = g_cov + ((size_t)bh*(NL+1) + l)*(DhD*DhD);
    float* outp = g_attw + ((size_t)bh*NSLOT + s)*(DhD*DhD);
    int warp = threadIdx.x >> 5, lane = threadIdx.x & 31;
    for (int d = warp; d < DhD; d += 8) {
        float v0 = covp[d*DhD + lane]      * invtau;
        float v1 = covp[d*DhD + lane + 32] * invtau;
        float m = fmaxf(v0, v1);
        #pragma unroll
        for (int o = 16; o > 0; o >>= 1) m = fmaxf(m, __shfl_xor_sync(0xffffffffu, m, o));
        float e0 = expf(v0 - m), e1 = expf(v1 - m);
        float ss = e0 + e1;
        #pragma unroll
        for (int o = 16; o > 0; o >>= 1) ss += __shfl_xor_sync(0xffffffffu, ss, o);
        float f = w / ss;
        outp[d*DhD + lane]      = e0 * f;
        outp[d*DhD + lane + 32] = e1 * f;
    }
}

// ---------------- out_h: sum_s V shifted @ attw_s (scalar, writes packed) ----
__global__ void contrib_kernel()
{
    __shared__ float Att[64][68];
    __shared__ float Vs[64][68];
    const int bh = blockIdx.y, t0 = blockIdx.x * 64;
    const int bb = bh >> 3, hh = bh & 7;
    const float* Vb = g_V + (size_t)bh*Tdim*DhD;
    const int tid = threadIdx.x, tx = tid & 15, ty = tid >> 4;
    float acc[4][4] = {};
    for (int s = 0; s < NSLOT; s++) {
        const int shift = g_shift[bh*NSLOT + s];
        const float* ap = g_attw + ((size_t)bh*NSLOT + s)*(DhD*DhD);
        #pragma unroll
        for (int p = tid; p < 1024; p += 256) {
            int row = p >> 4, c4 = (p & 15) << 2;
            *(float4*)&Att[row][c4] = *(const float4*)(ap + row*DhD + c4);
            int src = (t0 + row - shift + Tdim) & (Tdim - 1);
            *(float4*)&Vs[row][c4] = *(const float4*)(Vb + src*DhD + c4);
        }
        __syncthreads();
        #pragma unroll 16
        for (int dd = 0; dd < 64; dd++) {
            float a[4], b[4];
            #pragma unroll
            for (int i = 0; i < 4; i++) a[i] = Vs[ty + 16*i][dd];
            #pragma unroll
            for (int j = 0; j < 4; j++) b[j] = Att[dd][tx + 16*j];
            #pragma unroll
            for (int i = 0; i < 4; i++)
                #pragma unroll
                for (int j = 0; j < 4; j++)
                    acc[i][j] = fmaf(a[i], b[j], acc[i][j]);
        }
        __syncthreads();
    }
    #pragma unroll
    for (int i = 0; i < 4; i++) {
        int t = t0 + ty + 16*i;
        #pragma unroll
        for (int j = 0; j < 4; j++) {
            int c = tx + 16*j;
            g_oP[((size_t)(bb*Tdim + t))*Ddim + hh*DhD + c] = pack_hilo(acc[i][j]);
        }
    }
}

// ---------------- launch ------------------------------------------------------
extern "C" void kernel_launch(void* const* d_in, const int* in_sizes, int n_in,
                              void* d_out, int out_size)
{
    const float* x           = (const float*)d_in[0];
    const float* Wq          = (const float*)d_in[1];
    const float* bq          = (const float*)d_in[2];
    const float* Wk          = (const float*)d_in[3];
    const float* bk          = (const float*)d_in[4];
    const float* Wv          = (const float*)d_in[5];
    const float* bv          = (const float*)d_in[6];
    const float* Wo          = (const float*)d_in[7];
    const float* bo          = (const float*)d_in[8];
    const float* log_tau     = (const float*)d_in[9];
    const float* lambda_auto = (const float*)d_in[10];
    const float* beta_lag    = (const float*)d_in[11];
    const float* log_tau_lag = (const float*)d_in[12];
    float* out = (float*)d_out;

    prep_x_kernel<<<Bdim*Tdim*Ddim/1024, 256>>>(x);
    prep_w_kernel<<<dim3(8, 8, 4), 256>>>(Wq, Wk, Wv, Wo);
    gemm_qkv_mma<<<dim3(Bdim*Tdim/64, Ddim/64, 3), 256>>>(bq, bk, bv);
    normalize_kernel<<<dim3(BH, 2), 512>>>();
    prep_q_kernel<<<dim3(BH, 8), 256>>>();
    prep_k_kernel<<<dim3(BH, 8), 256>>>();
    cov_mma_kernel<<<dim3(NL+1, BH), 256>>>(lambda_auto);
    topk_kernel<<<BH, 32>>>(log_tau_lag, beta_lag);
    att_kernel<<<dim3(NSLOT, BH), 256>>>(log_tau);
    contrib_kernel<<<dim3(Tdim/64, BH), 256>>>();
    gemm_out_mma<<<dim3(Bdim*Tdim/64, Ddim/64), 256>>>(bo, out);
}

// round 11
// speedup vs baseline: 1.9600x; 1.0904x over previous
#include <cuda_runtime.h>
#include <cuda_bf16.h>
#include <math.h>
#include <stdint.h>

// Problem constants (fixed shapes from the reference)
#define Bdim 4
#define Hdim 8
#define Tdim 512
#define Ddim 512
#define DhD  64
#define NL   64     // number of lag candidates
#define KTOP 18     // top-k lags = 2*ceil(log2(512)) = 18
#define NSLOT 19    // 1 (lag 0 / instantaneous) + KTOP
#define BH   (Bdim*Hdim)

// lags for T=512, LMAX=64: step=7 -> 1,8,...,442 then last forced to 511
__device__ __forceinline__ int lag_of(int l) { return (l == NL-1) ? (Tdim-1) : (1 + 7*l); }

// ---------------- mma.sync helpers ------------------------------------------
__device__ __forceinline__ uint32_t smem_u32(const void* p) {
    uint32_t a;
    asm("{ .reg .u64 t; cvta.to.shared.u64 t, %1; cvt.u32.u64 %0, t; }" : "=r"(a) : "l"(p));
    return a;
}
__device__ __forceinline__ void ldsm4(uint32_t r[4], uint32_t addr) {
    asm volatile("ldmatrix.sync.aligned.m8n8.x4.shared.b16 {%0,%1,%2,%3}, [%4];"
        : "=r"(r[0]), "=r"(r[1]), "=r"(r[2]), "=r"(r[3]) : "r"(addr));
}
__device__ __forceinline__ void mma16816(float d[4], const uint32_t a[4], const uint32_t b[2]) {
    asm volatile("mma.sync.aligned.m16n8k16.row.col.f32.bf16.bf16.f32 "
        "{%0,%1,%2,%3},{%4,%5,%6,%7},{%8,%9},{%0,%1,%2,%3};"
        : "+f"(d[0]), "+f"(d[1]), "+f"(d[2]), "+f"(d[3])
        : "r"(a[0]), "r"(a[1]), "r"(a[2]), "r"(a[3]), "r"(b[0]), "r"(b[1]));
}

// ---------------- pack helper: fp32 -> (hi bf16, lo bf16) u32 ----------------
__device__ __forceinline__ uint32_t pack_hilo(float v) {
    __nv_bfloat16 h = __float2bfloat16(v);
    float hf = __bfloat162float(h);
    __nv_bfloat16 l = __float2bfloat16(v - hf);
    return (uint32_t)(*(unsigned short*)&h) | ((uint32_t)(*(unsigned short*)&l) << 16);
}

// ---------------- scratch (static device memory; no runtime allocation) ----
__device__ float g_Q[BH*Tdim*DhD];                 // 4 MB, normalized in place
__device__ float g_K[BH*Tdim*DhD];                 // 4 MB
__device__ uint32_t g_VP[BH*Tdim*DhD];             // 4 MB: V packed (hi,lo), head-major
__device__ uint32_t g_xP[Bdim*Tdim*Ddim];          // 4 MB: x packed (hi,lo), row-major
__device__ uint32_t g_WP[4*Ddim*Ddim];             // 4 MB: W^T packed, z = q,k,v,o
__device__ uint32_t g_oP[Bdim*Tdim*Ddim];          // 4 MB: out_h packed (from contrib)
__device__ uint32_t g_Kph[(size_t)BH*4*DhD*1024];  // 33.5 MB: 4 pre-shift phases, doubled
__device__ uint32_t g_QT[(size_t)BH*DhD*512];      // 4.2 MB: [bh][c][t], (hi,lo) packed
__device__ float g_cov[(size_t)BH*(NL+1)*DhD*DhD]; // 34 MB (slot NL = lag 0)
__device__ float g_score[BH*NL];
__device__ int   g_shift[BH*NSLOT];
__device__ float g_wslot[BH*NSLOT];
__device__ int   g_covsel[BH*NSLOT];
__device__ uint32_t g_attwT[(size_t)BH*NSLOT*DhD*DhD]; // 10 MB: [c][d] packed

// ---------------- prep_x: pack x -> g_xP (row-major, k-contig) ---------------
__global__ void prep_x_kernel(const float* __restrict__ x)
{
    int i = (blockIdx.x * 256 + threadIdx.x) * 4;
    float4 v = *(const float4*)(x + i);
    uint4 o;
    o.x = pack_hilo(v.x); o.y = pack_hilo(v.y);
    o.z = pack_hilo(v.z); o.w = pack_hilo(v.w);
    *(uint4*)(g_xP + i) = o;
}

// ---------------- prep_w: transpose + pack all 4 weights -> g_WP[z][n][k] ----
__global__ void prep_w_kernel(const float* __restrict__ Wq, const float* __restrict__ Wk,
                              const float* __restrict__ Wv, const float* __restrict__ Wo)
{
    __shared__ uint32_t s[64][65];
    const int z = blockIdx.z;
    const float* W = (z == 0) ? Wq : (z == 1) ? Wk : (z == 2) ? Wv : Wo;
    uint32_t* dst = g_WP + (size_t)z*Ddim*Ddim;
    const int k0 = blockIdx.x * 64, n0 = blockIdx.y * 64;
    const int tid = threadIdx.x;
    #pragma unroll
    for (int p = tid; p < 4096; p += 256) {
        int r = p >> 6, c = p & 63;   // r: k idx, c: n idx
        s[c][r] = pack_hilo(W[(size_t)(k0 + r)*Ddim + n0 + c]);
    }
    __syncthreads();
    #pragma unroll
    for (int p = tid; p < 4096; p += 256) {
        int n = p >> 6, k = p & 63;
        dst[(size_t)(n0 + n)*Ddim + k0 + k] = s[n][k];
    }
}

// ---------------- QKV GEMM via HMMA (cov template) ---------------------------
// C = x @ W + bias, scattered head-major; z selects Q/K/V. V written packed.
#define TSTRIDE 272
__global__ void __launch_bounds__(256) gemm_qkv_mma(const float* __restrict__ bq,
                                                    const float* __restrict__ bk,
                                                    const float* __restrict__ bv)
{
    __shared__ __align__(16) char sA[64*TSTRIDE];
    __shared__ __align__(16) char sB[64*TSTRIDE];
    const int z = blockIdx.z;
    const float* bias = (z == 0) ? bq : (z == 1) ? bk : bv;
    float* C          = (z == 0) ? g_Q : g_K;
    const uint32_t* BP = g_WP + (size_t)z*Ddim*Ddim;
    const int m0 = blockIdx.x * 64, n0 = blockIdx.y * 64;
    const int tid = threadIdx.x, wid = tid >> 5, lane = tid & 31;
    const int rowstrip = wid & 3, colhalf = wid >> 2;
    const int mw = rowstrip * 16;

    float acc[4][4] = {};

    const int srow = tid >> 2, sseg = tid & 3;
    const int arow_ld = mw + (lane & 15), acol_ld = (lane >> 4) * 8;
    const uint32_t sAb = smem_u32(sA), sBb = smem_u32(sB);

    const uint32_t* srcA0 = g_xP + (size_t)(m0 + srow)*Ddim + sseg*16;
    const uint32_t* srcB0 = BP + (size_t)(n0 + srow)*Ddim + sseg*16;
    uint32_t* dstA = (uint32_t*)(sA + srow*TSTRIDE) + sseg*16;
    uint32_t* dstB = (uint32_t*)(sB + srow*TSTRIDE) + sseg*16;

    for (int chunk = 0; chunk < 8; chunk++) {
        {
            const uint32_t* srcA = srcA0 + chunk*64;
            const uint32_t* srcB = srcB0 + chunk*64;
            #pragma unroll
            for (int i = 0; i < 4; i++)
                *(uint4*)(dstA + 4*i) = *(const uint4*)(srcA + 4*i);
            #pragma unroll
            for (int i = 0; i < 4; i++)
                *(uint4*)(dstB + 4*i) = *(const uint4*)(srcB + 4*i);
        }
        __syncthreads();
        #pragma unroll
        for (int ks = 0; ks < 8; ks++) {
            const int k0 = ks * 16;
            uint32_t a4[4];
            ldsm4(a4, sAb + arow_ld*TSTRIDE + (k0 + acol_ld)*2);
            #pragma unroll
            for (int jt2 = 0; jt2 < 2; jt2++) {
                const int jt = colhalf*2 + jt2;
                const int brow = 16*jt + (lane >> 4)*8 + (lane & 7);
                const int bcol = k0 + ((lane >> 3) & 1)*8;
                uint32_t b4[4];
                ldsm4(b4, sBb + brow*TSTRIDE + bcol*2);
                mma16816(acc[2*jt2],   a4, b4);
                mma16816(acc[2*jt2+1], a4, b4 + 2);
                uint32_t bs[4];
                #pragma unroll
                for (int i = 0; i < 4; i++) bs[i] = __byte_perm(b4[i], 0, 0x1032);
                mma16816(acc[2*jt2],   a4, bs);
                mma16816(acc[2*jt2+1], a4, bs + 2);
            }
        }
        __syncthreads();
    }

    const int g = lane >> 2, tig = lane & 3;
    #pragma unroll
    for (int j = 0; j < 4; j++) {
        const int c0 = colhalf*32 + 8*j + 2*tig;
        #pragma unroll
        for (int half = 0; half < 2; half++) {
            int m = m0 + mw + g + 8*half;
            int b = m >> 9, t = m & (Tdim-1);
            #pragma unroll
            for (int e = 0; e < 2; e++) {
                int n = n0 + c0 + e;
                int h = n >> 6, c = n & (DhD-1);
                size_t idx = (((size_t)(b*Hdim + h))*Tdim + t)*DhD + c;
                float v = acc[j][2*half + e] + bias[n];
                if (z == 2) g_VP[idx] = pack_hilo(v);
                else        C[idx] = v;
            }
        }
    }
}

// ---------------- output GEMM via HMMA: out = out_h @ Wo + bo ----------------
__global__ void __launch_bounds__(256) gemm_out_mma(const float* __restrict__ bo,
                                                    float* __restrict__ out)
{
    __shared__ __align__(16) char sA[64*TSTRIDE];
    __shared__ __align__(16) char sB[64*TSTRIDE];
    const uint32_t* BP = g_WP + (size_t)3*Ddim*Ddim;
    const int m0 = blockIdx.x * 64, n0 = blockIdx.y * 64;
    const int tid = threadIdx.x, wid = tid >> 5, lane = tid & 31;
    const int rowstrip = wid & 3, colhalf = wid >> 2;
    const int mw = rowstrip * 16;

    float acc[4][4] = {};

    const int srow = tid >> 2, sseg = tid & 3;
    const int arow_ld = mw + (lane & 15), acol_ld = (lane >> 4) * 8;
    const uint32_t sAb = smem_u32(sA), sBb = smem_u32(sB);

    const uint32_t* srcA0 = g_oP + (size_t)(m0 + srow)*Ddim + sseg*16;
    const uint32_t* srcB0 = BP + (size_t)(n0 + srow)*Ddim + sseg*16;
    uint32_t* dstA = (uint32_t*)(sA + srow*TSTRIDE) + sseg*16;
    uint32_t* dstB = (uint32_t*)(sB + srow*TSTRIDE) + sseg*16;

    for (int chunk = 0; chunk < 8; chunk++) {
        {
            const uint32_t* srcA = srcA0 + chunk*64;
            const uint32_t* srcB = srcB0 + chunk*64;
            #pragma unroll
            for (int i = 0; i < 4; i++)
                *(uint4*)(dstA + 4*i) = *(const uint4*)(srcA + 4*i);
            #pragma unroll
            for (int i = 0; i < 4; i++)
                *(uint4*)(dstB + 4*i) = *(const uint4*)(srcB + 4*i);
        }
        __syncthreads();
        #pragma unroll
        for (int ks = 0; ks < 8; ks++) {
            const int k0 = ks * 16;
            uint32_t a4[4];
            ldsm4(a4, sAb + arow_ld*TSTRIDE + (k0 + acol_ld)*2);
            #pragma unroll
            for (int jt2 = 0; jt2 < 2; jt2++) {
                const int jt = colhalf*2 + jt2;
                const int brow = 16*jt + (lane >> 4)*8 + (lane & 7);
                const int bcol = k0 + ((lane >> 3) & 1)*8;
                uint32_t b4[4];
                ldsm4(b4, sBb + brow*TSTRIDE + bcol*2);
                mma16816(acc[2*jt2],   a4, b4);
                mma16816(acc[2*jt2+1], a4, b4 + 2);
                uint32_t bs[4];
                #pragma unroll
                for (int i = 0; i < 4; i++) bs[i] = __byte_perm(b4[i], 0, 0x1032);
                mma16816(acc[2*jt2],   a4, bs);
                mma16816(acc[2*jt2+1], a4, bs + 2);
            }
        }
        __syncthreads();
    }

    const int g = lane >> 2, tig = lane & 3;
    #pragma unroll
    for (int j = 0; j < 4; j++) {
        const int c0 = colhalf*32 + 8*j + 2*tig;
        const int n = n0 + c0;
        const int r0 = m0 + mw + g, r1 = r0 + 8;
        *(float2*)(out + (size_t)r0*Ddim + n) = make_float2(acc[j][0] + bo[n], acc[j][1] + bo[n+1]);
        *(float2*)(out + (size_t)r1*Ddim + n) = make_float2(acc[j][2] + bo[n], acc[j][3] + bo[n+1]);
    }
}

// ---------------- L2-normalize Q and K over the time axis --------------------
__global__ void normalize_kernel()
{
    __shared__ float part[512];
    __shared__ float sinv[DhD];
    int bh = blockIdx.x;
    float* base = (blockIdx.y ? g_K : g_Q) + (size_t)bh*Tdim*DhD;
    int d = threadIdx.x & 63, g = threadIdx.x >> 6;
    float s = 0.f;
    for (int t = g*64; t < (g+1)*64; t++) {
        float v = base[t*DhD + d]; s = fmaf(v, v, s);
    }
    part[threadIdx.x] = s;
    __syncthreads();
    if (threadIdx.x < 64) {
        float tot = 0.f;
        #pragma unroll
        for (int g2 = 0; g2 < 8; g2++) tot += part[d + g2*64];
        sinv[d] = 1.0f / sqrtf(fmaxf(tot, 1e-8f));
    }
    __syncthreads();
    float inv = sinv[d];
    for (int t = g*64; t < (g+1)*64; t++) base[t*DhD + d] *= inv;
}

// ---------------- prep_q: Q transpose + pack -> g_QT[bh][c][512] -------------
__global__ void prep_q_kernel()
{
    __shared__ uint32_t s[64][65];
    const int bh = blockIdx.x, t0 = blockIdx.y * 64;
    const float* src = g_Q + (size_t)bh*Tdim*DhD;
    uint32_t* dst = g_QT + (size_t)bh*DhD*512;
    const int tid = threadIdx.x;
    #pragma unroll
    for (int p = tid; p < 4096; p += 256) {
        int r = p >> 6, d = p & 63;
        s[d][r] = pack_hilo(src[(t0 + r)*DhD + d]);
    }
    __syncthreads();
    #pragma unroll
    for (int p = tid; p < 4096; p += 256) {
        int d = p >> 6, t = p & 63;
        dst[(size_t)d*512 + t0 + t] = s[d][t];
    }
}

// ---------------- prep_k: K transpose + pack + 4 shift-phases, doubled -------
__global__ void prep_k_kernel()
{
    __shared__ uint32_t s[64][65];
    const int bh = blockIdx.x, t0 = blockIdx.y * 64;
    const float* src = g_K + (size_t)bh*Tdim*DhD;
    uint32_t* dst = g_Kph + (size_t)bh*4*DhD*1024;
    const int tid = threadIdx.x;
    #pragma unroll
    for (int p = tid; p < 4096; p += 256) {
        int r = p >> 6, d = p & 63;
        s[d][r] = pack_hilo(src[(t0 + r)*DhD + d]);
    }
    __syncthreads();
    #pragma unroll
    for (int ph = 0; ph < 4; ph++) {
        for (int p = tid; p < 4096; p += 256) {
            int d = p >> 6, t = p & 63;
            uint32_t w = s[d][t];
            int tp = (t0 + t - ph) & (Tdim - 1);
            uint32_t* row = dst + ((size_t)ph*DhD + d)*1024;
            row[tp]       = w;
            row[tp + 512] = w;
        }
    }
}

// ---------------- cov via HMMA, interleaved hi/lo (R9, unchanged) ------------
__global__ void __launch_bounds__(256) cov_mma_kernel(const float* __restrict__ lam_ptr)
{
    __shared__ __align__(16) char sA[64*TSTRIDE];
    __shared__ __align__(16) char sB[64*TSTRIDE];
    __shared__ float s_tot[8], s_dia[8];

    const int slot = blockIdx.x, bh = blockIdx.y;
    const int lag = (slot == NL) ? 0 : lag_of(slot);
    const int tid = threadIdx.x, wid = tid >> 5, lane = tid & 31;
    const int rowstrip = wid & 3, colhalf = wid >> 2;
    const int m0 = rowstrip * 16;

    float acc[4][4] = {};

    const int srow = tid >> 2, sseg = tid & 3;
    const int arow_ld = m0 + (lane & 15), acol_ld = (lane >> 4) * 8;
    const uint32_t sAb = smem_u32(sA), sBb = smem_u32(sB);

    const int ph = (Tdim - lag) & 3;
    const uint32_t* KTp = g_Kph + (((size_t)bh*4 + ph)*DhD + srow)*1024;
    const uint32_t* QTr = g_QT + ((size_t)bh*DhD + srow)*512;
    uint32_t* dstA = (uint32_t*)(sA + srow*TSTRIDE) + sseg*16;
    uint32_t* dstB = (uint32_t*)(sB + srow*TSTRIDE) + sseg*16;

    for (int chunk = 0; chunk < 8; chunk++) {
        const int t0 = chunk * 64;
        {
            const int st = (t0 - lag) & (Tdim - 1);
            const uint32_t* srcA = KTp + (st - ph) + sseg*16;
            const uint32_t* srcB = QTr + t0 + sseg*16;
            #pragma unroll
            for (int i = 0; i < 4; i++)
                *(uint4*)(dstA + 4*i) = *(const uint4*)(srcA + 4*i);
            #pragma unroll
            for (int i = 0; i < 4; i++)
                *(uint4*)(dstB + 4*i) = *(const uint4*)(srcB + 4*i);
        }
        __syncthreads();
        #pragma unroll
        for (int ks = 0; ks < 8; ks++) {
            const int k0 = ks * 16;
            uint32_t a4[4];
            ldsm4(a4, sAb + arow_ld*TSTRIDE + (k0 + acol_ld)*2);
            #pragma unroll
            for (int jt2 = 0; jt2 < 2; jt2++) {
                const int jt = colhalf*2 + jt2;
                const int brow = 16*jt + (lane >> 4)*8 + (lane & 7);
                const int bcol = k0 + ((lane >> 3) & 1)*8;
                uint32_t b4[4];
                ldsm4(b4, sBb + brow*TSTRIDE + bcol*2);
                mma16816(acc[2*jt2],   a4, b4);
                mma16816(acc[2*jt2+1], a4, b4 + 2);
                uint32_t bs[4];
                #pragma unroll
                for (int i = 0; i < 4; i++) bs[i] = __byte_perm(b4[i], 0, 0x1032);
                mma16816(acc[2*jt2],   a4, bs);
                mma16816(acc[2*jt2+1], a4, bs + 2);
            }
        }
        __syncthreads();
    }

    const int g = lane >> 2, tig = lane & 3;
    float tot = 0.f, dia = 0.f;
    float* covp = g_cov + ((size_t)bh*(NL+1) + slot)*(DhD*DhD);
    const int r0 = m0 + g, r1 = m0 + g + 8;
    #pragma unroll
    for (int j = 0; j < 4; j++) {
        const int c0 = colhalf*32 + 8*j + 2*tig;
        *(float2*)(covp + r0*DhD + c0) = make_float2(acc[j][0], acc[j][1]);
        *(float2*)(covp + r1*DhD + c0) = make_float2(acc[j][2], acc[j][3]);
        tot += fabsf(acc[j][0]) + fabsf(acc[j][1]) + fabsf(acc[j][2]) + fabsf(acc[j][3]);
        if (r0 == c0)     dia += fabsf(acc[j][0]);
        if (r0 == c0 + 1) dia += fabsf(acc[j][1]);
        if (r1 == c0)     dia += fabsf(acc[j][2]);
        if (r1 == c0 + 1) dia += fabsf(acc[j][3]);
    }
    if (slot < NL) {
        #pragma unroll
        for (int o = 16; o > 0; o >>= 1) {
            tot += __shfl_xor_sync(0xffffffffu, tot, o);
            dia += __shfl_xor_sync(0xffffffffu, dia, o);
        }
        if (lane == 0) { s_tot[wid] = tot; s_dia[wid] = dia; }
        __syncthreads();
        if (tid == 0) {
            float T = 0.f, D = 0.f;
            #pragma unroll
            for (int w = 0; w < 8; w++) { T += s_tot[w]; D += s_dia[w]; }
            float lam = fminf(fmaxf(*lam_ptr, 0.f), 1.f);
            g_score[bh*NL + slot] = lam*D + (1.f - lam)*(T - D);
        }
    }
}

// ---------------- top-18 lag selection: one warp per bh, shuffle argmax ------
__global__ void topk_kernel(const float* __restrict__ lt_lag,
                            const float* __restrict__ beta_ptr)
{
    const int bh = blockIdx.x, l = threadIdx.x; // 32 threads
    float v0 = g_score[bh*NL + l];
    float v1 = g_score[bh*NL + l + 32];
    float selV[KTOP]; int selI[KTOP];
    #pragma unroll
    for (int k = 0; k < KTOP; k++) {
        float bv; int bi;
        if (v0 >= v1) { bv = v0; bi = l; } else { bv = v1; bi = l + 32; }
        #pragma unroll
        for (int o = 16; o > 0; o >>= 1) {
            float ov = __shfl_xor_sync(0xffffffffu, bv, o);
            int   oi = __shfl_xor_sync(0xffffffffu, bi, o);
            if (ov > bv || (ov == bv && oi < bi)) { bv = ov; bi = oi; }
        }
        selV[k] = bv; selI[k] = bi;
        if (bi == l)      v0 = -3.4e38f;
        if (bi == l + 32) v1 = -3.4e38f;
    }
    if (l == 0) {
        float tl = fmaxf(expf(*lt_lag), 1e-4f);
        float mx = selV[0];
        float e[KTOP], esum = 0.f;
        #pragma unroll
        for (int k = 0; k < KTOP; k++) { e[k] = expf((selV[k] - mx)/tl); esum += e[k]; }
        float beta = fminf(fmaxf(*beta_ptr, 0.f), 1.f);
        g_shift[bh*NSLOT]  = 0;
        g_wslot[bh*NSLOT]  = 1.f - beta;
        g_covsel[bh*NSLOT] = NL;
        #pragma unroll
        for (int k = 0; k < KTOP; k++) {
            g_shift[bh*NSLOT + 1 + k]  = lag_of(selI[k]);
            g_wslot[bh*NSLOT + 1 + k]  = beta * e[k] / esum;
            g_covsel[bh*NSLOT + 1 + k] = selI[k];
        }
    }
}

// ---------------- attwT[s][c][d] = pack(weight_s * softmax_c(cov/tau)) -------
__global__ void att_kernel(const float* __restrict__ log_tau_ptr)
{
    __shared__ uint32_t sT[64][65];
    const int s = blockIdx.x, bh = blockIdx.y;
    const int l = g_covsel[bh*NSLOT + s];
    const float w = g_wslot[bh*NSLOT + s];
    const float invtau = 1.0f / fmaxf(expf(*log_tau_ptr), 1e-4f);
    const float* covp = g_cov + ((size_t)bh*(NL+1) + l)*(DhD*DhD);
    uint32_t* outp = g_attwT + ((size_t)bh*NSLOT + s)*(DhD*DhD);
    const int tid = threadIdx.x;
    int warp = tid >> 5, lane = tid & 31;
    for (int d = warp; d < DhD; d += 8) {
        float v0 = covp[d*DhD + lane]      * invtau;
        float v1 = covp[d*DhD + lane + 32] * invtau;
        float m = fmaxf(v0, v1);
        #pragma unroll
        for (int o = 16; o > 0; o >>= 1) m = fmaxf(m, __shfl_xor_sync(0xffffffffu, m, o));
        float e0 = expf(v0 - m), e1 = expf(v1 - m);
        float ss = e0 + e1;
        #pragma unroll
        for (int o = 16; o > 0; o >>= 1) ss += __shfl_xor_sync(0xffffffffu, ss, o);
        float f = w / ss;
        sT[lane][d]      = pack_hilo(e0 * f);
        sT[lane + 32][d] = pack_hilo(e1 * f);
    }
    __syncthreads();
    #pragma unroll
    for (int p = tid; p < 4096; p += 256) {
        outp[p] = sT[p >> 6][p & 63];
    }
}

// ---------------- contrib via HMMA: out_h = sum_s V_shifted @ attw_s ---------
// A rows = whole shifted V rows (contiguous, aligned); B = attwT[c][d].
__global__ void __launch_bounds__(256) contrib_mma_kernel()
{
    __shared__ __align__(16) char sA[64*TSTRIDE];
    __shared__ __align__(16) char sB[64*TSTRIDE];
    const int bh = blockIdx.y, t0 = blockIdx.x * 64;
    const int bb = bh >> 3, hh = bh & 7;
    const int tid = threadIdx.x, wid = tid >> 5, lane = tid & 31;
    const int rowstrip = wid & 3, colhalf = wid >> 2;
    const int mw = rowstrip * 16;

    float acc[4][4] = {};

    const int srow = tid >> 2, sseg = tid & 3;
    const int arow_ld = mw + (lane & 15), acol_ld = (lane >> 4) * 8;
    const uint32_t sAb = smem_u32(sA), sBb = smem_u32(sB);

    const uint32_t* VPb = g_VP + (size_t)bh*Tdim*DhD;
    uint32_t* dstA = (uint32_t*)(sA + srow*TSTRIDE) + sseg*16;
    uint32_t* dstB = (uint32_t*)(sB + srow*TSTRIDE) + sseg*16;

    for (int s = 0; s < NSLOT; s++) {
        const int shift = g_shift[bh*NSLOT + s];
        const uint32_t* ap = g_attwT + ((size_t)bh*NSLOT + s)*(DhD*DhD);
        {
            const int srcT = (t0 + srow - shift + Tdim) & (Tdim - 1);
            const uint32_t* srcA = VPb + (size_t)srcT*DhD + sseg*16;
            const uint32_t* srcB = ap + srow*DhD + sseg*16;
            #pragma unroll
            for (int i = 0; i < 4; i++)
                *(uint4*)(dstA + 4*i) = *(const uint4*)(srcA + 4*i);
            #pragma unroll
            for (int i = 0; i < 4; i++)
                *(uint4*)(dstB + 4*i) = *(const uint4*)(srcB + 4*i);
        }
        __syncthreads();
        #pragma unroll
        for (int ks = 0; ks < 8; ks++) {
            const int k0 = ks * 16;
            uint32_t a4[4];
            ldsm4(a4, sAb + arow_ld*TSTRIDE + (k0 + acol_ld)*2);
            #pragma unroll
            for (int jt2 = 0; jt2 < 2; jt2++) {
                const int jt = colhalf*2 + jt2;
                const int brow = 16*jt + (lane >> 4)*8 + (lane & 7);
                const int bcol = k0 + ((lane >> 3) & 1)*8;
                uint32_t b4[4];
                ldsm4(b4, sBb + brow*TSTRIDE + bcol*2);
                mma16816(acc[2*jt2],   a4, b4);
                mma16816(acc[2*jt2+1], a4, b4 + 2);
                uint32_t bs[4];
                #pragma unroll
                for (int i = 0; i < 4; i++) bs[i] = __byte_perm(b4[i], 0, 0x1032);
                mma16816(acc[2*jt2],   a4, bs);
                mma16816(acc[2*jt2+1], a4, bs + 2);
            }
        }
        __syncthreads();
    }

    const int g = lane >> 2, tig = lane & 3;
    #pragma unroll
    for (int j = 0; j < 4; j++) {
        const int c0 = colhalf*32 + 8*j + 2*tig;
        #pragma unroll
        for (int half = 0; half < 2; half++) {
            int t = t0 + mw + g + 8*half;
            size_t row = ((size_t)(bb*Tdim + t))*Ddim + hh*DhD;
            g_oP[row + c0]     = pack_hilo(acc[j][2*half + 0]);
            g_oP[row + c0 + 1] = pack_hilo(acc[j][2*half + 1]);
        }
    }
}

// ---------------- launch ------------------------------------------------------
extern "C" void kernel_launch(void* const* d_in, const int* in_sizes, int n_in,
                              void* d_out, int out_size)
{
    const float* x           = (const float*)d_in[0];
    const float* Wq          = (const float*)d_in[1];
    const float* bq          = (const float*)d_in[2];
    const float* Wk          = (const float*)d_in[3];
    const float* bk          = (const float*)d_in[4];
    const float* Wv          = (const float*)d_in[5];
    const float* bv          = (const float*)d_in[6];
    const float* Wo          = (const float*)d_in[7];
    const float* bo          = (const float*)d_in[8];
    const float* log_tau     = (const float*)d_in[9];
    const float* lambda_auto = (const float*)d_in[10];
    const float* beta_lag    = (const float*)d_in[11];
    const float* log_tau_lag = (const float*)d_in[12];
    float* out = (float*)d_out;

    prep_x_kernel<<<Bdim*Tdim*Ddim/1024, 256>>>(x);
    prep_w_kernel<<<dim3(8, 8, 4), 256>>>(Wq, Wk, Wv, Wo);
    gemm_qkv_mma<<<dim3(Bdim*Tdim/64, Ddim/64, 3), 256>>>(bq, bk, bv);
    normalize_kernel<<<dim3(BH, 2), 512>>>();
    prep_q_kernel<<<dim3(BH, 8), 256>>>();
    prep_k_kernel<<<dim3(BH, 8), 256>>>();
    cov_mma_kernel<<<dim3(NL+1, BH), 256>>>(lambda_auto);
    topk_kernel<<<BH, 32>>>(log_tau_lag, beta_lag);
    att_kernel<<<dim3(NSLOT, BH), 256>>>(log_tau);
    contrib_mma_kernel<<<dim3(Tdim/64, BH), 256>>>();
    gemm_out_mma<<<dim3(Bdim*Tdim/64, Ddim/64), 256>>>(bo, out);
}

// round 12
// speedup vs baseline: 2.1703x; 1.1073x over previous
#include <cuda_runtime.h>
#include <cuda_bf16.h>
#include <math.h>
#include <stdint.h>

// Problem constants (fixed shapes from the reference)
#define Bdim 4
#define Hdim 8
#define Tdim 512
#define Ddim 512
#define DhD  64
#define NL   64     // number of lag candidates
#define KTOP 18     // top-k lags = 2*ceil(log2(512)) = 18
#define NSLOT 19    // 1 (lag 0 / instantaneous) + KTOP
#define BH   (Bdim*Hdim)

// lags for T=512, LMAX=64: step=7 -> 1,8,...,442 then last forced to 511
__device__ __forceinline__ int lag_of(int l) { return (l == NL-1) ? (Tdim-1) : (1 + 7*l); }

// ---------------- mma.sync helpers ------------------------------------------
__device__ __forceinline__ uint32_t smem_u32(const void* p) {
    uint32_t a;
    asm("{ .reg .u64 t; cvta.to.shared.u64 t, %1; cvt.u32.u64 %0, t; }" : "=r"(a) : "l"(p));
    return a;
}
__device__ __forceinline__ void ldsm4(uint32_t r[4], uint32_t addr) {
    asm volatile("ldmatrix.sync.aligned.m8n8.x4.shared.b16 {%0,%1,%2,%3}, [%4];"
        : "=r"(r[0]), "=r"(r[1]), "=r"(r[2]), "=r"(r[3]) : "r"(addr));
}
__device__ __forceinline__ void mma16816(float d[4], const uint32_t a[4], const uint32_t b[2]) {
    asm volatile("mma.sync.aligned.m16n8k16.row.col.f32.bf16.bf16.f32 "
        "{%0,%1,%2,%3},{%4,%5,%6,%7},{%8,%9},{%0,%1,%2,%3};"
        : "+f"(d[0]), "+f"(d[1]), "+f"(d[2]), "+f"(d[3])
        : "r"(a[0]), "r"(a[1]), "r"(a[2]), "r"(a[3]), "r"(b[0]), "r"(b[1]));
}

// ---------------- pack helper: fp32 -> (hi bf16, lo bf16) u32 ----------------
__device__ __forceinline__ uint32_t pack_hilo(float v) {
    __nv_bfloat16 h = __float2bfloat16(v);
    float hf = __bfloat162float(h);
    __nv_bfloat16 l = __float2bfloat16(v - hf);
    return (uint32_t)(*(unsigned short*)&h) | ((uint32_t)(*(unsigned short*)&l) << 16);
}

// ---------------- scratch (static device memory; no runtime allocation) ----
__device__ float g_Q[BH*Tdim*DhD];                 // 4 MB, raw (pre-norm)
__device__ float g_K[BH*Tdim*DhD];                 // 4 MB, raw (pre-norm)
__device__ uint32_t g_VP[BH*Tdim*DhD];             // 4 MB: V packed (hi,lo), head-major
__device__ uint32_t g_xP[Bdim*Tdim*Ddim];          // 4 MB: x packed (hi,lo), row-major
__device__ uint32_t g_WP[4*Ddim*Ddim];             // 4 MB: W^T packed, z = q,k,v,o
__device__ uint32_t g_oP[Bdim*Tdim*Ddim];          // 4 MB: out_h packed (from contrib)
__device__ uint32_t g_Kph[(size_t)BH*4*DhD*1024];  // 33.5 MB: 4 pre-shift phases, doubled
__device__ uint32_t g_QT[(size_t)BH*DhD*512];      // 4.2 MB: [bh][c][t], (hi,lo) packed
__device__ float g_cov[(size_t)BH*(NL+1)*DhD*DhD]; // 34 MB (slot NL = lag 0)
__device__ float g_score[BH*NL];
__device__ int   g_shift[BH*NSLOT];
__device__ float g_wslot[BH*NSLOT];
__device__ int   g_covsel[BH*NSLOT];
__device__ uint32_t g_attwT[(size_t)BH*NSLOT*DhD*DhD]; // 10 MB: [c][d] packed

// ---------------- prep_x: pack x -> g_xP (row-major, k-contig) ---------------
__global__ void prep_x_kernel(const float* __restrict__ x)
{
    int i = (blockIdx.x * 256 + threadIdx.x) * 4;
    float4 v = *(const float4*)(x + i);
    uint4 o;
    o.x = pack_hilo(v.x); o.y = pack_hilo(v.y);
    o.z = pack_hilo(v.z); o.w = pack_hilo(v.w);
    *(uint4*)(g_xP + i) = o;
}

// ---------------- prep_w: transpose + pack all 4 weights -> g_WP[z][n][k] ----
__global__ void prep_w_kernel(const float* __restrict__ Wq, const float* __restrict__ Wk,
                              const float* __restrict__ Wv, const float* __restrict__ Wo)
{
    __shared__ uint32_t s[64][65];
    const int z = blockIdx.z;
    const float* W = (z == 0) ? Wq : (z == 1) ? Wk : (z == 2) ? Wv : Wo;
    uint32_t* dst = g_WP + (size_t)z*Ddim*Ddim;
    const int k0 = blockIdx.x * 64, n0 = blockIdx.y * 64;
    const int tid = threadIdx.x;
    #pragma unroll
    for (int p = tid; p < 4096; p += 256) {
        int r = p >> 6, c = p & 63;   // r: k idx, c: n idx
        s[c][r] = pack_hilo(W[(size_t)(k0 + r)*Ddim + n0 + c]);
    }
    __syncthreads();
    #pragma unroll
    for (int p = tid; p < 4096; p += 256) {
        int n = p >> 6, k = p & 63;
        dst[(size_t)(n0 + n)*Ddim + k0 + k] = s[n][k];
    }
}

// ---------------- QKV GEMM via HMMA (cov template) ---------------------------
// C = x @ W + bias, scattered head-major; z selects Q/K/V. V written packed.
#define TSTRIDE 272
__global__ void __launch_bounds__(256) gemm_qkv_mma(const float* __restrict__ bq,
                                                    const float* __restrict__ bk,
                                                    const float* __restrict__ bv)
{
    __shared__ __align__(16) char sA[64*TSTRIDE];
    __shared__ __align__(16) char sB[64*TSTRIDE];
    const int z = blockIdx.z;
    const float* bias = (z == 0) ? bq : (z == 1) ? bk : bv;
    float* C          = (z == 0) ? g_Q : g_K;
    const uint32_t* BP = g_WP + (size_t)z*Ddim*Ddim;
    const int m0 = blockIdx.x * 64, n0 = blockIdx.y * 64;
    const int tid = threadIdx.x, wid = tid >> 5, lane = tid & 31;
    const int rowstrip = wid & 3, colhalf = wid >> 2;
    const int mw = rowstrip * 16;

    float acc[4][4] = {};

    const int srow = tid >> 2, sseg = tid & 3;
    const int arow_ld = mw + (lane & 15), acol_ld = (lane >> 4) * 8;
    const uint32_t sAb = smem_u32(sA), sBb = smem_u32(sB);

    const uint32_t* srcA0 = g_xP + (size_t)(m0 + srow)*Ddim + sseg*16;
    const uint32_t* srcB0 = BP + (size_t)(n0 + srow)*Ddim + sseg*16;
    uint32_t* dstA = (uint32_t*)(sA + srow*TSTRIDE) + sseg*16;
    uint32_t* dstB = (uint32_t*)(sB + srow*TSTRIDE) + sseg*16;

    for (int chunk = 0; chunk < 8; chunk++) {
        {
            const uint32_t* srcA = srcA0 + chunk*64;
            const uint32_t* srcB = srcB0 + chunk*64;
            #pragma unroll
            for (int i = 0; i < 4; i++)
                *(uint4*)(dstA + 4*i) = *(const uint4*)(srcA + 4*i);
            #pragma unroll
            for (int i = 0; i < 4; i++)
                *(uint4*)(dstB + 4*i) = *(const uint4*)(srcB + 4*i);
        }
        __syncthreads();
        #pragma unroll
        for (int ks = 0; ks < 8; ks++) {
            const int k0 = ks * 16;
            uint32_t a4[4];
            ldsm4(a4, sAb + arow_ld*TSTRIDE + (k0 + acol_ld)*2);
            #pragma unroll
            for (int jt2 = 0; jt2 < 2; jt2++) {
                const int jt = colhalf*2 + jt2;
                const int brow = 16*jt + (lane >> 4)*8 + (lane & 7);
                const int bcol = k0 + ((lane >> 3) & 1)*8;
                uint32_t b4[4];
                ldsm4(b4, sBb + brow*TSTRIDE + bcol*2);
                mma16816(acc[2*jt2],   a4, b4);
                mma16816(acc[2*jt2+1], a4, b4 + 2);
                uint32_t bs[4];
                #pragma unroll
                for (int i = 0; i < 4; i++) bs[i] = __byte_perm(b4[i], 0, 0x1032);
                mma16816(acc[2*jt2],   a4, bs);
                mma16816(acc[2*jt2+1], a4, bs + 2);
            }
        }
        __syncthreads();
    }

    const int g = lane >> 2, tig = lane & 3;
    #pragma unroll
    for (int j = 0; j < 4; j++) {
        const int c0 = colhalf*32 + 8*j + 2*tig;
        #pragma unroll
        for (int half = 0; half < 2; half++) {
            int m = m0 + mw + g + 8*half;
            int b = m >> 9, t = m & (Tdim-1);
            #pragma unroll
            for (int e = 0; e < 2; e++) {
                int n = n0 + c0 + e;
                int h = n >> 6, c = n & (DhD-1);
                size_t idx = (((size_t)(b*Hdim + h))*Tdim + t)*DhD + c;
                float v = acc[j][2*half + e] + bias[n];
                if (z == 2) g_VP[idx] = pack_hilo(v);
                else        C[idx] = v;
            }
        }
    }
}

// ---------------- output GEMM via HMMA: out = out_h @ Wo + bo ----------------
__global__ void __launch_bounds__(256) gemm_out_mma(const float* __restrict__ bo,
                                                    float* __restrict__ out)
{
    __shared__ __align__(16) char sA[64*TSTRIDE];
    __shared__ __align__(16) char sB[64*TSTRIDE];
    const uint32_t* BP = g_WP + (size_t)3*Ddim*Ddim;
    const int m0 = blockIdx.x * 64, n0 = blockIdx.y * 64;
    const int tid = threadIdx.x, wid = tid >> 5, lane = tid & 31;
    const int rowstrip = wid & 3, colhalf = wid >> 2;
    const int mw = rowstrip * 16;

    float acc[4][4] = {};

    const int srow = tid >> 2, sseg = tid & 3;
    const int arow_ld = mw + (lane & 15), acol_ld = (lane >> 4) * 8;
    const uint32_t sAb = smem_u32(sA), sBb = smem_u32(sB);

    const uint32_t* srcA0 = g_oP + (size_t)(m0 + srow)*Ddim + sseg*16;
    const uint32_t* srcB0 = BP + (size_t)(n0 + srow)*Ddim + sseg*16;
    uint32_t* dstA = (uint32_t*)(sA + srow*TSTRIDE) + sseg*16;
    uint32_t* dstB = (uint32_t*)(sB + srow*TSTRIDE) + sseg*16;

    for (int chunk = 0; chunk < 8; chunk++) {
        {
            const uint32_t* srcA = srcA0 + chunk*64;
            const uint32_t* srcB = srcB0 + chunk*64;
            #pragma unroll
            for (int i = 0; i < 4; i++)
                *(uint4*)(dstA + 4*i) = *(const uint4*)(srcA + 4*i);
            #pragma unroll
            for (int i = 0; i < 4; i++)
                *(uint4*)(dstB + 4*i) = *(const uint4*)(srcB + 4*i);
        }
        __syncthreads();
        #pragma unroll
        for (int ks = 0; ks < 8; ks++) {
            const int k0 = ks * 16;
            uint32_t a4[4];
            ldsm4(a4, sAb + arow_ld*TSTRIDE + (k0 + acol_ld)*2);
            #pragma unroll
            for (int jt2 = 0; jt2 < 2; jt2++) {
                const int jt = colhalf*2 + jt2;
                const int brow = 16*jt + (lane >> 4)*8 + (lane & 7);
                const int bcol = k0 + ((lane >> 3) & 1)*8;
                uint32_t b4[4];
                ldsm4(b4, sBb + brow*TSTRIDE + bcol*2);
                mma16816(acc[2*jt2],   a4, b4);
                mma16816(acc[2*jt2+1], a4, b4 + 2);
                uint32_t bs[4];
                #pragma unroll
                for (int i = 0; i < 4; i++) bs[i] = __byte_perm(b4[i], 0, 0x1032);
                mma16816(acc[2*jt2],   a4, bs);
                mma16816(acc[2*jt2+1], a4, bs + 2);
            }
        }
        __syncthreads();
    }

    const int g = lane >> 2, tig = lane & 3;
    #pragma unroll
    for (int j = 0; j < 4; j++) {
        const int c0 = colhalf*32 + 8*j + 2*tig;
        const int n = n0 + c0;
        const int r0 = m0 + mw + g, r1 = r0 + 8;
        *(float2*)(out + (size_t)r0*Ddim + n) = make_float2(acc[j][0] + bo[n], acc[j][1] + bo[n+1]);
        *(float2*)(out + (size_t)r1*Ddim + n) = make_float2(acc[j][2] + bo[n], acc[j][3] + bo[n+1]);
    }
}

// ---------------- fused: L2-norm (over t) + transpose + pack -----------------
// y=0: Q -> g_QT[bh][c][512].  y=1: K -> g_Kph (4 shift phases, doubled).
__global__ void norm_prep_kernel()
{
    __shared__ float part[256];
    __shared__ float sinv[DhD];
    __shared__ uint32_t s[64][65];
    const int bh = blockIdx.x, isK = blockIdx.y;
    const float* src = (isK ? g_K : g_Q) + (size_t)bh*Tdim*DhD;
    const int tid = threadIdx.x;
    const int d = tid & 63, g = tid >> 6;
    float ssum = 0.f;
    for (int t = g*128; t < (g+1)*128; t++) {
        float v = src[t*DhD + d]; ssum = fmaf(v, v, ssum);
    }
    part[tid] = ssum;
    __syncthreads();
    if (tid < 64) {
        float tot = part[d] + part[d+64] + part[d+128] + part[d+192];
        sinv[d] = 1.0f / sqrtf(fmaxf(tot, 1e-8f));
    }
    __syncthreads();

    if (!isK) {
        uint32_t* dst = g_QT + (size_t)bh*DhD*512;
        for (int tile = 0; tile < 8; tile++) {
            int t0 = tile * 64;
            #pragma unroll
            for (int p = tid; p < 4096; p += 256) {
                int r = p >> 6, dd = p & 63;
                s[dd][r] = pack_hilo(src[(t0 + r)*DhD + dd] * sinv[dd]);
            }
            __syncthreads();
            #pragma unroll
            for (int p = tid; p < 4096; p += 256) {
                int dd = p >> 6, t = p & 63;
                dst[(size_t)dd*512 + t0 + t] = s[dd][t];
            }
            __syncthreads();
        }
    } else {
        uint32_t* dst = g_Kph + (size_t)bh*4*DhD*1024;
        for (int tile = 0; tile < 8; tile++) {
            int t0 = tile * 64;
            #pragma unroll
            for (int p = tid; p < 4096; p += 256) {
                int r = p >> 6, dd = p & 63;
                s[dd][r] = pack_hilo(src[(t0 + r)*DhD + dd] * sinv[dd]);
            }
            __syncthreads();
            #pragma unroll
            for (int ph = 0; ph < 4; ph++) {
                for (int p = tid; p < 4096; p += 256) {
                    int dd = p >> 6, t = p & 63;
                    uint32_t w = s[dd][t];
                    int tp = (t0 + t - ph) & (Tdim - 1);
                    uint32_t* row = dst + ((size_t)ph*DhD + dd)*1024;
                    row[tp]       = w;
                    row[tp + 512] = w;
                }
            }
            __syncthreads();
        }
    }
}

// ---------------- cov via HMMA: 2 lag slots per block, shared Q tile ---------
// slot = 2*pair + s2; slot 64 = lag 0 (cov0), slot 65 = dummy (discarded).
// Chunks of 32 t (64 virtual-k). A: 128 rows (2 slots x 64 d), B: 64 rows.
#define CSTRIDE 144
__global__ void __launch_bounds__(256) cov_mma_kernel(const float* __restrict__ lam_ptr)
{
    __shared__ __align__(16) char sA[128*CSTRIDE];  // 18 KB
    __shared__ __align__(16) char sB[64*CSTRIDE];   // 9 KB
    __shared__ float s_tot[8][2], s_dia[8][2];

    const int pair = blockIdx.x, bh = blockIdx.y;
    const int slot0 = 2*pair, slot1 = 2*pair + 1;
    const int lag0 = (slot0 >= NL) ? 0 : lag_of(slot0);
    const int lag1 = (slot1 >= NL) ? 0 : lag_of(slot1);
    const int tid = threadIdx.x, wid = tid >> 5, lane = tid & 31;
    const int rowstrip = wid & 3, colhalf = wid >> 2;
    const int mw = rowstrip * 16;

    float acc[2][4][4] = {};

    // staging: A 128 rows x 2 segs of 64B; B 64 rows x 4 segs of 32B
    const int srowA = tid >> 1, ssegA = tid & 1;
    const int slotA = srowA >> 6, dA = srowA & 63;
    const int lagA = slotA ? lag1 : lag0;
    const int phA = (Tdim - lagA) & 3;
    const uint32_t* KTp = g_Kph + (((size_t)bh*4 + phA)*DhD + dA)*1024;
    uint32_t* dstA = (uint32_t*)(sA + srowA*CSTRIDE) + ssegA*16;

    const int srowB = tid >> 2, ssegB = tid & 3;
    const uint32_t* QTr = g_QT + ((size_t)bh*DhD + srowB)*512;
    uint32_t* dstB = (uint32_t*)(sB + srowB*CSTRIDE) + ssegB*8;

    const int arow_ld = mw + (lane & 15), acol_ld = (lane >> 4) * 8;
    const uint32_t sAb = smem_u32(sA), sBb = smem_u32(sB);

    for (int chunk = 0; chunk < 16; chunk++) {
        const int t0 = chunk * 32;
        {
            const int st = (t0 - lagA + Tdim) & (Tdim - 1);
            const uint32_t* srcA = KTp + (st - phA) + ssegA*16;
            #pragma unroll
            for (int i = 0; i < 4; i++)
                *(uint4*)(dstA + 4*i) = *(const uint4*)(srcA + 4*i);
            const uint32_t* srcB = QTr + t0 + ssegB*8;
            #pragma unroll
            for (int i = 0; i < 2; i++)
                *(uint4*)(dstB + 4*i) = *(const uint4*)(srcB + 4*i);
        }
        __syncthreads();
        #pragma unroll
        for (int ks = 0; ks < 4; ks++) {
            const int k0 = ks * 16;   // virtual-k within chunk
            uint32_t a0[4], a1[4];
            ldsm4(a0, sAb + arow_ld*CSTRIDE + (k0 + acol_ld)*2);
            ldsm4(a1, sAb + (arow_ld + 64)*CSTRIDE + (k0 + acol_ld)*2);
            #pragma unroll
            for (int jt2 = 0; jt2 < 2; jt2++) {
                const int jt = colhalf*2 + jt2;
                const int brow = 16*jt + (lane >> 4)*8 + (lane & 7);
                const int bcol = k0 + ((lane >> 3) & 1)*8;
                uint32_t b4[4];
                ldsm4(b4, sBb + brow*CSTRIDE + bcol*2);
                mma16816(acc[0][2*jt2],   a0, b4);
                mma16816(acc[0][2*jt2+1], a0, b4 + 2);
                mma16816(acc[1][2*jt2],   a1, b4);
                mma16816(acc[1][2*jt2+1], a1, b4 + 2);
                uint32_t bs[4];
                #pragma unroll
                for (int i = 0; i < 4; i++) bs[i] = __byte_perm(b4[i], 0, 0x1032);
                mma16816(acc[0][2*jt2],   a0, bs);
                mma16816(acc[0][2*jt2+1], a0, bs + 2);
                mma16816(acc[1][2*jt2],   a1, bs);
                mma16816(acc[1][2*jt2+1], a1, bs + 2);
            }
        }
        __syncthreads();
    }

    // ---- epilogue: store cov + fused score, per slot -------------------------
    const int g = lane >> 2, tig = lane & 3;
    const int r0 = mw + g, r1 = mw + g + 8;
    #pragma unroll
    for (int s2 = 0; s2 < 2; s2++) {
        const int slot = 2*pair + s2;
        float tot = 0.f, dia = 0.f;
        if (slot <= NL) {
            float* covp = g_cov + ((size_t)bh*(NL+1) + slot)*(DhD*DhD);
            #pragma unroll
            for (int j = 0; j < 4; j++) {
                const int c0 = colhalf*32 + 8*j + 2*tig;
                *(float2*)(covp + r0*DhD + c0) = make_float2(acc[s2][j][0], acc[s2][j][1]);
                *(float2*)(covp + r1*DhD + c0) = make_float2(acc[s2][j][2], acc[s2][j][3]);
                tot += fabsf(acc[s2][j][0]) + fabsf(acc[s2][j][1])
                     + fabsf(acc[s2][j][2]) + fabsf(acc[s2][j][3]);
                if (r0 == c0)     dia += fabsf(acc[s2][j][0]);
                if (r0 == c0 + 1) dia += fabsf(acc[s2][j][1]);
                if (r1 == c0)     dia += fabsf(acc[s2][j][2]);
                if (r1 == c0 + 1) dia += fabsf(acc[s2][j][3]);
            }
        }
        #pragma unroll
        for (int o = 16; o > 0; o >>= 1) {
            tot += __shfl_xor_sync(0xffffffffu, tot, o);
            dia += __shfl_xor_sync(0xffffffffu, dia, o);
        }
        if (lane == 0) { s_tot[wid][s2] = tot; s_dia[wid][s2] = dia; }
    }
    __syncthreads();
    if (tid < 2) {
        const int slot = 2*pair + tid;
        if (slot < NL) {
            float T = 0.f, D = 0.f;
            #pragma unroll
            for (int w = 0; w < 8; w++) { T += s_tot[w][tid]; D += s_dia[w][tid]; }
            float lam = fminf(fmaxf(*lam_ptr, 0.f), 1.f);
            g_score[bh*NL + slot] = lam*D + (1.f - lam)*(T - D);
        }
    }
}

// ---------------- top-18 lag selection: one warp per bh, shuffle argmax ------
__global__ void topk_kernel(const float* __restrict__ lt_lag,
                            const float* __restrict__ beta_ptr)
{
    const int bh = blockIdx.x, l = threadIdx.x; // 32 threads
    float v0 = g_score[bh*NL + l];
    float v1 = g_score[bh*NL + l + 32];
    float selV[KTOP]; int selI[KTOP];
    #pragma unroll
    for (int k = 0; k < KTOP; k++) {
        float bv; int bi;
        if (v0 >= v1) { bv = v0; bi = l; } else { bv = v1; bi = l + 32; }
        #pragma unroll
        for (int o = 16; o > 0; o >>= 1) {
            float ov = __shfl_xor_sync(0xffffffffu, bv, o);
            int   oi = __shfl_xor_sync(0xffffffffu, bi, o);
            if (ov > bv || (ov == bv && oi < bi)) { bv = ov; bi = oi; }
        }
        selV[k] = bv; selI[k] = bi;
        if (bi == l)      v0 = -3.4e38f;
        if (bi == l + 32) v1 = -3.4e38f;
    }
    if (l == 0) {
        float tl = fmaxf(expf(*lt_lag), 1e-4f);
        float mx = selV[0];
        float e[KTOP], esum = 0.f;
        #pragma unroll
        for (int k = 0; k < KTOP; k++) { e[k] = expf((selV[k] - mx)/tl); esum += e[k]; }
        float beta = fminf(fmaxf(*beta_ptr, 0.f), 1.f);
        g_shift[bh*NSLOT]  = 0;
        g_wslot[bh*NSLOT]  = 1.f - beta;
        g_covsel[bh*NSLOT] = NL;
        #pragma unroll
        for (int k = 0; k < KTOP; k++) {
            g_shift[bh*NSLOT + 1 + k]  = lag_of(selI[k]);
            g_wslot[bh*NSLOT + 1 + k]  = beta * e[k] / esum;
            g_covsel[bh*NSLOT + 1 + k] = selI[k];
        }
    }
}

// ---------------- attwT[s][c][d] = pack(weight_s * softmax_c(cov/tau)) -------
__global__ void att_kernel(const float* __restrict__ log_tau_ptr)
{
    __shared__ uint32_t sT[64][65];
    const int s = blockIdx.x, bh = blockIdx.y;
    const int l = g_covsel[bh*NSLOT + s];
    const float w = g_wslot[bh*NSLOT + s];
    const float invtau = 1.0f / fmaxf(expf(*log_tau_ptr), 1e-4f);
    const float* covp = g_cov + ((size_t)bh*(NL+1) + l)*(DhD*DhD);
    uint32_t* outp = g_attwT + ((size_t)bh*NSLOT + s)*(DhD*DhD);
    const int tid = threadIdx.x;
    int warp = tid >> 5, lane = tid & 31;
    for (int d = warp; d < DhD; d += 8) {
        float v0 = covp[d*DhD + lane]      * invtau;
        float v1 = covp[d*DhD + lane + 32] * invtau;
        float m = fmaxf(v0, v1);
        #pragma unroll
        for (int o = 16; o > 0; o >>= 1) m = fmaxf(m, __shfl_xor_sync(0xffffffffu, m, o));
        float e0 = expf(v0 - m), e1 = expf(v1 - m);
        float ss = e0 + e1;
        #pragma unroll
        for (int o = 16; o > 0; o >>= 1) ss += __shfl_xor_sync(0xffffffffu, ss, o);
        float f = w / ss;
        sT[lane][d]      = pack_hilo(e0 * f);
        sT[lane + 32][d] = pack_hilo(e1 * f);
    }
    __syncthreads();
    #pragma unroll
    for (int p = tid; p < 4096; p += 256) {
        outp[p] = sT[p >> 6][p & 63];
    }
}

// ---------------- contrib via HMMA: out_h = sum_s V_shifted @ attw_s ---------
__global__ void __launch_bounds__(256) contrib_mma_kernel()
{
    __shared__ __align__(16) char sA[64*TSTRIDE];
    __shared__ __align__(16) char sB[64*TSTRIDE];
    const int bh = blockIdx.y, t0 = blockIdx.x * 64;
    const int bb = bh >> 3, hh = bh & 7;
    const int tid = threadIdx.x, wid = tid >> 5, lane = tid & 31;
    const int rowstrip = wid & 3, colhalf = wid >> 2;
    const int mw = rowstrip * 16;

    float acc[4][4] = {};

    const int srow = tid >> 2, sseg = tid & 3;
    const int arow_ld = mw + (lane & 15), acol_ld = (lane >> 4) * 8;
    const uint32_t sAb = smem_u32(sA), sBb = smem_u32(sB);

    const uint32_t* VPb = g_VP + (size_t)bh*Tdim*DhD;
    uint32_t* dstA = (uint32_t*)(sA + srow*TSTRIDE) + sseg*16;
    uint32_t* dstB = (uint32_t*)(sB + srow*TSTRIDE) + sseg*16;

    for (int s = 0; s < NSLOT; s++) {
        const int shift = g_shift[bh*NSLOT + s];
        const uint32_t* ap = g_attwT + ((size_t)bh*NSLOT + s)*(DhD*DhD);
        {
            const int srcT = (t0 + srow - shift + Tdim) & (Tdim - 1);
            const uint32_t* srcA = VPb + (size_t)srcT*DhD + sseg*16;
            const uint32_t* srcB = ap + srow*DhD + sseg*16;
            #pragma unroll
            for (int i = 0; i < 4; i++)
                *(uint4*)(dstA + 4*i) = *(const uint4*)(srcA + 4*i);
            #pragma unroll
            for (int i = 0; i < 4; i++)
                *(uint4*)(dstB + 4*i) = *(const uint4*)(srcB + 4*i);
        }
        __syncthreads();
        #pragma unroll
        for (int ks = 0; ks < 8; ks++) {
            const int k0 = ks * 16;
            uint32_t a4[4];
            ldsm4(a4, sAb + arow_ld*TSTRIDE + (k0 + acol_ld)*2);
            #pragma unroll
            for (int jt2 = 0; jt2 < 2; jt2++) {
                const int jt = colhalf*2 + jt2;
                const int brow = 16*jt + (lane >> 4)*8 + (lane & 7);
                const int bcol = k0 + ((lane >> 3) & 1)*8;
                uint32_t b4[4];
                ldsm4(b4, sBb + brow*TSTRIDE + bcol*2);
                mma16816(acc[2*jt2],   a4, b4);
                mma16816(acc[2*jt2+1], a4, b4 + 2);
                uint32_t bs[4];
                #pragma unroll
                for (int i = 0; i < 4; i++) bs[i] = __byte_perm(b4[i], 0, 0x1032);
                mma16816(acc[2*jt2],   a4, bs);
                mma16816(acc[2*jt2+1], a4, bs + 2);
            }
        }
        __syncthreads();
    }

    const int g = lane >> 2, tig = lane & 3;
    #pragma unroll
    for (int j = 0; j < 4; j++) {
        const int c0 = colhalf*32 + 8*j + 2*tig;
        #pragma unroll
        for (int half = 0; half < 2; half++) {
            int t = t0 + mw + g + 8*half;
            size_t row = ((size_t)(bb*Tdim + t))*Ddim + hh*DhD;
            g_oP[row + c0]     = pack_hilo(acc[j][2*half + 0]);
            g_oP[row + c0 + 1] = pack_hilo(acc[j][2*half + 1]);
        }
    }
}

// ---------------- launch ------------------------------------------------------
extern "C" void kernel_launch(void* const* d_in, const int* in_sizes, int n_in,
                              void* d_out, int out_size)
{
    const float* x           = (const float*)d_in[0];
    const float* Wq          = (const float*)d_in[1];
    const float* bq          = (const float*)d_in[2];
    const float* Wk          = (const float*)d_in[3];
    const float* bk          = (const float*)d_in[4];
    const float* Wv          = (const float*)d_in[5];
    const float* bv          = (const float*)d_in[6];
    const float* Wo          = (const float*)d_in[7];
    const float* bo          = (const float*)d_in[8];
    const float* log_tau     = (const float*)d_in[9];
    const float* lambda_auto = (const float*)d_in[10];
    const float* beta_lag    = (const float*)d_in[11];
    const float* log_tau_lag = (const float*)d_in[12];
    float* out = (float*)d_out;

    prep_x_kernel<<<Bdim*Tdim*Ddim/1024, 256>>>(x);
    prep_w_kernel<<<dim3(8, 8, 4), 256>>>(Wq, Wk, Wv, Wo);
    gemm_qkv_mma<<<dim3(Bdim*Tdim/64, Ddim/64, 3), 256>>>(bq, bk, bv);
    norm_prep_kernel<<<dim3(BH, 2), 256>>>();
    cov_mma_kernel<<<dim3(33, BH), 256>>>(lambda_auto);
    topk_kernel<<<BH, 32>>>(log_tau_lag, beta_lag);
    att_kernel<<<dim3(NSLOT, BH), 256>>>(log_tau);
    contrib_mma_kernel<<<dim3(Tdim/64, BH), 256>>>();
    gemm_out_mma<<<dim3(Bdim*Tdim/64, Ddim/64), 256>>>(bo, out);
}

// round 13
// speedup vs baseline: 2.4253x; 1.1175x over previous
#include <cuda_runtime.h>
#include <cuda_bf16.h>
#include <math.h>
#include <stdint.h>

// Problem constants (fixed shapes from the reference)
#define Bdim 4
#define Hdim 8
#define Tdim 512
#define Ddim 512
#define DhD  64
#define NL   64     // number of lag candidates
#define KTOP 18     // top-k lags = 2*ceil(log2(512)) = 18
#define NSLOT 19    // 1 (lag 0 / instantaneous) + KTOP
#define BH   (Bdim*Hdim)

// lags for T=512, LMAX=64: step=7 -> 1,8,...,442 then last forced to 511
__device__ __forceinline__ int lag_of(int l) { return (l == NL-1) ? (Tdim-1) : (1 + 7*l); }

// ---------------- mma.sync helpers ------------------------------------------
__device__ __forceinline__ uint32_t smem_u32(const void* p) {
    uint32_t a;
    asm("{ .reg .u64 t; cvta.to.shared.u64 t, %1; cvt.u32.u64 %0, t; }" : "=r"(a) : "l"(p));
    return a;
}
__device__ __forceinline__ void ldsm4(uint32_t r[4], uint32_t addr) {
    asm volatile("ldmatrix.sync.aligned.m8n8.x4.shared.b16 {%0,%1,%2,%3}, [%4];"
        : "=r"(r[0]), "=r"(r[1]), "=r"(r[2]), "=r"(r[3]) : "r"(addr));
}
__device__ __forceinline__ void mma16816(float d[4], const uint32_t a[4], const uint32_t b[2]) {
    asm volatile("mma.sync.aligned.m16n8k16.row.col.f32.bf16.bf16.f32 "
        "{%0,%1,%2,%3},{%4,%5,%6,%7},{%8,%9},{%0,%1,%2,%3};"
        : "+f"(d[0]), "+f"(d[1]), "+f"(d[2]), "+f"(d[3])
        : "r"(a[0]), "r"(a[1]), "r"(a[2]), "r"(a[3]), "r"(b[0]), "r"(b[1]));
}

// ---------------- pack helper: fp32 -> (hi bf16, lo bf16) u32 ----------------
__device__ __forceinline__ uint32_t pack_hilo(float v) {
    __nv_bfloat16 h = __float2bfloat16(v);
    float hf = __bfloat162float(h);
    __nv_bfloat16 l = __float2bfloat16(v - hf);
    return (uint32_t)(*(unsigned short*)&h) | ((uint32_t)(*(unsigned short*)&l) << 16);
}

// ---------------- scratch (static device memory; no runtime allocation) ----
__device__ float g_Q[BH*Tdim*DhD];                 // 4 MB, raw (pre-norm)
__device__ float g_K[BH*Tdim*DhD];                 // 4 MB, raw (pre-norm)
__device__ float g_sinv[2*BH*DhD];                 // inv L2 norms (0:Q, 1:K)
__device__ uint32_t g_VP[BH*Tdim*DhD];             // 4 MB: V packed (hi,lo), head-major
__device__ uint32_t g_xP[Bdim*Tdim*Ddim];          // 4 MB: x packed (hi,lo), row-major
__device__ uint32_t g_WP[4*Ddim*Ddim];             // 4 MB: W^T packed, z = q,k,v,o
__device__ uint32_t g_oP[Bdim*Tdim*Ddim];          // 4 MB: out_h packed (from contrib)
__device__ uint32_t g_Kph[(size_t)BH*4*DhD*1024];  // 33.5 MB: 4 pre-shift phases, doubled
__device__ uint32_t g_QT[(size_t)BH*DhD*512];      // 4.2 MB: [bh][c][t], (hi,lo) packed
__device__ float g_cov[(size_t)BH*(NL+1)*DhD*DhD]; // 34 MB (slot NL = lag 0)
__device__ float g_score[BH*NL];
__device__ int   g_shift[BH*NSLOT];
__device__ float g_wslot[BH*NSLOT];
__device__ int   g_covsel[BH*NSLOT];
__device__ uint32_t g_attwT[(size_t)BH*NSLOT*DhD*DhD]; // 10 MB: [c][d] packed

// ---------------- prep_x: pack x -> g_xP (row-major, k-contig) ---------------
__global__ void prep_x_kernel(const float* __restrict__ x)
{
    int i = (blockIdx.x * 256 + threadIdx.x) * 4;
    float4 v = *(const float4*)(x + i);
    uint4 o;
    o.x = pack_hilo(v.x); o.y = pack_hilo(v.y);
    o.z = pack_hilo(v.z); o.w = pack_hilo(v.w);
    *(uint4*)(g_xP + i) = o;
}

// ---------------- prep_w: transpose + pack all 4 weights -> g_WP[z][n][k] ----
__global__ void prep_w_kernel(const float* __restrict__ Wq, const float* __restrict__ Wk,
                              const float* __restrict__ Wv, const float* __restrict__ Wo)
{
    __shared__ uint32_t s[64][65];
    const int z = blockIdx.z;
    const float* W = (z == 0) ? Wq : (z == 1) ? Wk : (z == 2) ? Wv : Wo;
    uint32_t* dst = g_WP + (size_t)z*Ddim*Ddim;
    const int k0 = blockIdx.x * 64, n0 = blockIdx.y * 64;
    const int tid = threadIdx.x;
    #pragma unroll
    for (int p = tid; p < 4096; p += 256) {
        int r = p >> 6, c = p & 63;   // r: k idx, c: n idx
        s[c][r] = pack_hilo(W[(size_t)(k0 + r)*Ddim + n0 + c]);
    }
    __syncthreads();
    #pragma unroll
    for (int p = tid; p < 4096; p += 256) {
        int n = p >> 6, k = p & 63;
        dst[(size_t)(n0 + n)*Ddim + k0 + k] = s[n][k];
    }
}

// ---------------- QKV GEMM via HMMA (pipelined) -------------------------------
// C = x @ W + bias, scattered head-major; z selects Q/K/V. V written packed.
#define TSTRIDE 272
__global__ void __launch_bounds__(256) gemm_qkv_mma(const float* __restrict__ bq,
                                                    const float* __restrict__ bk,
                                                    const float* __restrict__ bv)
{
    __shared__ __align__(16) char sA[64*TSTRIDE];
    __shared__ __align__(16) char sB[64*TSTRIDE];
    const int z = blockIdx.z;
    const float* bias = (z == 0) ? bq : (z == 1) ? bk : bv;
    float* C          = (z == 0) ? g_Q : g_K;
    const uint32_t* BP = g_WP + (size_t)z*Ddim*Ddim;
    const int m0 = blockIdx.x * 64, n0 = blockIdx.y * 64;
    const int tid = threadIdx.x, wid = tid >> 5, lane = tid & 31;
    const int rowstrip = wid & 3, colhalf = wid >> 2;
    const int mw = rowstrip * 16;

    float acc[4][4] = {};

    const int srow = tid >> 2, sseg = tid & 3;
    const int arow_ld = mw + (lane & 15), acol_ld = (lane >> 4) * 8;
    const uint32_t sAb = smem_u32(sA), sBb = smem_u32(sB);

    const uint32_t* srcA0 = g_xP + (size_t)(m0 + srow)*Ddim + sseg*16;
    const uint32_t* srcB0 = BP + (size_t)(n0 + srow)*Ddim + sseg*16;
    uint32_t* dstA = (uint32_t*)(sA + srow*TSTRIDE) + sseg*16;
    uint32_t* dstB = (uint32_t*)(sB + srow*TSTRIDE) + sseg*16;

    uint4 rA[4], rB[4];
    #pragma unroll
    for (int i = 0; i < 4; i++) rA[i] = *(const uint4*)(srcA0 + 4*i);
    #pragma unroll
    for (int i = 0; i < 4; i++) rB[i] = *(const uint4*)(srcB0 + 4*i);

    for (int chunk = 0; chunk < 8; chunk++) {
        #pragma unroll
        for (int i = 0; i < 4; i++) *(uint4*)(dstA + 4*i) = rA[i];
        #pragma unroll
        for (int i = 0; i < 4; i++) *(uint4*)(dstB + 4*i) = rB[i];
        __syncthreads();
        if (chunk < 7) {
            const uint32_t* srcA = srcA0 + (chunk+1)*64;
            const uint32_t* srcB = srcB0 + (chunk+1)*64;
            #pragma unroll
            for (int i = 0; i < 4; i++) rA[i] = *(const uint4*)(srcA + 4*i);
            #pragma unroll
            for (int i = 0; i < 4; i++) rB[i] = *(const uint4*)(srcB + 4*i);
        }
        #pragma unroll
        for (int ks = 0; ks < 8; ks++) {
            const int k0 = ks * 16;
            uint32_t a4[4];
            ldsm4(a4, sAb + arow_ld*TSTRIDE + (k0 + acol_ld)*2);
            #pragma unroll
            for (int jt2 = 0; jt2 < 2; jt2++) {
                const int jt = colhalf*2 + jt2;
                const int brow = 16*jt + (lane >> 4)*8 + (lane & 7);
                const int bcol = k0 + ((lane >> 3) & 1)*8;
                uint32_t b4[4];
                ldsm4(b4, sBb + brow*TSTRIDE + bcol*2);
                mma16816(acc[2*jt2],   a4, b4);
                mma16816(acc[2*jt2+1], a4, b4 + 2);
                uint32_t bs[4];
                #pragma unroll
                for (int i = 0; i < 4; i++) bs[i] = __byte_perm(b4[i], 0, 0x1032);
                mma16816(acc[2*jt2],   a4, bs);
                mma16816(acc[2*jt2+1], a4, bs + 2);
            }
        }
        __syncthreads();
    }

    const int g = lane >> 2, tig = lane & 3;
    #pragma unroll
    for (int j = 0; j < 4; j++) {
        const int c0 = colhalf*32 + 8*j + 2*tig;
        #pragma unroll
        for (int half = 0; half < 2; half++) {
            int m = m0 + mw + g + 8*half;
            int b = m >> 9, t = m & (Tdim-1);
            #pragma unroll
            for (int e = 0; e < 2; e++) {
                int n = n0 + c0 + e;
                int h = n >> 6, c = n & (DhD-1);
                size_t idx = (((size_t)(b*Hdim + h))*Tdim + t)*DhD + c;
                float v = acc[j][2*half + e] + bias[n];
                if (z == 2) g_VP[idx] = pack_hilo(v);
                else        C[idx] = v;
            }
        }
    }
}

// ---------------- output GEMM via HMMA (pipelined) ----------------------------
__global__ void __launch_bounds__(256) gemm_out_mma(const float* __restrict__ bo,
                                                    float* __restrict__ out)
{
    __shared__ __align__(16) char sA[64*TSTRIDE];
    __shared__ __align__(16) char sB[64*TSTRIDE];
    const uint32_t* BP = g_WP + (size_t)3*Ddim*Ddim;
    const int m0 = blockIdx.x * 64, n0 = blockIdx.y * 64;
    const int tid = threadIdx.x, wid = tid >> 5, lane = tid & 31;
    const int rowstrip = wid & 3, colhalf = wid >> 2;
    const int mw = rowstrip * 16;

    float acc[4][4] = {};

    const int srow = tid >> 2, sseg = tid & 3;
    const int arow_ld = mw + (lane & 15), acol_ld = (lane >> 4) * 8;
    const uint32_t sAb = smem_u32(sA), sBb = smem_u32(sB);

    const uint32_t* srcA0 = g_oP + (size_t)(m0 + srow)*Ddim + sseg*16;
    const uint32_t* srcB0 = BP + (size_t)(n0 + srow)*Ddim + sseg*16;
    uint32_t* dstA = (uint32_t*)(sA + srow*TSTRIDE) + sseg*16;
    uint32_t* dstB = (uint32_t*)(sB + srow*TSTRIDE) + sseg*16;

    uint4 rA[4], rB[4];
    #pragma unroll
    for (int i = 0; i < 4; i++) rA[i] = *(const uint4*)(srcA0 + 4*i);
    #pragma unroll
    for (int i = 0; i < 4; i++) rB[i] = *(const uint4*)(srcB0 + 4*i);

    for (int chunk = 0; chunk < 8; chunk++) {
        #pragma unroll
        for (int i = 0; i < 4; i++) *(uint4*)(dstA + 4*i) = rA[i];
        #pragma unroll
        for (int i = 0; i < 4; i++) *(uint4*)(dstB + 4*i) = rB[i];
        __syncthreads();
        if (chunk < 7) {
            const uint32_t* srcA = srcA0 + (chunk+1)*64;
            const uint32_t* srcB = srcB0 + (chunk+1)*64;
            #pragma unroll
            for (int i = 0; i < 4; i++) rA[i] = *(const uint4*)(srcA + 4*i);
            #pragma unroll
            for (int i = 0; i < 4; i++) rB[i] = *(const uint4*)(srcB + 4*i);
        }
        #pragma unroll
        for (int ks = 0; ks < 8; ks++) {
            const int k0 = ks * 16;
            uint32_t a4[4];
            ldsm4(a4, sAb + arow_ld*TSTRIDE + (k0 + acol_ld)*2);
            #pragma unroll
            for (int jt2 = 0; jt2 < 2; jt2++) {
                const int jt = colhalf*2 + jt2;
                const int brow = 16*jt + (lane >> 4)*8 + (lane & 7);
                const int bcol = k0 + ((lane >> 3) & 1)*8;
                uint32_t b4[4];
                ldsm4(b4, sBb + brow*TSTRIDE + bcol*2);
                mma16816(acc[2*jt2],   a4, b4);
                mma16816(acc[2*jt2+1], a4, b4 + 2);
                uint32_t bs[4];
                #pragma unroll
                for (int i = 0; i < 4; i++) bs[i] = __byte_perm(b4[i], 0, 0x1032);
                mma16816(acc[2*jt2],   a4, bs);
                mma16816(acc[2*jt2+1], a4, bs + 2);
            }
        }
        __syncthreads();
    }

    const int g = lane >> 2, tig = lane & 3;
    #pragma unroll
    for (int j = 0; j < 4; j++) {
        const int c0 = colhalf*32 + 8*j + 2*tig;
        const int n = n0 + c0;
        const int r0 = m0 + mw + g, r1 = r0 + 8;
        *(float2*)(out + (size_t)r0*Ddim + n) = make_float2(acc[j][0] + bo[n], acc[j][1] + bo[n+1]);
        *(float2*)(out + (size_t)r1*Ddim + n) = make_float2(acc[j][2] + bo[n], acc[j][3] + bo[n+1]);
    }
}

// ---------------- norm sumsq: g_sinv[side][bh][d] ----------------------------
__global__ void norm_sumsq_kernel()
{
    __shared__ float part[512];
    const int bh = blockIdx.x, isK = blockIdx.y;
    const float* src = (isK ? g_K : g_Q) + (size_t)bh*Tdim*DhD;
    const int d = threadIdx.x & 63, g = threadIdx.x >> 6;
    float s = 0.f;
    for (int t = g*64; t < (g+1)*64; t++) {
        float v = src[t*DhD + d]; s = fmaf(v, v, s);
    }
    part[threadIdx.x] = s;
    __syncthreads();
    if (threadIdx.x < 64) {
        float tot = 0.f;
        #pragma unroll
        for (int g2 = 0; g2 < 8; g2++) tot += part[d + g2*64];
        g_sinv[(isK*BH + bh)*DhD + d] = 1.0f / sqrtf(fmaxf(tot, 1e-8f));
    }
}

// ---------------- prep_q: normalize + transpose + pack -> g_QT ---------------
__global__ void prep_q_kernel()
{
    __shared__ uint32_t s[64][65];
    const int bh = blockIdx.x, t0 = blockIdx.y * 64;
    const float* src = g_Q + (size_t)bh*Tdim*DhD;
    const float* sinv = g_sinv + (size_t)bh*DhD;
    uint32_t* dst = g_QT + (size_t)bh*DhD*512;
    const int tid = threadIdx.x;
    #pragma unroll
    for (int p = tid; p < 4096; p += 256) {
        int r = p >> 6, d = p & 63;
        s[d][r] = pack_hilo(src[(t0 + r)*DhD + d] * sinv[d]);
    }
    __syncthreads();
    #pragma unroll
    for (int p = tid; p < 4096; p += 256) {
        int d = p >> 6, t = p & 63;
        dst[(size_t)d*512 + t0 + t] = s[d][t];
    }
}

// ---------------- prep_k: normalize + transpose + pack + 4 phases ------------
__global__ void prep_k_kernel()
{
    __shared__ uint32_t s[64][65];
    const int bh = blockIdx.x, t0 = blockIdx.y * 64;
    const float* src = g_K + (size_t)bh*Tdim*DhD;
    const float* sinv = g_sinv + (size_t)(BH + bh)*DhD;
    uint32_t* dst = g_Kph + (size_t)bh*4*DhD*1024;
    const int tid = threadIdx.x;
    #pragma unroll
    for (int p = tid; p < 4096; p += 256) {
        int r = p >> 6, d = p & 63;
        s[d][r] = pack_hilo(src[(t0 + r)*DhD + d] * sinv[d]);
    }
    __syncthreads();
    #pragma unroll
    for (int ph = 0; ph < 4; ph++) {
        for (int p = tid; p < 4096; p += 256) {
            int d = p >> 6, t = p & 63;
            uint32_t w = s[d][t];
            int tp = (t0 + t - ph) & (Tdim - 1);
            uint32_t* row = dst + ((size_t)ph*DhD + d)*1024;
            row[tp]       = w;
            row[tp + 512] = w;
        }
    }
}

// ---------------- cov via HMMA: 2 lag slots per block, pipelined -------------
#define CSTRIDE 144
__global__ void __launch_bounds__(256) cov_mma_kernel(const float* __restrict__ lam_ptr)
{
    __shared__ __align__(16) char sA[128*CSTRIDE];  // 18 KB
    __shared__ __align__(16) char sB[64*CSTRIDE];   // 9 KB
    __shared__ float s_tot[8][2], s_dia[8][2];

    const int pair = blockIdx.x, bh = blockIdx.y;
    const int slot0 = 2*pair, slot1 = 2*pair + 1;
    const int lag0 = (slot0 >= NL) ? 0 : lag_of(slot0);
    const int lag1 = (slot1 >= NL) ? 0 : lag_of(slot1);
    const int tid = threadIdx.x, wid = tid >> 5, lane = tid & 31;
    const int rowstrip = wid & 3, colhalf = wid >> 2;
    const int mw = rowstrip * 16;

    float acc[2][4][4] = {};

    const int srowA = tid >> 1, ssegA = tid & 1;
    const int slotA = srowA >> 6, dA = srowA & 63;
    const int lagA = slotA ? lag1 : lag0;
    const int phA = (Tdim - lagA) & 3;
    const uint32_t* KTp = g_Kph + (((size_t)bh*4 + phA)*DhD + dA)*1024;
    uint32_t* dstA = (uint32_t*)(sA + srowA*CSTRIDE) + ssegA*16;

    const int srowB = tid >> 2, ssegB = tid & 3;
    const uint32_t* QTr = g_QT + ((size_t)bh*DhD + srowB)*512;
    uint32_t* dstB = (uint32_t*)(sB + srowB*CSTRIDE) + ssegB*8;

    const int arow_ld = mw + (lane & 15), acol_ld = (lane >> 4) * 8;
    const uint32_t sAb = smem_u32(sA), sBb = smem_u32(sB);

    uint4 rA[4], rB[2];
    {
        const int st = (0 - lagA + Tdim) & (Tdim - 1);
        const uint32_t* srcA = KTp + (st - phA) + ssegA*16;
        #pragma unroll
        for (int i = 0; i < 4; i++) rA[i] = *(const uint4*)(srcA + 4*i);
        const uint32_t* srcB = QTr + ssegB*8;
        #pragma unroll
        for (int i = 0; i < 2; i++) rB[i] = *(const uint4*)(srcB + 4*i);
    }

    for (int chunk = 0; chunk < 16; chunk++) {
        #pragma unroll
        for (int i = 0; i < 4; i++) *(uint4*)(dstA + 4*i) = rA[i];
        #pragma unroll
        for (int i = 0; i < 2; i++) *(uint4*)(dstB + 4*i) = rB[i];
        __syncthreads();
        if (chunk < 15) {
            const int t0n = (chunk+1) * 32;
            const int st = (t0n - lagA + Tdim) & (Tdim - 1);
            const uint32_t* srcA = KTp + (st - phA) + ssegA*16;
            #pragma unroll
            for (int i = 0; i < 4; i++) rA[i] = *(const uint4*)(srcA + 4*i);
            const uint32_t* srcB = QTr + t0n + ssegB*8;
            #pragma unroll
            for (int i = 0; i < 2; i++) rB[i] = *(const uint4*)(srcB + 4*i);
        }
        #pragma unroll
        for (int ks = 0; ks < 4; ks++) {
            const int k0 = ks * 16;
            uint32_t a0[4], a1[4];
            ldsm4(a0, sAb + arow_ld*CSTRIDE + (k0 + acol_ld)*2);
            ldsm4(a1, sAb + (arow_ld + 64)*CSTRIDE + (k0 + acol_ld)*2);
            #pragma unroll
            for (int jt2 = 0; jt2 < 2; jt2++) {
                const int jt = colhalf*2 + jt2;
                const int brow = 16*jt + (lane >> 4)*8 + (lane & 7);
                const int bcol = k0 + ((lane >> 3) & 1)*8;
                uint32_t b4[4];
                ldsm4(b4, sBb + brow*CSTRIDE + bcol*2);
                mma16816(acc[0][2*jt2],   a0, b4);
                mma16816(acc[0][2*jt2+1], a0, b4 + 2);
                mma16816(acc[1][2*jt2],   a1, b4);
                mma16816(acc[1][2*jt2+1], a1, b4 + 2);
                uint32_t bs[4];
                #pragma unroll
                for (int i = 0; i < 4; i++) bs[i] = __byte_perm(b4[i], 0, 0x1032);
                mma16816(acc[0][2*jt2],   a0, bs);
                mma16816(acc[0][2*jt2+1], a0, bs + 2);
                mma16816(acc[1][2*jt2],   a1, bs);
                mma16816(acc[1][2*jt2+1], a1, bs + 2);
            }
        }
        __syncthreads();
    }

    const int g = lane >> 2, tig = lane & 3;
    const int r0 = mw + g, r1 = mw + g + 8;
    #pragma unroll
    for (int s2 = 0; s2 < 2; s2++) {
        const int slot = 2*pair + s2;
        float tot = 0.f, dia = 0.f;
        if (slot <= NL) {
            float* covp = g_cov + ((size_t)bh*(NL+1) + slot)*(DhD*DhD);
            #pragma unroll
            for (int j = 0; j < 4; j++) {
                const int c0 = colhalf*32 + 8*j + 2*tig;
                *(float2*)(covp + r0*DhD + c0) = make_float2(acc[s2][j][0], acc[s2][j][1]);
                *(float2*)(covp + r1*DhD + c0) = make_float2(acc[s2][j][2], acc[s2][j][3]);
                tot += fabsf(acc[s2][j][0]) + fabsf(acc[s2][j][1])
                     + fabsf(acc[s2][j][2]) + fabsf(acc[s2][j][3]);
                if (r0 == c0)     dia += fabsf(acc[s2][j][0]);
                if (r0 == c0 + 1) dia += fabsf(acc[s2][j][1]);
                if (r1 == c0)     dia += fabsf(acc[s2][j][2]);
                if (r1 == c0 + 1) dia += fabsf(acc[s2][j][3]);
            }
        }
        #pragma unroll
        for (int o = 16; o > 0; o >>= 1) {
            tot += __shfl_xor_sync(0xffffffffu, tot, o);
            dia += __shfl_xor_sync(0xffffffffu, dia, o);
        }
        if (lane == 0) { s_tot[wid][s2] = tot; s_dia[wid][s2] = dia; }
    }
    __syncthreads();
    if (tid < 2) {
        const int slot = 2*pair + tid;
        if (slot < NL) {
            float T = 0.f, D = 0.f;
            #pragma unroll
            for (int w = 0; w < 8; w++) { T += s_tot[w][tid]; D += s_dia[w][tid]; }
            float lam = fminf(fmaxf(*lam_ptr, 0.f), 1.f);
            g_score[bh*NL + slot] = lam*D + (1.f - lam)*(T - D);
        }
    }
}

// ---------------- top-18 lag selection: one warp per bh, shuffle argmax ------
__global__ void topk_kernel(const float* __restrict__ lt_lag,
                            const float* __restrict__ beta_ptr)
{
    const int bh = blockIdx.x, l = threadIdx.x; // 32 threads
    float v0 = g_score[bh*NL + l];
    float v1 = g_score[bh*NL + l + 32];
    float selV[KTOP]; int selI[KTOP];
    #pragma unroll
    for (int k = 0; k < KTOP; k++) {
        float bv; int bi;
        if (v0 >= v1) { bv = v0; bi = l; } else { bv = v1; bi = l + 32; }
        #pragma unroll
        for (int o = 16; o > 0; o >>= 1) {
            float ov = __shfl_xor_sync(0xffffffffu, bv, o);
            int   oi = __shfl_xor_sync(0xffffffffu, bi, o);
            if (ov > bv || (ov == bv && oi < bi)) { bv = ov; bi = oi; }
        }
        selV[k] = bv; selI[k] = bi;
        if (bi == l)      v0 = -3.4e38f;
        if (bi == l + 32) v1 = -3.4e38f;
    }
    if (l == 0) {
        float tl = fmaxf(expf(*lt_lag), 1e-4f);
        float mx = selV[0];
        float e[KTOP], esum = 0.f;
        #pragma unroll
        for (int k = 0; k < KTOP; k++) { e[k] = expf((selV[k] - mx)/tl); esum += e[k]; }
        float beta = fminf(fmaxf(*beta_ptr, 0.f), 1.f);
        g_shift[bh*NSLOT]  = 0;
        g_wslot[bh*NSLOT]  = 1.f - beta;
        g_covsel[bh*NSLOT] = NL;
        #pragma unroll
        for (int k = 0; k < KTOP; k++) {
            g_shift[bh*NSLOT + 1 + k]  = lag_of(selI[k]);
            g_wslot[bh*NSLOT + 1 + k]  = beta * e[k] / esum;
            g_covsel[bh*NSLOT + 1 + k] = selI[k];
        }
    }
}

// ---------------- attwT[s][c][d] = pack(weight_s * softmax_c(cov/tau)) -------
__global__ void att_kernel(const float* __restrict__ log_tau_ptr)
{
    __shared__ uint32_t sT[64][65];
    const int s = blockIdx.x, bh = blockIdx.y;
    const int l = g_covsel[bh*NSLOT + s];
    const float w = g_wslot[bh*NSLOT + s];
    const float invtau = 1.0f / fmaxf(expf(*log_tau_ptr), 1e-4f);
    const float* covp = g_cov + ((size_t)bh*(NL+1) + l)*(DhD*DhD);
    uint32_t* outp = g_attwT + ((size_t)bh*NSLOT + s)*(DhD*DhD);
    const int tid = threadIdx.x;
    int warp = tid >> 5, lane = tid & 31;
    for (int d = warp; d < DhD; d += 8) {
        float v0 = covp[d*DhD + lane]      * invtau;
        float v1 = covp[d*DhD + lane + 32] * invtau;
        float m = fmaxf(v0, v1);
        #pragma unroll
        for (int o = 16; o > 0; o >>= 1) m = fmaxf(m, __shfl_xor_sync(0xffffffffu, m, o));
        float e0 = expf(v0 - m), e1 = expf(v1 - m);
        float ss = e0 + e1;
        #pragma unroll
        for (int o = 16; o > 0; o >>= 1) ss += __shfl_xor_sync(0xffffffffu, ss, o);
        float f = w / ss;
        sT[lane][d]      = pack_hilo(e0 * f);
        sT[lane + 32][d] = pack_hilo(e1 * f);
    }
    __syncthreads();
    #pragma unroll
    for (int p = tid; p < 4096; p += 256) {
        outp[p] = sT[p >> 6][p & 63];
    }
}

// ---------------- contrib via HMMA (pipelined): sum_s V_shifted @ attw_s -----
__global__ void __launch_bounds__(256) contrib_mma_kernel()
{
    __shared__ __align__(16) char sA[64*TSTRIDE];
    __shared__ __align__(16) char sB[64*TSTRIDE];
    const int bh = blockIdx.y, t0 = blockIdx.x * 64;
    const int bb = bh >> 3, hh = bh & 7;
    const int tid = threadIdx.x, wid = tid >> 5, lane = tid & 31;
    const int rowstrip = wid & 3, colhalf = wid >> 2;
    const int mw = rowstrip * 16;

    float acc[4][4] = {};

    const int srow = tid >> 2, sseg = tid & 3;
    const int arow_ld = mw + (lane & 15), acol_ld = (lane >> 4) * 8;
    const uint32_t sAb = smem_u32(sA), sBb = smem_u32(sB);

    const uint32_t* VPb = g_VP + (size_t)bh*Tdim*DhD;
    uint32_t* dstA = (uint32_t*)(sA + srow*TSTRIDE) + sseg*16;
    uint32_t* dstB = (uint32_t*)(sB + srow*TSTRIDE) + sseg*16;

    uint4 rA[4], rB[4];
    {
        const int shift = g_shift[bh*NSLOT];
        const uint32_t* ap = g_attwT + (size_t)bh*NSLOT*(DhD*DhD);
        const int srcT = (t0 + srow - shift + Tdim) & (Tdim - 1);
        const uint32_t* srcA = VPb + (size_t)srcT*DhD + sseg*16;
        const uint32_t* srcB = ap + srow*DhD + sseg*16;
        #pragma unroll
        for (int i = 0; i < 4; i++) rA[i] = *(const uint4*)(srcA + 4*i);
        #pragma unroll
        for (int i = 0; i < 4; i++) rB[i] = *(const uint4*)(srcB + 4*i);
    }

    for (int s = 0; s < NSLOT; s++) {
        #pragma unroll
        for (int i = 0; i < 4; i++) *(uint4*)(dstA + 4*i) = rA[i];
        #pragma unroll
        for (int i = 0; i < 4; i++) *(uint4*)(dstB + 4*i) = rB[i];
        __syncthreads();
        if (s < NSLOT - 1) {
            const int shift = g_shift[bh*NSLOT + s + 1];
            const uint32_t* ap = g_attwT + ((size_t)bh*NSLOT + s + 1)*(DhD*DhD);
            const int srcT = (t0 + srow - shift + Tdim) & (Tdim - 1);
            const uint32_t* srcA = VPb + (size_t)srcT*DhD + sseg*16;
            const uint32_t* srcB = ap + srow*DhD + sseg*16;
            #pragma unroll
            for (int i = 0; i < 4; i++) rA[i] = *(const uint4*)(srcA + 4*i);
            #pragma unroll
            for (int i = 0; i < 4; i++) rB[i] = *(const uint4*)(srcB + 4*i);
        }
        #pragma unroll
        for (int ks = 0; ks < 8; ks++) {
            const int k0 = ks * 16;
            uint32_t a4[4];
            ldsm4(a4, sAb + arow_ld*TSTRIDE + (k0 + acol_ld)*2);
            #pragma unroll
            for (int jt2 = 0; jt2 < 2; jt2++) {
                const int jt = colhalf*2 + jt2;
                const int brow = 16*jt + (lane >> 4)*8 + (lane & 7);
                const int bcol = k0 + ((lane >> 3) & 1)*8;
                uint32_t b4[4];
                ldsm4(b4, sBb + brow*TSTRIDE + bcol*2);
                mma16816(acc[2*jt2],   a4, b4);
                mma16816(acc[2*jt2+1], a4, b4 + 2);
                uint32_t bs[4];
                #pragma unroll
                for (int i = 0; i < 4; i++) bs[i] = __byte_perm(b4[i], 0, 0x1032);
                mma16816(acc[2*jt2],   a4, bs);
                mma16816(acc[2*jt2+1], a4, bs + 2);
            }
        }
        __syncthreads();
    }

    const int g = lane >> 2, tig = lane & 3;
    #pragma unroll
    for (int j = 0; j < 4; j++) {
        const int c0 = colhalf*32 + 8*j + 2*tig;
        #pragma unroll
        for (int half = 0; half < 2; half++) {
            int t = t0 + mw + g + 8*half;
            size_t row = ((size_t)(bb*Tdim + t))*Ddim + hh*DhD;
            g_oP[row + c0]     = pack_hilo(acc[j][2*half + 0]);
            g_oP[row + c0 + 1] = pack_hilo(acc[j][2*half + 1]);
        }
    }
}

// ---------------- launch ------------------------------------------------------
extern "C" void kernel_launch(void* const* d_in, const int* in_sizes, int n_in,
                              void* d_out, int out_size)
{
    const float* x           = (const float*)d_in[0];
    const float* Wq          = (const float*)d_in[1];
    const float* bq          = (const float*)d_in[2];
    const float* Wk          = (const float*)d_in[3];
    const float* bk          = (const float*)d_in[4];
    const float* Wv          = (const float*)d_in[5];
    const float* bv          = (const float*)d_in[6];
    const float* Wo          = (const float*)d_in[7];
    const float* bo          = (const float*)d_in[8];
    const float* log_tau     = (const float*)d_in[9];
    const float* lambda_auto = (const float*)d_in[10];
    const float* beta_lag    = (const float*)d_in[11];
    const float* log_tau_lag = (const float*)d_in[12];
    float* out = (float*)d_out;

    prep_x_kernel<<<Bdim*Tdim*Ddim/1024, 256>>>(x);
    prep_w_kernel<<<dim3(8, 8, 4), 256>>>(Wq, Wk, Wv, Wo);
    gemm_qkv_mma<<<dim3(Bdim*Tdim/64, Ddim/64, 3), 256>>>(bq, bk, bv);
    norm_sumsq_kernel<<<dim3(BH, 2), 512>>>();
    prep_q_kernel<<<dim3(BH, 8), 256>>>();
    prep_k_kernel<<<dim3(BH, 8), 256>>>();
    cov_mma_kernel<<<dim3(33, BH), 256>>>(lambda_auto);
    topk_kernel<<<BH, 32>>>(log_tau_lag, beta_lag);
    att_kernel<<<dim3(NSLOT, BH), 256>>>(log_tau);
    contrib_mma_kernel<<<dim3(Tdim/64, BH), 256>>>();
    gemm_out_mma<<<dim3(Bdim*Tdim/64, Ddim/64), 256>>>(bo, out);
}

// round 14
// speedup vs baseline: 2.7635x; 1.1394x over previous
#include <cuda_runtime.h>
#include <cuda_bf16.h>
#include <math.h>
#include <stdint.h>

// Problem constants (fixed shapes from the reference)
#define Bdim 4
#define Hdim 8
#define Tdim 512
#define Ddim 512
#define DhD  64
#define NL   64     // number of lag candidates
#define KTOP 18     // top-k lags = 2*ceil(log2(512)) = 18
#define NSLOT 19    // 1 (lag 0 / instantaneous) + KTOP
#define BH   (Bdim*Hdim)

// lags for T=512, LMAX=64: step=7 -> 1,8,...,442 then last forced to 511
__device__ __forceinline__ int lag_of(int l) { return (l == NL-1) ? (Tdim-1) : (1 + 7*l); }

// ---------------- mma.sync helpers ------------------------------------------
__device__ __forceinline__ uint32_t smem_u32(const void* p) {
    uint32_t a;
    asm("{ .reg .u64 t; cvta.to.shared.u64 t, %1; cvt.u32.u64 %0, t; }" : "=r"(a) : "l"(p));
    return a;
}
__device__ __forceinline__ void ldsm4(uint32_t r[4], uint32_t addr) {
    asm volatile("ldmatrix.sync.aligned.m8n8.x4.shared.b16 {%0,%1,%2,%3}, [%4];"
        : "=r"(r[0]), "=r"(r[1]), "=r"(r[2]), "=r"(r[3]) : "r"(addr));
}
__device__ __forceinline__ void mma16816(float d[4], const uint32_t a[4], const uint32_t b[2]) {
    asm volatile("mma.sync.aligned.m16n8k16.row.col.f32.bf16.bf16.f32 "
        "{%0,%1,%2,%3},{%4,%5,%6,%7},{%8,%9},{%0,%1,%2,%3};"
        : "+f"(d[0]), "+f"(d[1]), "+f"(d[2]), "+f"(d[3])
        : "r"(a[0]), "r"(a[1]), "r"(a[2]), "r"(a[3]), "r"(b[0]), "r"(b[1]));
}

// ---------------- pack helper: fp32 -> (hi bf16, lo bf16) u32 ----------------
__device__ __forceinline__ uint32_t pack_hilo(float v) {
    __nv_bfloat16 h = __float2bfloat16(v);
    float hf = __bfloat162float(h);
    __nv_bfloat16 l = __float2bfloat16(v - hf);
    return (uint32_t)(*(unsigned short*)&h) | ((uint32_t)(*(unsigned short*)&l) << 16);
}

// ---------------- scratch (static device memory; no runtime allocation) ----
__device__ float g_Q[BH*Tdim*DhD];                 // 4 MB, raw (pre-norm)
__device__ float g_K[BH*Tdim*DhD];                 // 4 MB, raw (pre-norm)
__device__ float g_sinv[2*BH*DhD];                 // inv L2 norms (0:Q, 1:K)
__device__ uint32_t g_VP[BH*Tdim*DhD];             // 4 MB: V packed (hi,lo), head-major
__device__ uint32_t g_xP[Bdim*Tdim*Ddim];          // 4 MB: x packed (hi,lo), row-major
__device__ uint32_t g_WP[4*Ddim*Ddim];             // 4 MB: W^T packed, z = q,k,v,o
__device__ uint32_t g_oP[Bdim*Tdim*Ddim];          // 4 MB: out_h packed (from contrib)
__device__ uint32_t g_Kph[(size_t)BH*4*DhD*1024];  // 33.5 MB: 4 pre-shift phases, doubled
__device__ uint32_t g_QT[(size_t)BH*DhD*512];      // 4.2 MB: [bh][c][t], (hi,lo) packed
__device__ float g_cov[(size_t)BH*(NL+1)*DhD*DhD]; // 34 MB (slot NL = lag 0)
__device__ float g_score[BH*NL];
__device__ int   g_shift[BH*NSLOT];
__device__ float g_wslot[BH*NSLOT];
__device__ int   g_covsel[BH*NSLOT];
__device__ uint32_t g_attwT[(size_t)BH*NSLOT*DhD*DhD]; // 10 MB: [c][d] packed

// ---------------- prep_x: pack x -> g_xP (row-major, k-contig) ---------------
__global__ void prep_x_kernel(const float* __restrict__ x)
{
    int i = (blockIdx.x * 256 + threadIdx.x) * 4;
    float4 v = *(const float4*)(x + i);
    uint4 o;
    o.x = pack_hilo(v.x); o.y = pack_hilo(v.y);
    o.z = pack_hilo(v.z); o.w = pack_hilo(v.w);
    *(uint4*)(g_xP + i) = o;
}

// ---------------- prep_w: transpose + pack all 4 weights -> g_WP[z][n][k] ----
__global__ void prep_w_kernel(const float* __restrict__ Wq, const float* __restrict__ Wk,
                              const float* __restrict__ Wv, const float* __restrict__ Wo)
{
    __shared__ uint32_t s[64][65];
    const int z = blockIdx.z;
    const float* W = (z == 0) ? Wq : (z == 1) ? Wk : (z == 2) ? Wv : Wo;
    uint32_t* dst = g_WP + (size_t)z*Ddim*Ddim;
    const int k0 = blockIdx.x * 64, n0 = blockIdx.y * 64;
    const int tid = threadIdx.x;
    #pragma unroll
    for (int p = tid; p < 4096; p += 256) {
        int r = p >> 6, c = p & 63;   // r: k idx, c: n idx
        s[c][r] = pack_hilo(W[(size_t)(k0 + r)*Ddim + n0 + c]);
    }
    __syncthreads();
    #pragma unroll
    for (int p = tid; p < 4096; p += 256) {
        int n = p >> 6, k = p & 63;
        dst[(size_t)(n0 + n)*Ddim + k0 + k] = s[n][k];
    }
}

// ---------------- QKV GEMM via HMMA, M=128 tile, pipelined -------------------
// C = x @ W + bias, scattered head-major; z selects Q/K/V. V written packed.
#define CSTRIDE 144
__global__ void __launch_bounds__(256) gemm_qkv_mma(const float* __restrict__ bq,
                                                    const float* __restrict__ bk,
                                                    const float* __restrict__ bv)
{
    __shared__ __align__(16) char sA[128*CSTRIDE];  // 18 KB
    __shared__ __align__(16) char sB[64*CSTRIDE];   // 9 KB
    const int z = blockIdx.z;
    const float* bias = (z == 0) ? bq : (z == 1) ? bk : bv;
    float* C          = (z == 0) ? g_Q : g_K;
    const uint32_t* BP = g_WP + (size_t)z*Ddim*Ddim;
    const int m0 = blockIdx.x * 128, n0 = blockIdx.y * 64;
    const int tid = threadIdx.x, wid = tid >> 5, lane = tid & 31;
    const int rowstrip = wid & 3, colhalf = wid >> 2;
    const int mw = rowstrip * 16;

    float acc[2][4][4] = {};

    const int srowA = tid >> 1, ssegA = tid & 1;
    const int srowB = tid >> 2, ssegB = tid & 3;
    const int arow_ld = mw + (lane & 15), acol_ld = (lane >> 4) * 8;
    const uint32_t sAb = smem_u32(sA), sBb = smem_u32(sB);

    const uint32_t* srcA0 = g_xP + (size_t)(m0 + srowA)*Ddim + ssegA*16;
    const uint32_t* srcB0 = BP + (size_t)(n0 + srowB)*Ddim + ssegB*8;
    uint32_t* dstA = (uint32_t*)(sA + srowA*CSTRIDE) + ssegA*16;
    uint32_t* dstB = (uint32_t*)(sB + srowB*CSTRIDE) + ssegB*8;

    uint4 rA[4], rB[2];
    #pragma unroll
    for (int i = 0; i < 4; i++) rA[i] = *(const uint4*)(srcA0 + 4*i);
    #pragma unroll
    for (int i = 0; i < 2; i++) rB[i] = *(const uint4*)(srcB0 + 4*i);

    for (int chunk = 0; chunk < 16; chunk++) {
        #pragma unroll
        for (int i = 0; i < 4; i++) *(uint4*)(dstA + 4*i) = rA[i];
        #pragma unroll
        for (int i = 0; i < 2; i++) *(uint4*)(dstB + 4*i) = rB[i];
        __syncthreads();
        if (chunk < 15) {
            const uint32_t* srcA = srcA0 + (chunk+1)*32;
            const uint32_t* srcB = srcB0 + (chunk+1)*32;
            #pragma unroll
            for (int i = 0; i < 4; i++) rA[i] = *(const uint4*)(srcA + 4*i);
            #pragma unroll
            for (int i = 0; i < 2; i++) rB[i] = *(const uint4*)(srcB + 4*i);
        }
        #pragma unroll
        for (int ks = 0; ks < 4; ks++) {
            const int k0 = ks * 16;
            uint32_t a0[4], a1[4];
            ldsm4(a0, sAb + arow_ld*CSTRIDE + (k0 + acol_ld)*2);
            ldsm4(a1, sAb + (arow_ld + 64)*CSTRIDE + (k0 + acol_ld)*2);
            #pragma unroll
            for (int jt2 = 0; jt2 < 2; jt2++) {
                const int jt = colhalf*2 + jt2;
                const int brow = 16*jt + (lane >> 4)*8 + (lane & 7);
                const int bcol = k0 + ((lane >> 3) & 1)*8;
                uint32_t b4[4];
                ldsm4(b4, sBb + brow*CSTRIDE + bcol*2);
                mma16816(acc[0][2*jt2],   a0, b4);
                mma16816(acc[0][2*jt2+1], a0, b4 + 2);
                mma16816(acc[1][2*jt2],   a1, b4);
                mma16816(acc[1][2*jt2+1], a1, b4 + 2);
                uint32_t bs[4];
                #pragma unroll
                for (int i = 0; i < 4; i++) bs[i] = __byte_perm(b4[i], 0, 0x1032);
                mma16816(acc[0][2*jt2],   a0, bs);
                mma16816(acc[0][2*jt2+1], a0, bs + 2);
                mma16816(acc[1][2*jt2],   a1, bs);
                mma16816(acc[1][2*jt2+1], a1, bs + 2);
            }
        }
        __syncthreads();
    }

    const int g = lane >> 2, tig = lane & 3;
    #pragma unroll
    for (int s2 = 0; s2 < 2; s2++) {
        #pragma unroll
        for (int j = 0; j < 4; j++) {
            const int c0 = colhalf*32 + 8*j + 2*tig;
            #pragma unroll
            for (int half = 0; half < 2; half++) {
                int m = m0 + 64*s2 + mw + g + 8*half;
                int b = m >> 9, t = m & (Tdim-1);
                #pragma unroll
                for (int e = 0; e < 2; e++) {
                    int n = n0 + c0 + e;
                    int h = n >> 6, c = n & (DhD-1);
                    size_t idx = (((size_t)(b*Hdim + h))*Tdim + t)*DhD + c;
                    float v = acc[s2][j][2*half + e] + bias[n];
                    if (z == 2) g_VP[idx] = pack_hilo(v);
                    else        C[idx] = v;
                }
            }
        }
    }
}

// ---------------- output GEMM via HMMA, M=128 tile, pipelined ----------------
__global__ void __launch_bounds__(256) gemm_out_mma(const float* __restrict__ bo,
                                                    float* __restrict__ out)
{
    __shared__ __align__(16) char sA[128*CSTRIDE];
    __shared__ __align__(16) char sB[64*CSTRIDE];
    const uint32_t* BP = g_WP + (size_t)3*Ddim*Ddim;
    const int m0 = blockIdx.x * 128, n0 = blockIdx.y * 64;
    const int tid = threadIdx.x, wid = tid >> 5, lane = tid & 31;
    const int rowstrip = wid & 3, colhalf = wid >> 2;
    const int mw = rowstrip * 16;

    float acc[2][4][4] = {};

    const int srowA = tid >> 1, ssegA = tid & 1;
    const int srowB = tid >> 2, ssegB = tid & 3;
    const int arow_ld = mw + (lane & 15), acol_ld = (lane >> 4) * 8;
    const uint32_t sAb = smem_u32(sA), sBb = smem_u32(sB);

    const uint32_t* srcA0 = g_oP + (size_t)(m0 + srowA)*Ddim + ssegA*16;
    const uint32_t* srcB0 = BP + (size_t)(n0 + srowB)*Ddim + ssegB*8;
    uint32_t* dstA = (uint32_t*)(sA + srowA*CSTRIDE) + ssegA*16;
    uint32_t* dstB = (uint32_t*)(sB + srowB*CSTRIDE) + ssegB*8;

    uint4 rA[4], rB[2];
    #pragma unroll
    for (int i = 0; i < 4; i++) rA[i] = *(const uint4*)(srcA0 + 4*i);
    #pragma unroll
    for (int i = 0; i < 2; i++) rB[i] = *(const uint4*)(srcB0 + 4*i);

    for (int chunk = 0; chunk < 16; chunk++) {
        #pragma unroll
        for (int i = 0; i < 4; i++) *(uint4*)(dstA + 4*i) = rA[i];
        #pragma unroll
        for (int i = 0; i < 2; i++) *(uint4*)(dstB + 4*i) = rB[i];
        __syncthreads();
        if (chunk < 15) {
            const uint32_t* srcA = srcA0 + (chunk+1)*32;
            const uint32_t* srcB = srcB0 + (chunk+1)*32;
            #pragma unroll
            for (int i = 0; i < 4; i++) rA[i] = *(const uint4*)(srcA + 4*i);
            #pragma unroll
            for (int i = 0; i < 2; i++) rB[i] = *(const uint4*)(srcB + 4*i);
        }
        #pragma unroll
        for (int ks = 0; ks < 4; ks++) {
            const int k0 = ks * 16;
            uint32_t a0[4], a1[4];
            ldsm4(a0, sAb + arow_ld*CSTRIDE + (k0 + acol_ld)*2);
            ldsm4(a1, sAb + (arow_ld + 64)*CSTRIDE + (k0 + acol_ld)*2);
            #pragma unroll
            for (int jt2 = 0; jt2 < 2; jt2++) {
                const int jt = colhalf*2 + jt2;
                const int brow = 16*jt + (lane >> 4)*8 + (lane & 7);
                const int bcol = k0 + ((lane >> 3) & 1)*8;
                uint32_t b4[4];
                ldsm4(b4, sBb + brow*CSTRIDE + bcol*2);
                mma16816(acc[0][2*jt2],   a0, b4);
                mma16816(acc[0][2*jt2+1], a0, b4 + 2);
                mma16816(acc[1][2*jt2],   a1, b4);
                mma16816(acc[1][2*jt2+1], a1, b4 + 2);
                uint32_t bs[4];
                #pragma unroll
                for (int i = 0; i < 4; i++) bs[i] = __byte_perm(b4[i], 0, 0x1032);
                mma16816(acc[0][2*jt2],   a0, bs);
                mma16816(acc[0][2*jt2+1], a0, bs + 2);
                mma16816(acc[1][2*jt2],   a1, bs);
                mma16816(acc[1][2*jt2+1], a1, bs + 2);
            }
        }
        __syncthreads();
    }

    const int g = lane >> 2, tig = lane & 3;
    #pragma unroll
    for (int s2 = 0; s2 < 2; s2++) {
        #pragma unroll
        for (int j = 0; j < 4; j++) {
            const int c0 = colhalf*32 + 8*j + 2*tig;
            const int n = n0 + c0;
            const int r0 = m0 + 64*s2 + mw + g, r1 = r0 + 8;
            *(float2*)(out + (size_t)r0*Ddim + n) =
                make_float2(acc[s2][j][0] + bo[n], acc[s2][j][1] + bo[n+1]);
            *(float2*)(out + (size_t)r1*Ddim + n) =
                make_float2(acc[s2][j][2] + bo[n], acc[s2][j][3] + bo[n+1]);
        }
    }
}

// ---------------- norm sumsq: g_sinv[side][bh][d] ----------------------------
__global__ void norm_sumsq_kernel()
{
    __shared__ float part[512];
    const int bh = blockIdx.x, isK = blockIdx.y;
    const float* src = (isK ? g_K : g_Q) + (size_t)bh*Tdim*DhD;
    const int d = threadIdx.x & 63, g = threadIdx.x >> 6;
    float s = 0.f;
    for (int t = g*64; t < (g+1)*64; t++) {
        float v = src[t*DhD + d]; s = fmaf(v, v, s);
    }
    part[threadIdx.x] = s;
    __syncthreads();
    if (threadIdx.x < 64) {
        float tot = 0.f;
        #pragma unroll
        for (int g2 = 0; g2 < 8; g2++) tot += part[d + g2*64];
        g_sinv[(isK*BH + bh)*DhD + d] = 1.0f / sqrtf(fmaxf(tot, 1e-8f));
    }
}

// ---------------- prep_q: normalize + transpose + pack -> g_QT ---------------
__global__ void prep_q_kernel()
{
    __shared__ uint32_t s[64][65];
    const int bh = blockIdx.x, t0 = blockIdx.y * 64;
    const float* src = g_Q + (size_t)bh*Tdim*DhD;
    const float* sinv = g_sinv + (size_t)bh*DhD;
    uint32_t* dst = g_QT + (size_t)bh*DhD*512;
    const int tid = threadIdx.x;
    #pragma unroll
    for (int p = tid; p < 4096; p += 256) {
        int r = p >> 6, d = p & 63;
        s[d][r] = pack_hilo(src[(t0 + r)*DhD + d] * sinv[d]);
    }
    __syncthreads();
    #pragma unroll
    for (int p = tid; p < 4096; p += 256) {
        int d = p >> 6, t = p & 63;
        dst[(size_t)d*512 + t0 + t] = s[d][t];
    }
}

// ---------------- prep_k: normalize + transpose + pack + 4 phases ------------
__global__ void prep_k_kernel()
{
    __shared__ uint32_t s[64][65];
    const int bh = blockIdx.x, t0 = blockIdx.y * 64;
    const float* src = g_K + (size_t)bh*Tdim*DhD;
    const float* sinv = g_sinv + (size_t)(BH + bh)*DhD;
    uint32_t* dst = g_Kph + (size_t)bh*4*DhD*1024;
    const int tid = threadIdx.x;
    #pragma unroll
    for (int p = tid; p < 4096; p += 256) {
        int r = p >> 6, d = p & 63;
        s[d][r] = pack_hilo(src[(t0 + r)*DhD + d] * sinv[d]);
    }
    __syncthreads();
    #pragma unroll
    for (int ph = 0; ph < 4; ph++) {
        for (int p = tid; p < 4096; p += 256) {
            int d = p >> 6, t = p & 63;
            uint32_t w = s[d][t];
            int tp = (t0 + t - ph) & (Tdim - 1);
            uint32_t* row = dst + ((size_t)ph*DhD + d)*1024;
            row[tp]       = w;
            row[tp + 512] = w;
        }
    }
}

// ---------------- cov via HMMA: 2 lag slots per block, pipelined (R13) -------
__global__ void __launch_bounds__(256) cov_mma_kernel(const float* __restrict__ lam_ptr)
{
    __shared__ __align__(16) char sA[128*CSTRIDE];  // 18 KB
    __shared__ __align__(16) char sB[64*CSTRIDE];   // 9 KB
    __shared__ float s_tot[8][2], s_dia[8][2];

    const int pair = blockIdx.x, bh = blockIdx.y;
    const int slot0 = 2*pair, slot1 = 2*pair + 1;
    const int lag0 = (slot0 >= NL) ? 0 : lag_of(slot0);
    const int lag1 = (slot1 >= NL) ? 0 : lag_of(slot1);
    const int tid = threadIdx.x, wid = tid >> 5, lane = tid & 31;
    const int rowstrip = wid & 3, colhalf = wid >> 2;
    const int mw = rowstrip * 16;

    float acc[2][4][4] = {};

    const int srowA = tid >> 1, ssegA = tid & 1;
    const int slotA = srowA >> 6, dA = srowA & 63;
    const int lagA = slotA ? lag1 : lag0;
    const int phA = (Tdim - lagA) & 3;
    const uint32_t* KTp = g_Kph + (((size_t)bh*4 + phA)*DhD + dA)*1024;
    uint32_t* dstA = (uint32_t*)(sA + srowA*CSTRIDE) + ssegA*16;

    const int srowB = tid >> 2, ssegB = tid & 3;
    const uint32_t* QTr = g_QT + ((size_t)bh*DhD + srowB)*512;
    uint32_t* dstB = (uint32_t*)(sB + srowB*CSTRIDE) + ssegB*8;

    const int arow_ld = mw + (lane & 15), acol_ld = (lane >> 4) * 8;
    const uint32_t sAb = smem_u32(sA), sBb = smem_u32(sB);

    uint4 rA[4], rB[2];
    {
        const int st = (0 - lagA + Tdim) & (Tdim - 1);
        const uint32_t* srcA = KTp + (st - phA) + ssegA*16;
        #pragma unroll
        for (int i = 0; i < 4; i++) rA[i] = *(const uint4*)(srcA + 4*i);
        const uint32_t* srcB = QTr + ssegB*8;
        #pragma unroll
        for (int i = 0; i < 2; i++) rB[i] = *(const uint4*)(srcB + 4*i);
    }

    for (int chunk = 0; chunk < 16; chunk++) {
        #pragma unroll
        for (int i = 0; i < 4; i++) *(uint4*)(dstA + 4*i) = rA[i];
        #pragma unroll
        for (int i = 0; i < 2; i++) *(uint4*)(dstB + 4*i) = rB[i];
        __syncthreads();
        if (chunk < 15) {
            const int t0n = (chunk+1) * 32;
            const int st = (t0n - lagA + Tdim) & (Tdim - 1);
            const uint32_t* srcA = KTp + (st - phA) + ssegA*16;
            #pragma unroll
            for (int i = 0; i < 4; i++) rA[i] = *(const uint4*)(srcA + 4*i);
            const uint32_t* srcB = QTr + t0n + ssegB*8;
            #pragma unroll
            for (int i = 0; i < 2; i++) rB[i] = *(const uint4*)(srcB + 4*i);
        }
        #pragma unroll
        for (int ks = 0; ks < 4; ks++) {
            const int k0 = ks * 16;
            uint32_t a0[4], a1[4];
            ldsm4(a0, sAb + arow_ld*CSTRIDE + (k0 + acol_ld)*2);
            ldsm4(a1, sAb + (arow_ld + 64)*CSTRIDE + (k0 + acol_ld)*2);
            #pragma unroll
            for (int jt2 = 0; jt2 < 2; jt2++) {
                const int jt = colhalf*2 + jt2;
                const int brow = 16*jt + (lane >> 4)*8 + (lane & 7);
                const int bcol = k0 + ((lane >> 3) & 1)*8;
                uint32_t b4[4];
                ldsm4(b4, sBb + brow*CSTRIDE + bcol*2);
                mma16816(acc[0][2*jt2],   a0, b4);
                mma16816(acc[0][2*jt2+1], a0, b4 + 2);
                mma16816(acc[1][2*jt2],   a1, b4);
                mma16816(acc[1][2*jt2+1], a1, b4 + 2);
                uint32_t bs[4];
                #pragma unroll
                for (int i = 0; i < 4; i++) bs[i] = __byte_perm(b4[i], 0, 0x1032);
                mma16816(acc[0][2*jt2],   a0, bs);
                mma16816(acc[0][2*jt2+1], a0, bs + 2);
                mma16816(acc[1][2*jt2],   a1, bs);
                mma16816(acc[1][2*jt2+1], a1, bs + 2);
            }
        }
        __syncthreads();
    }

    const int g = lane >> 2, tig = lane & 3;
    const int r0 = mw + g, r1 = mw + g + 8;
    #pragma unroll
    for (int s2 = 0; s2 < 2; s2++) {
        const int slot = 2*pair + s2;
        float tot = 0.f, dia = 0.f;
        if (slot <= NL) {
            float* covp = g_cov + ((size_t)bh*(NL+1) + slot)*(DhD*DhD);
            #pragma unroll
            for (int j = 0; j < 4; j++) {
                const int c0 = colhalf*32 + 8*j + 2*tig;
                *(float2*)(covp + r0*DhD + c0) = make_float2(acc[s2][j][0], acc[s2][j][1]);
                *(float2*)(covp + r1*DhD + c0) = make_float2(acc[s2][j][2], acc[s2][j][3]);
                tot += fabsf(acc[s2][j][0]) + fabsf(acc[s2][j][1])
                     + fabsf(acc[s2][j][2]) + fabsf(acc[s2][j][3]);
                if (r0 == c0)     dia += fabsf(acc[s2][j][0]);
                if (r0 == c0 + 1) dia += fabsf(acc[s2][j][1]);
                if (r1 == c0)     dia += fabsf(acc[s2][j][2]);
                if (r1 == c0 + 1) dia += fabsf(acc[s2][j][3]);
            }
        }
        #pragma unroll
        for (int o = 16; o > 0; o >>= 1) {
            tot += __shfl_xor_sync(0xffffffffu, tot, o);
            dia += __shfl_xor_sync(0xffffffffu, dia, o);
        }
        if (lane == 0) { s_tot[wid][s2] = tot; s_dia[wid][s2] = dia; }
    }
    __syncthreads();
    if (tid < 2) {
        const int slot = 2*pair + tid;
        if (slot < NL) {
            float T = 0.f, D = 0.f;
            #pragma unroll
            for (int w = 0; w < 8; w++) { T += s_tot[w][tid]; D += s_dia[w][tid]; }
            float lam = fminf(fmaxf(*lam_ptr, 0.f), 1.f);
            g_score[bh*NL + slot] = lam*D + (1.f - lam)*(T - D);
        }
    }
}

// ---------------- top-18 lag selection: one warp per bh, shuffle argmax ------
__global__ void topk_kernel(const float* __restrict__ lt_lag,
                            const float* __restrict__ beta_ptr)
{
    const int bh = blockIdx.x, l = threadIdx.x; // 32 threads
    float v0 = g_score[bh*NL + l];
    float v1 = g_score[bh*NL + l + 32];
    float selV[KTOP]; int selI[KTOP];
    #pragma unroll
    for (int k = 0; k < KTOP; k++) {
        float bv; int bi;
        if (v0 >= v1) { bv = v0; bi = l; } else { bv = v1; bi = l + 32; }
        #pragma unroll
        for (int o = 16; o > 0; o >>= 1) {
            float ov = __shfl_xor_sync(0xffffffffu, bv, o);
            int   oi = __shfl_xor_sync(0xffffffffu, bi, o);
            if (ov > bv || (ov == bv && oi < bi)) { bv = ov; bi = oi; }
        }
        selV[k] = bv; selI[k] = bi;
        if (bi == l)      v0 = -3.4e38f;
        if (bi == l + 32) v1 = -3.4e38f;
    }
    if (l == 0) {
        float tl = fmaxf(expf(*lt_lag), 1e-4f);
        float mx = selV[0];
        float e[KTOP], esum = 0.f;
        #pragma unroll
        for (int k = 0; k < KTOP; k++) { e[k] = expf((selV[k] - mx)/tl); esum += e[k]; }
        float beta = fminf(fmaxf(*beta_ptr, 0.f), 1.f);
        g_shift[bh*NSLOT]  = 0;
        g_wslot[bh*NSLOT]  = 1.f - beta;
        g_covsel[bh*NSLOT] = NL;
        #pragma unroll
        for (int k = 0; k < KTOP; k++) {
            g_shift[bh*NSLOT + 1 + k]  = lag_of(selI[k]);
            g_wslot[bh*NSLOT + 1 + k]  = beta * e[k] / esum;
            g_covsel[bh*NSLOT + 1 + k] = selI[k];
        }
    }
}

// ---------------- attwT[s][c][d] = pack(weight_s * softmax_c(cov/tau)) -------
__global__ void att_kernel(const float* __restrict__ log_tau_ptr)
{
    __shared__ uint32_t sT[64][65];
    const int s = blockIdx.x, bh = blockIdx.y;
    const int l = g_covsel[bh*NSLOT + s];
    const float w = g_wslot[bh*NSLOT + s];
    const float invtau = 1.0f / fmaxf(expf(*log_tau_ptr), 1e-4f);
    const float* covp = g_cov + ((size_t)bh*(NL+1) + l)*(DhD*DhD);
    uint32_t* outp = g_attwT + ((size_t)bh*NSLOT + s)*(DhD*DhD);
    const int tid = threadIdx.x;
    int warp = tid >> 5, lane = tid & 31;
    for (int d = warp; d < DhD; d += 8) {
        float v0 = covp[d*DhD + lane]      * invtau;
        float v1 = covp[d*DhD + lane + 32] * invtau;
        float m = fmaxf(v0, v1);
        #pragma unroll
        for (int o = 16; o > 0; o >>= 1) m = fmaxf(m, __shfl_xor_sync(0xffffffffu, m, o));
        float e0 = expf(v0 - m), e1 = expf(v1 - m);
        float ss = e0 + e1;
        #pragma unroll
        for (int o = 16; o > 0; o >>= 1) ss += __shfl_xor_sync(0xffffffffu, ss, o);
        float f = w / ss;
        sT[lane][d]      = pack_hilo(e0 * f);
        sT[lane + 32][d] = pack_hilo(e1 * f);
    }
    __syncthreads();
    #pragma unroll
    for (int p = tid; p < 4096; p += 256) {
        outp[p] = sT[p >> 6][p & 63];
    }
}

// ---------------- contrib via HMMA, M=128 t-tile, pipelined ------------------
// out_h[t,c] = sum_s V[(t-shift_s)%T] @ attw_s; 19 slots x 2 k-halves.
__global__ void __launch_bounds__(256) contrib_mma_kernel()
{
    __shared__ __align__(16) char sA[128*CSTRIDE];
    __shared__ __align__(16) char sB[64*CSTRIDE];
    const int bh = blockIdx.y, t0 = blockIdx.x * 128;
    const int bb = bh >> 3, hh = bh & 7;
    const int tid = threadIdx.x, wid = tid >> 5, lane = tid & 31;
    const int rowstrip = wid & 3, colhalf = wid >> 2;
    const int mw = rowstrip * 16;

    float acc[2][4][4] = {};

    const int srowA = tid >> 1, ssegA = tid & 1;
    const int srowB = tid >> 2, ssegB = tid & 3;
    const int arow_ld = mw + (lane & 15), acol_ld = (lane >> 4) * 8;
    const uint32_t sAb = smem_u32(sA), sBb = smem_u32(sB);

    const uint32_t* VPb = g_VP + (size_t)bh*Tdim*DhD;
    uint32_t* dstA = (uint32_t*)(sA + srowA*CSTRIDE) + ssegA*16;
    uint32_t* dstB = (uint32_t*)(sB + srowB*CSTRIDE) + ssegB*8;

    // iteration idx = s*2 + kh over 19 slots x 2 k-halves
    uint4 rA[4], rB[2];
    {
        const int shift = g_shift[bh*NSLOT];
        const uint32_t* ap = g_attwT + (size_t)bh*NSLOT*(DhD*DhD);
        const int srcT = (t0 + srowA - shift + Tdim) & (Tdim - 1);
        const uint32_t* srcA = VPb + (size_t)srcT*DhD + ssegA*16;
        const uint32_t* srcB = ap + srowB*DhD + ssegB*8;
        #pragma unroll
        for (int i = 0; i < 4; i++) rA[i] = *(const uint4*)(srcA + 4*i);
        #pragma unroll
        for (int i = 0; i < 2; i++) rB[i] = *(const uint4*)(srcB + 4*i);
    }

    for (int it = 0; it < NSLOT*2; it++) {
        #pragma unroll
        for (int i = 0; i < 4; i++) *(uint4*)(dstA + 4*i) = rA[i];
        #pragma unroll
        for (int i = 0; i < 2; i++) *(uint4*)(dstB + 4*i) = rB[i];
        __syncthreads();
        if (it < NSLOT*2 - 1) {
            const int nit = it + 1;
            const int s = nit >> 1, kh = nit & 1;
            const int shift = g_shift[bh*NSLOT + s];
            const uint32_t* ap = g_attwT + ((size_t)bh*NSLOT + s)*(DhD*DhD);
            const int srcT = (t0 + srowA - shift + Tdim) & (Tdim - 1);
            const uint32_t* srcA = VPb + (size_t)srcT*DhD + kh*32 + ssegA*16;
            const uint32_t* srcB = ap + srowB*DhD + kh*32 + ssegB*8;
            #pragma unroll
            for (int i = 0; i < 4; i++) rA[i] = *(const uint4*)(srcA + 4*i);
            #pragma unroll
            for (int i = 0; i < 2; i++) rB[i] = *(const uint4*)(srcB + 4*i);
        }
        #pragma unroll
        for (int ks = 0; ks < 4; ks++) {
            const int k0 = ks * 16;
            uint32_t a0[4], a1[4];
            ldsm4(a0, sAb + arow_ld*CSTRIDE + (k0 + acol_ld)*2);
            ldsm4(a1, sAb + (arow_ld + 64)*CSTRIDE + (k0 + acol_ld)*2);
            #pragma unroll
            for (int jt2 = 0; jt2 < 2; jt2++) {
                const int jt = colhalf*2 + jt2;
                const int brow = 16*jt + (lane >> 4)*8 + (lane & 7);
                const int bcol = k0 + ((lane >> 3) & 1)*8;
                uint32_t b4[4];
                ldsm4(b4, sBb + brow*CSTRIDE + bcol*2);
                mma16816(acc[0][2*jt2],   a0, b4);
                mma16816(acc[0][2*jt2+1], a0, b4 + 2);
                mma16816(acc[1][2*jt2],   a1, b4);
                mma16816(acc[1][2*jt2+1], a1, b4 + 2);
                uint32_t bs[4];
                #pragma unroll
                for (int i = 0; i < 4; i++) bs[i] = __byte_perm(b4[i], 0, 0x1032);
                mma16816(acc[0][2*jt2],   a0, bs);
                mma16816(acc[0][2*jt2+1], a0, bs + 2);
                mma16816(acc[1][2*jt2],   a1, bs);
                mma16816(acc[1][2*jt2+1], a1, bs + 2);
            }
        }
        __syncthreads();
    }

    const int g = lane >> 2, tig = lane & 3;
    #pragma unroll
    for (int s2 = 0; s2 < 2; s2++) {
        #pragma unroll
        for (int j = 0; j < 4; j++) {
            const int c0 = colhalf*32 + 8*j + 2*tig;
            #pragma unroll
            for (int half = 0; half < 2; half++) {
                int t = t0 + 64*s2 + mw + g + 8*half;
                size_t row = ((size_t)(bb*Tdim + t))*Ddim + hh*DhD;
                g_oP[row + c0]     = pack_hilo(acc[s2][j][2*half + 0]);
                g_oP[row + c0 + 1] = pack_hilo(acc[s2][j][2*half + 1]);
            }
        }
    }
}

// ---------------- launch ------------------------------------------------------
extern "C" void kernel_launch(void* const* d_in, const int* in_sizes, int n_in,
                              void* d_out, int out_size)
{
    const float* x           = (const float*)d_in[0];
    const float* Wq          = (const float*)d_in[1];
    const float* bq          = (const float*)d_in[2];
    const float* Wk          = (const float*)d_in[3];
    const float* bk          = (const float*)d_in[4];
    const float* Wv          = (const float*)d_in[5];
    const float* bv          = (const float*)d_in[6];
    const float* Wo          = (const float*)d_in[7];
    const float* bo          = (const float*)d_in[8];
    const float* log_tau     = (const float*)d_in[9];
    const float* lambda_auto = (const float*)d_in[10];
    const float* beta_lag    = (const float*)d_in[11];
    const float* log_tau_lag = (const float*)d_in[12];
    float* out = (float*)d_out;

    prep_x_kernel<<<Bdim*Tdim*Ddim/1024, 256>>>(x);
    prep_w_kernel<<<dim3(8, 8, 4), 256>>>(Wq, Wk, Wv, Wo);
    gemm_qkv_mma<<<dim3(Bdim*Tdim/128, Ddim/64, 3), 256>>>(bq, bk, bv);
    norm_sumsq_kernel<<<dim3(BH, 2), 512>>>();
    prep_q_kernel<<<dim3(BH, 8), 256>>>();
    prep_k_kernel<<<dim3(BH, 8), 256>>>();
    cov_mma_kernel<<<dim3(33, BH), 256>>>(lambda_auto);
    topk_kernel<<<BH, 32>>>(log_tau_lag, beta_lag);
    att_kernel<<<dim3(NSLOT, BH), 256>>>(log_tau);
    contrib_mma_kernel<<<dim3(Tdim/128, BH), 256>>>();
    gemm_out_mma<<<dim3(Bdim*Tdim/128, Ddim/64), 256>>>(bo, out);
}

// round 15
// speedup vs baseline: 2.8044x; 1.0148x over previous
#include <cuda_runtime.h>
#include <cuda_bf16.h>
#include <math.h>
#include <stdint.h>

// Problem constants (fixed shapes from the reference)
#define Bdim 4
#define Hdim 8
#define Tdim 512
#define Ddim 512
#define DhD  64
#define NL   64     // number of lag candidates
#define KTOP 18     // top-k lags = 2*ceil(log2(512)) = 18
#define NSLOT 19    // 1 (lag 0 / instantaneous) + KTOP
#define BH   (Bdim*Hdim)

// lags for T=512, LMAX=64: step=7 -> 1,8,...,442 then last forced to 511
__device__ __forceinline__ int lag_of(int l) { return (l == NL-1) ? (Tdim-1) : (1 + 7*l); }

// ---------------- mma.sync helpers ------------------------------------------
__device__ __forceinline__ uint32_t smem_u32(const void* p) {
    uint32_t a;
    asm("{ .reg .u64 t; cvta.to.shared.u64 t, %1; cvt.u32.u64 %0, t; }" : "=r"(a) : "l"(p));
    return a;
}
__device__ __forceinline__ void ldsm4(uint32_t r[4], uint32_t addr) {
    asm volatile("ldmatrix.sync.aligned.m8n8.x4.shared.b16 {%0,%1,%2,%3}, [%4];"
        : "=r"(r[0]), "=r"(r[1]), "=r"(r[2]), "=r"(r[3]) : "r"(addr));
}
__device__ __forceinline__ void mma16816(float d[4], const uint32_t a[4], const uint32_t b[2]) {
    asm volatile("mma.sync.aligned.m16n8k16.row.col.f32.bf16.bf16.f32 "
        "{%0,%1,%2,%3},{%4,%5,%6,%7},{%8,%9},{%0,%1,%2,%3};"
        : "+f"(d[0]), "+f"(d[1]), "+f"(d[2]), "+f"(d[3])
        : "r"(a[0]), "r"(a[1]), "r"(a[2]), "r"(a[3]), "r"(b[0]), "r"(b[1]));
}

// ---------------- pack helper: fp32 -> (hi bf16, lo bf16) u32 ----------------
__device__ __forceinline__ uint32_t pack_hilo(float v) {
    __nv_bfloat16 h = __float2bfloat16(v);
    float hf = __bfloat162float(h);
    __nv_bfloat16 l = __float2bfloat16(v - hf);
    return (uint32_t)(*(unsigned short*)&h) | ((uint32_t)(*(unsigned short*)&l) << 16);
}

// ---------------- scratch (static device memory; no runtime allocation) ----
__device__ float g_Q[BH*Tdim*DhD];                 // 4 MB, raw (pre-norm)
__device__ float g_K[BH*Tdim*DhD];                 // 4 MB, raw (pre-norm)
__device__ uint32_t g_VP[BH*Tdim*DhD];             // 4 MB: V packed (hi,lo), head-major
__device__ uint32_t g_xP[Bdim*Tdim*Ddim];          // 4 MB: x packed (hi,lo), row-major
__device__ uint32_t g_WP[4*Ddim*Ddim];             // 4 MB: W^T packed, z = q,k,v,o
__device__ uint32_t g_oP[Bdim*Tdim*Ddim];          // 4 MB: out_h packed (from contrib)
__device__ uint32_t g_Kph[(size_t)BH*4*DhD*1024];  // 33.5 MB: 4 pre-shift phases, doubled
__device__ uint32_t g_QT[(size_t)BH*DhD*512];      // 4.2 MB: [bh][c][t], (hi,lo) packed
__device__ float g_cov[(size_t)BH*(NL+1)*DhD*DhD]; // 34 MB (slot NL = lag 0)
__device__ float g_score[BH*NL];
__device__ int   g_shift[BH*NSLOT];
__device__ float g_wslot[BH*NSLOT];
__device__ int   g_covsel[BH*NSLOT];
__device__ uint32_t g_attwT[(size_t)BH*NSLOT*DhD*DhD]; // 10 MB: [c][d] packed

// ---------------- prep_xw: pack x (z=4) / transpose+pack weights (z=0..3) ----
__global__ void prep_xw_kernel(const float* __restrict__ x,
                               const float* __restrict__ Wq, const float* __restrict__ Wk,
                               const float* __restrict__ Wv, const float* __restrict__ Wo)
{
    const int z = blockIdx.z;
    const int tid = threadIdx.x;
    if (z < 4) {
        __shared__ uint32_t s[64][65];
        const float* W = (z == 0) ? Wq : (z == 1) ? Wk : (z == 2) ? Wv : Wo;
        uint32_t* dst = g_WP + (size_t)z*Ddim*Ddim;
        const int k0 = blockIdx.x * 64, n0 = blockIdx.y * 64;
        #pragma unroll
        for (int p = tid; p < 4096; p += 256) {
            int r = p >> 6, c = p & 63;   // r: k idx, c: n idx
            s[c][r] = pack_hilo(W[(size_t)(k0 + r)*Ddim + n0 + c]);
        }
        __syncthreads();
        #pragma unroll
        for (int p = tid; p < 4096; p += 256) {
            int n = p >> 6, k = p & 63;
            dst[(size_t)(n0 + n)*Ddim + k0 + k] = s[n][k];
        }
    } else {
        // x: 1M elems over 64 blocks (bx,by) of 16384 each
        int base = (blockIdx.y*8 + blockIdx.x)*16384 + tid*4;
        #pragma unroll
        for (int i = 0; i < 16; i++) {
            int idx = base + i*1024;
            float4 v = *(const float4*)(x + idx);
            uint4 o;
            o.x = pack_hilo(v.x); o.y = pack_hilo(v.y);
            o.z = pack_hilo(v.z); o.w = pack_hilo(v.w);
            *(uint4*)(g_xP + idx) = o;
        }
    }
}

// ---------------- QKV GEMM via HMMA, M=128 tile, pipelined -------------------
// C = x @ W + bias, scattered head-major; z selects Q/K/V. V written packed.
#define CSTRIDE 144
__global__ void __launch_bounds__(256) gemm_qkv_mma(const float* __restrict__ bq,
                                                    const float* __restrict__ bk,
                                                    const float* __restrict__ bv)
{
    __shared__ __align__(16) char sA[128*CSTRIDE];  // 18 KB
    __shared__ __align__(16) char sB[64*CSTRIDE];   // 9 KB
    const int z = blockIdx.z;
    const float* bias = (z == 0) ? bq : (z == 1) ? bk : bv;
    float* C          = (z == 0) ? g_Q : g_K;
    const uint32_t* BP = g_WP + (size_t)z*Ddim*Ddim;
    const int m0 = blockIdx.x * 128, n0 = blockIdx.y * 64;
    const int tid = threadIdx.x, wid = tid >> 5, lane = tid & 31;
    const int rowstrip = wid & 3, colhalf = wid >> 2;
    const int mw = rowstrip * 16;

    float acc[2][4][4] = {};

    const int srowA = tid >> 1, ssegA = tid & 1;
    const int srowB = tid >> 2, ssegB = tid & 3;
    const int arow_ld = mw + (lane & 15), acol_ld = (lane >> 4) * 8;
    const uint32_t sAb = smem_u32(sA), sBb = smem_u32(sB);

    const uint32_t* srcA0 = g_xP + (size_t)(m0 + srowA)*Ddim + ssegA*16;
    const uint32_t* srcB0 = BP + (size_t)(n0 + srowB)*Ddim + ssegB*8;
    uint32_t* dstA = (uint32_t*)(sA + srowA*CSTRIDE) + ssegA*16;
    uint32_t* dstB = (uint32_t*)(sB + srowB*CSTRIDE) + ssegB*8;

    uint4 rA[4], rB[2];
    #pragma unroll
    for (int i = 0; i < 4; i++) rA[i] = *(const uint4*)(srcA0 + 4*i);
    #pragma unroll
    for (int i = 0; i < 2; i++) rB[i] = *(const uint4*)(srcB0 + 4*i);

    for (int chunk = 0; chunk < 16; chunk++) {
        #pragma unroll
        for (int i = 0; i < 4; i++) *(uint4*)(dstA + 4*i) = rA[i];
        #pragma unroll
        for (int i = 0; i < 2; i++) *(uint4*)(dstB + 4*i) = rB[i];
        __syncthreads();
        if (chunk < 15) {
            const uint32_t* srcA = srcA0 + (chunk+1)*32;
            const uint32_t* srcB = srcB0 + (chunk+1)*32;
            #pragma unroll
            for (int i = 0; i < 4; i++) rA[i] = *(const uint4*)(srcA + 4*i);
            #pragma unroll
            for (int i = 0; i < 2; i++) rB[i] = *(const uint4*)(srcB + 4*i);
        }
        #pragma unroll
        for (int ks = 0; ks < 4; ks++) {
            const int k0 = ks * 16;
            uint32_t a0[4], a1[4];
            ldsm4(a0, sAb + arow_ld*CSTRIDE + (k0 + acol_ld)*2);
            ldsm4(a1, sAb + (arow_ld + 64)*CSTRIDE + (k0 + acol_ld)*2);
            #pragma unroll
            for (int jt2 = 0; jt2 < 2; jt2++) {
                const int jt = colhalf*2 + jt2;
                const int brow = 16*jt + (lane >> 4)*8 + (lane & 7);
                const int bcol = k0 + ((lane >> 3) & 1)*8;
                uint32_t b4[4];
                ldsm4(b4, sBb + brow*CSTRIDE + bcol*2);
                mma16816(acc[0][2*jt2],   a0, b4);
                mma16816(acc[0][2*jt2+1], a0, b4 + 2);
                mma16816(acc[1][2*jt2],   a1, b4);
                mma16816(acc[1][2*jt2+1], a1, b4 + 2);
                uint32_t bs[4];
                #pragma unroll
                for (int i = 0; i < 4; i++) bs[i] = __byte_perm(b4[i], 0, 0x1032);
                mma16816(acc[0][2*jt2],   a0, bs);
                mma16816(acc[0][2*jt2+1], a0, bs + 2);
                mma16816(acc[1][2*jt2],   a1, bs);
                mma16816(acc[1][2*jt2+1], a1, bs + 2);
            }
        }
        __syncthreads();
    }

    const int g = lane >> 2, tig = lane & 3;
    #pragma unroll
    for (int s2 = 0; s2 < 2; s2++) {
        #pragma unroll
        for (int j = 0; j < 4; j++) {
            const int c0 = colhalf*32 + 8*j + 2*tig;
            #pragma unroll
            for (int half = 0; half < 2; half++) {
                int m = m0 + 64*s2 + mw + g + 8*half;
                int b = m >> 9, t = m & (Tdim-1);
                #pragma unroll
                for (int e = 0; e < 2; e++) {
                    int n = n0 + c0 + e;
                    int h = n >> 6, c = n & (DhD-1);
                    size_t idx = (((size_t)(b*Hdim + h))*Tdim + t)*DhD + c;
                    float v = acc[s2][j][2*half + e] + bias[n];
                    if (z == 2) g_VP[idx] = pack_hilo(v);
                    else        C[idx] = v;
                }
            }
        }
    }
}

// ---------------- output GEMM via HMMA, M=128 tile, pipelined ----------------
__global__ void __launch_bounds__(256) gemm_out_mma(const float* __restrict__ bo,
                                                    float* __restrict__ out)
{
    __shared__ __align__(16) char sA[128*CSTRIDE];
    __shared__ __align__(16) char sB[64*CSTRIDE];
    const uint32_t* BP = g_WP + (size_t)3*Ddim*Ddim;
    const int m0 = blockIdx.x * 128, n0 = blockIdx.y * 64;
    const int tid = threadIdx.x, wid = tid >> 5, lane = tid & 31;
    const int rowstrip = wid & 3, colhalf = wid >> 2;
    const int mw = rowstrip * 16;

    float acc[2][4][4] = {};

    const int srowA = tid >> 1, ssegA = tid & 1;
    const int srowB = tid >> 2, ssegB = tid & 3;
    const int arow_ld = mw + (lane & 15), acol_ld = (lane >> 4) * 8;
    const uint32_t sAb = smem_u32(sA), sBb = smem_u32(sB);

    const uint32_t* srcA0 = g_oP + (size_t)(m0 + srowA)*Ddim + ssegA*16;
    const uint32_t* srcB0 = BP + (size_t)(n0 + srowB)*Ddim + ssegB*8;
    uint32_t* dstA = (uint32_t*)(sA + srowA*CSTRIDE) + ssegA*16;
    uint32_t* dstB = (uint32_t*)(sB + srowB*CSTRIDE) + ssegB*8;

    uint4 rA[4], rB[2];
    #pragma unroll
    for (int i = 0; i < 4; i++) rA[i] = *(const uint4*)(srcA0 + 4*i);
    #pragma unroll
    for (int i = 0; i < 2; i++) rB[i] = *(const uint4*)(srcB0 + 4*i);

    for (int chunk = 0; chunk < 16; chunk++) {
        #pragma unroll
        for (int i = 0; i < 4; i++) *(uint4*)(dstA + 4*i) = rA[i];
        #pragma unroll
        for (int i = 0; i < 2; i++) *(uint4*)(dstB + 4*i) = rB[i];
        __syncthreads();
        if (chunk < 15) {
            const uint32_t* srcA = srcA0 + (chunk+1)*32;
            const uint32_t* srcB = srcB0 + (chunk+1)*32;
            #pragma unroll
            for (int i = 0; i < 4; i++) rA[i] = *(const uint4*)(srcA + 4*i);
            #pragma unroll
            for (int i = 0; i < 2; i++) rB[i] = *(const uint4*)(srcB + 4*i);
        }
        #pragma unroll
        for (int ks = 0; ks < 4; ks++) {
            const int k0 = ks * 16;
            uint32_t a0[4], a1[4];
            ldsm4(a0, sAb + arow_ld*CSTRIDE + (k0 + acol_ld)*2);
            ldsm4(a1, sAb + (arow_ld + 64)*CSTRIDE + (k0 + acol_ld)*2);
            #pragma unroll
            for (int jt2 = 0; jt2 < 2; jt2++) {
                const int jt = colhalf*2 + jt2;
                const int brow = 16*jt + (lane >> 4)*8 + (lane & 7);
                const int bcol = k0 + ((lane >> 3) & 1)*8;
                uint32_t b4[4];
                ldsm4(b4, sBb + brow*CSTRIDE + bcol*2);
                mma16816(acc[0][2*jt2],   a0, b4);
                mma16816(acc[0][2*jt2+1], a0, b4 + 2);
                mma16816(acc[1][2*jt2],   a1, b4);
                mma16816(acc[1][2*jt2+1], a1, b4 + 2);
                uint32_t bs[4];
                #pragma unroll
                for (int i = 0; i < 4; i++) bs[i] = __byte_perm(b4[i], 0, 0x1032);
                mma16816(acc[0][2*jt2],   a0, bs);
                mma16816(acc[0][2*jt2+1], a0, bs + 2);
                mma16816(acc[1][2*jt2],   a1, bs);
                mma16816(acc[1][2*jt2+1], a1, bs + 2);
            }
        }
        __syncthreads();
    }

    const int g = lane >> 2, tig = lane & 3;
    #pragma unroll
    for (int s2 = 0; s2 < 2; s2++) {
        #pragma unroll
        for (int j = 0; j < 4; j++) {
            const int c0 = colhalf*32 + 8*j + 2*tig;
            const int n = n0 + c0;
            const int r0 = m0 + 64*s2 + mw + g, r1 = r0 + 8;
            *(float2*)(out + (size_t)r0*Ddim + n) =
                make_float2(acc[s2][j][0] + bo[n], acc[s2][j][1] + bo[n+1]);
            *(float2*)(out + (size_t)r1*Ddim + n) =
                make_float2(acc[s2][j][2] + bo[n], acc[s2][j][3] + bo[n+1]);
        }
    }
}

// ---------------- prep_qk: fused sumsq + normalize + transpose + pack --------
// grid (BH, 8, 2). z=0: Q -> g_QT.  z=1: K -> g_Kph (4 phases, doubled).
// Each block recomputes its plane's sumsq (L2-resident redundant read).
__global__ void prep_qk_kernel()
{
    __shared__ float part[256];
    __shared__ float sinv[DhD];
    __shared__ uint32_t s[64][65];
    const int bh = blockIdx.x, t0 = blockIdx.y * 64, isK = blockIdx.z;
    const float* src = (isK ? g_K : g_Q) + (size_t)bh*Tdim*DhD;
    const int tid = threadIdx.x;
    const int d = tid & 63, g = tid >> 6;
    float ss = 0.f;
    for (int t = g*128; t < (g+1)*128; t++) {
        float v = src[t*DhD + d]; ss = fmaf(v, v, ss);
    }
    part[tid] = ss;
    __syncthreads();
    if (tid < 64) {
        float tot = part[d] + part[d+64] + part[d+128] + part[d+192];
        sinv[d] = 1.0f / sqrtf(fmaxf(tot, 1e-8f));
    }
    __syncthreads();
    #pragma unroll
    for (int p = tid; p < 4096; p += 256) {
        int r = p >> 6, dd = p & 63;
        s[dd][r] = pack_hilo(src[(t0 + r)*DhD + dd] * sinv[dd]);
    }
    __syncthreads();
    if (!isK) {
        uint32_t* dst = g_QT + (size_t)bh*DhD*512;
        #pragma unroll
        for (int p = tid; p < 4096; p += 256) {
            int dd = p >> 6, t = p & 63;
            dst[(size_t)dd*512 + t0 + t] = s[dd][t];
        }
    } else {
        uint32_t* dst = g_Kph + (size_t)bh*4*DhD*1024;
        #pragma unroll
        for (int ph = 0; ph < 4; ph++) {
            for (int p = tid; p < 4096; p += 256) {
                int dd = p >> 6, t = p & 63;
                uint32_t w = s[dd][t];
                int tp = (t0 + t - ph) & (Tdim - 1);
                uint32_t* row = dst + ((size_t)ph*DhD + dd)*1024;
                row[tp]       = w;
                row[tp + 512] = w;
            }
        }
    }
}

// ---------------- cov via HMMA: 2 lag slots per block, pipelined -------------
__global__ void __launch_bounds__(256) cov_mma_kernel(const float* __restrict__ lam_ptr)
{
    __shared__ __align__(16) char sA[128*CSTRIDE];  // 18 KB
    __shared__ __align__(16) char sB[64*CSTRIDE];   // 9 KB
    __shared__ float s_tot[8][2], s_dia[8][2];

    const int pair = blockIdx.x, bh = blockIdx.y;
    const int slot0 = 2*pair, slot1 = 2*pair + 1;
    const int lag0 = (slot0 >= NL) ? 0 : lag_of(slot0);
    const int lag1 = (slot1 >= NL) ? 0 : lag_of(slot1);
    const int tid = threadIdx.x, wid = tid >> 5, lane = tid & 31;
    const int rowstrip = wid & 3, colhalf = wid >> 2;
    const int mw = rowstrip * 16;

    float acc[2][4][4] = {};

    const int srowA = tid >> 1, ssegA = tid & 1;
    const int slotA = srowA >> 6, dA = srowA & 63;
    const int lagA = slotA ? lag1 : lag0;
    const int phA = (Tdim - lagA) & 3;
    const uint32_t* KTp = g_Kph + (((size_t)bh*4 + phA)*DhD + dA)*1024;
    uint32_t* dstA = (uint32_t*)(sA + srowA*CSTRIDE) + ssegA*16;

    const int srowB = tid >> 2, ssegB = tid & 3;
    const uint32_t* QTr = g_QT + ((size_t)bh*DhD + srowB)*512;
    uint32_t* dstB = (uint32_t*)(sB + srowB*CSTRIDE) + ssegB*8;

    const int arow_ld = mw + (lane & 15), acol_ld = (lane >> 4) * 8;
    const uint32_t sAb = smem_u32(sA), sBb = smem_u32(sB);

    uint4 rA[4], rB[2];
    {
        const int st = (0 - lagA + Tdim) & (Tdim - 1);
        const uint32_t* srcA = KTp + (st - phA) + ssegA*16;
        #pragma unroll
        for (int i = 0; i < 4; i++) rA[i] = *(const uint4*)(srcA + 4*i);
        const uint32_t* srcB = QTr + ssegB*8;
        #pragma unroll
        for (int i = 0; i < 2; i++) rB[i] = *(const uint4*)(srcB + 4*i);
    }

    for (int chunk = 0; chunk < 16; chunk++) {
        #pragma unroll
        for (int i = 0; i < 4; i++) *(uint4*)(dstA + 4*i) = rA[i];
        #pragma unroll
        for (int i = 0; i < 2; i++) *(uint4*)(dstB + 4*i) = rB[i];
        __syncthreads();
        if (chunk < 15) {
            const int t0n = (chunk+1) * 32;
            const int st = (t0n - lagA + Tdim) & (Tdim - 1);
            const uint32_t* srcA = KTp + (st - phA) + ssegA*16;
            #pragma unroll
            for (int i = 0; i < 4; i++) rA[i] = *(const uint4*)(srcA + 4*i);
            const uint32_t* srcB = QTr + t0n + ssegB*8;
            #pragma unroll
            for (int i = 0; i < 2; i++) rB[i] = *(const uint4*)(srcB + 4*i);
        }
        #pragma unroll
        for (int ks = 0; ks < 4; ks++) {
            const int k0 = ks * 16;
            uint32_t a0[4], a1[4];
            ldsm4(a0, sAb + arow_ld*CSTRIDE + (k0 + acol_ld)*2);
            ldsm4(a1, sAb + (arow_ld + 64)*CSTRIDE + (k0 + acol_ld)*2);
            #pragma unroll
            for (int jt2 = 0; jt2 < 2; jt2++) {
                const int jt = colhalf*2 + jt2;
                const int brow = 16*jt + (lane >> 4)*8 + (lane & 7);
                const int bcol = k0 + ((lane >> 3) & 1)*8;
                uint32_t b4[4];
                ldsm4(b4, sBb + brow*CSTRIDE + bcol*2);
                mma16816(acc[0][2*jt2],   a0, b4);
                mma16816(acc[0][2*jt2+1], a0, b4 + 2);
                mma16816(acc[1][2*jt2],   a1, b4);
                mma16816(acc[1][2*jt2+1], a1, b4 + 2);
                uint32_t bs[4];
                #pragma unroll
                for (int i = 0; i < 4; i++) bs[i] = __byte_perm(b4[i], 0, 0x1032);
                mma16816(acc[0][2*jt2],   a0, bs);
                mma16816(acc[0][2*jt2+1], a0, bs + 2);
                mma16816(acc[1][2*jt2],   a1, bs);
                mma16816(acc[1][2*jt2+1], a1, bs + 2);
            }
        }
        __syncthreads();
    }

    const int g = lane >> 2, tig = lane & 3;
    const int r0 = mw + g, r1 = mw + g + 8;
    #pragma unroll
    for (int s2 = 0; s2 < 2; s2++) {
        const int slot = 2*pair + s2;
        float tot = 0.f, dia = 0.f;
        if (slot <= NL) {
            float* covp = g_cov + ((size_t)bh*(NL+1) + slot)*(DhD*DhD);
            #pragma unroll
            for (int j = 0; j < 4; j++) {
                const int c0 = colhalf*32 + 8*j + 2*tig;
                *(float2*)(covp + r0*DhD + c0) = make_float2(acc[s2][j][0], acc[s2][j][1]);
                *(float2*)(covp + r1*DhD + c0) = make_float2(acc[s2][j][2], acc[s2][j][3]);
                tot += fabsf(acc[s2][j][0]) + fabsf(acc[s2][j][1])
                     + fabsf(acc[s2][j][2]) + fabsf(acc[s2][j][3]);
                if (r0 == c0)     dia += fabsf(acc[s2][j][0]);
                if (r0 == c0 + 1) dia += fabsf(acc[s2][j][1]);
                if (r1 == c0)     dia += fabsf(acc[s2][j][2]);
                if (r1 == c0 + 1) dia += fabsf(acc[s2][j][3]);
            }
        }
        #pragma unroll
        for (int o = 16; o > 0; o >>= 1) {
            tot += __shfl_xor_sync(0xffffffffu, tot, o);
            dia += __shfl_xor_sync(0xffffffffu, dia, o);
        }
        if (lane == 0) { s_tot[wid][s2] = tot; s_dia[wid][s2] = dia; }
    }
    __syncthreads();
    if (tid < 2) {
        const int slot = 2*pair + tid;
        if (slot < NL) {
            float T = 0.f, D = 0.f;
            #pragma unroll
            for (int w = 0; w < 8; w++) { T += s_tot[w][tid]; D += s_dia[w][tid]; }
            float lam = fminf(fmaxf(*lam_ptr, 0.f), 1.f);
            g_score[bh*NL + slot] = lam*D + (1.f - lam)*(T - D);
        }
    }
}

// ---------------- top-18 lag selection: one warp per bh, shuffle argmax ------
__global__ void topk_kernel(const float* __restrict__ lt_lag,
                            const float* __restrict__ beta_ptr)
{
    const int bh = blockIdx.x, l = threadIdx.x; // 32 threads
    float v0 = g_score[bh*NL + l];
    float v1 = g_score[bh*NL + l + 32];
    float selV[KTOP]; int selI[KTOP];
    #pragma unroll
    for (int k = 0; k < KTOP; k++) {
        float bv; int bi;
        if (v0 >= v1) { bv = v0; bi = l; } else { bv = v1; bi = l + 32; }
        #pragma unroll
        for (int o = 16; o > 0; o >>= 1) {
            float ov = __shfl_xor_sync(0xffffffffu, bv, o);
            int   oi = __shfl_xor_sync(0xffffffffu, bi, o);
            if (ov > bv || (ov == bv && oi < bi)) { bv = ov; bi = oi; }
        }
        selV[k] = bv; selI[k] = bi;
        if (bi == l)      v0 = -3.4e38f;
        if (bi == l + 32) v1 = -3.4e38f;
    }
    if (l == 0) {
        float tl = fmaxf(expf(*lt_lag), 1e-4f);
        float mx = selV[0];
        float e[KTOP], esum = 0.f;
        #pragma unroll
        for (int k = 0; k < KTOP; k++) { e[k] = expf((selV[k] - mx)/tl); esum += e[k]; }
        float beta = fminf(fmaxf(*beta_ptr, 0.f), 1.f);
        g_shift[bh*NSLOT]  = 0;
        g_wslot[bh*NSLOT]  = 1.f - beta;
        g_covsel[bh*NSLOT] = NL;
        #pragma unroll
        for (int k = 0; k < KTOP; k++) {
            g_shift[bh*NSLOT + 1 + k]  = lag_of(selI[k]);
            g_wslot[bh*NSLOT + 1 + k]  = beta * e[k] / esum;
            g_covsel[bh*NSLOT + 1 + k] = selI[k];
        }
    }
}

// ---------------- attwT[s][c][d] = pack(weight_s * softmax_c(cov/tau)) -------
__global__ void att_kernel(const float* __restrict__ log_tau_ptr)
{
    __shared__ uint32_t sT[64][65];
    const int s = blockIdx.x, bh = blockIdx.y;
    const int l = g_covsel[bh*NSLOT + s];
    const float w = g_wslot[bh*NSLOT + s];
    const float invtau = 1.0f / fmaxf(expf(*log_tau_ptr), 1e-4f);
    const float* covp = g_cov + ((size_t)bh*(NL+1) + l)*(DhD*DhD);
    uint32_t* outp = g_attwT + ((size_t)bh*NSLOT + s)*(DhD*DhD);
    const int tid = threadIdx.x;
    int warp = tid >> 5, lane = tid & 31;
    for (int d = warp; d < DhD; d += 8) {
        float v0 = covp[d*DhD + lane]      * invtau;
        float v1 = covp[d*DhD + lane + 32] * invtau;
        float m = fmaxf(v0, v1);
        #pragma unroll
        for (int o = 16; o > 0; o >>= 1) m = fmaxf(m, __shfl_xor_sync(0xffffffffu, m, o));
        float e0 = expf(v0 - m), e1 = expf(v1 - m);
        float ss = e0 + e1;
        #pragma unroll
        for (int o = 16; o > 0; o >>= 1) ss += __shfl_xor_sync(0xffffffffu, ss, o);
        float f = w / ss;
        sT[lane][d]      = pack_hilo(e0 * f);
        sT[lane + 32][d] = pack_hilo(e1 * f);
    }
    __syncthreads();
    #pragma unroll
    for (int p = tid; p < 4096; p += 256) {
        outp[p] = sT[p >> 6][p & 63];
    }
}

// ---------------- contrib via HMMA, M=128 t-tile, pipelined ------------------
// out_h[t,c] = sum_s V[(t-shift_s)%T] @ attw_s; 19 slots x 2 k-halves.
__global__ void __launch_bounds__(256) contrib_mma_kernel()
{
    __shared__ __align__(16) char sA[128*CSTRIDE];
    __shared__ __align__(16) char sB[64*CSTRIDE];
    const int bh = blockIdx.y, t0 = blockIdx.x * 128;
    const int bb = bh >> 3, hh = bh & 7;
    const int tid = threadIdx.x, wid = tid >> 5, lane = tid & 31;
    const int rowstrip = wid & 3, colhalf = wid >> 2;
    const int mw = rowstrip * 16;

    float acc[2][4][4] = {};

    const int srowA = tid >> 1, ssegA = tid & 1;
    const int srowB = tid >> 2, ssegB = tid & 3;
    const int arow_ld = mw + (lane & 15), acol_ld = (lane >> 4) * 8;
    const uint32_t sAb = smem_u32(sA), sBb = smem_u32(sB);

    const uint32_t* VPb = g_VP + (size_t)bh*Tdim*DhD;
    uint32_t* dstA = (uint32_t*)(sA + srowA*CSTRIDE) + ssegA*16;
    uint32_t* dstB = (uint32_t*)(sB + srowB*CSTRIDE) + ssegB*8;

    // iteration idx = s*2 + kh over 19 slots x 2 k-halves
    uint4 rA[4], rB[2];
    {
        const int shift = g_shift[bh*NSLOT];
        const uint32_t* ap = g_attwT + (size_t)bh*NSLOT*(DhD*DhD);
        const int srcT = (t0 + srowA - shift + Tdim) & (Tdim - 1);
        const uint32_t* srcA = VPb + (size_t)srcT*DhD + ssegA*16;
        const uint32_t* srcB = ap + srowB*DhD + ssegB*8;
        #pragma unroll
        for (int i = 0; i < 4; i++) rA[i] = *(const uint4*)(srcA + 4*i);
        #pragma unroll
        for (int i = 0; i < 2; i++) rB[i] = *(const uint4*)(srcB + 4*i);
    }

    for (int it = 0; it < NSLOT*2; it++) {
        #pragma unroll
        for (int i = 0; i < 4; i++) *(uint4*)(dstA + 4*i) = rA[i];
        #pragma unroll
        for (int i = 0; i < 2; i++) *(uint4*)(dstB + 4*i) = rB[i];
        __syncthreads();
        if (it < NSLOT*2 - 1) {
            const int nit = it + 1;
            const int s = nit >> 1, kh = nit & 1;
            const int shift = g_shift[bh*NSLOT + s];
            const uint32_t* ap = g_attwT + ((size_t)bh*NSLOT + s)*(DhD*DhD);
            const int srcT = (t0 + srowA - shift + Tdim) & (Tdim - 1);
            const uint32_t* srcA = VPb + (size_t)srcT*DhD + kh*32 + ssegA*16;
            const uint32_t* srcB = ap + srowB*DhD + kh*32 + ssegB*8;
            #pragma unroll
            for (int i = 0; i < 4; i++) rA[i] = *(const uint4*)(srcA + 4*i);
            #pragma unroll
            for (int i = 0; i < 2; i++) rB[i] = *(const uint4*)(srcB + 4*i);
        }
        #pragma unroll
        for (int ks = 0; ks < 4; ks++) {
            const int k0 = ks * 16;
            uint32_t a0[4], a1[4];
            ldsm4(a0, sAb + arow_ld*CSTRIDE + (k0 + acol_ld)*2);
            ldsm4(a1, sAb + (arow_ld + 64)*CSTRIDE + (k0 + acol_ld)*2);
            #pragma unroll
            for (int jt2 = 0; jt2 < 2; jt2++) {
                const int jt = colhalf*2 + jt2;
                const int brow = 16*jt + (lane >> 4)*8 + (lane & 7);
                const int bcol = k0 + ((lane >> 3) & 1)*8;
                uint32_t b4[4];
                ldsm4(b4, sBb + brow*CSTRIDE + bcol*2);
                mma16816(acc[0][2*jt2],   a0, b4);
                mma16816(acc[0][2*jt2+1], a0, b4 + 2);
                mma16816(acc[1][2*jt2],   a1, b4);
                mma16816(acc[1][2*jt2+1], a1, b4 + 2);
                uint32_t bs[4];
                #pragma unroll
                for (int i = 0; i < 4; i++) bs[i] = __byte_perm(b4[i], 0, 0x1032);
                mma16816(acc[0][2*jt2],   a0, bs);
                mma16816(acc[0][2*jt2+1], a0, bs + 2);
                mma16816(acc[1][2*jt2],   a1, bs);
                mma16816(acc[1][2*jt2+1], a1, bs + 2);
            }
        }
        __syncthreads();
    }

    const int g = lane >> 2, tig = lane & 3;
    #pragma unroll
    for (int s2 = 0; s2 < 2; s2++) {
        #pragma unroll
        for (int j = 0; j < 4; j++) {
            const int c0 = colhalf*32 + 8*j + 2*tig;
            #pragma unroll
            for (int half = 0; half < 2; half++) {
                int t = t0 + 64*s2 + mw + g + 8*half;
                size_t row = ((size_t)(bb*Tdim + t))*Ddim + hh*DhD;
                g_oP[row + c0]     = pack_hilo(acc[s2][j][2*half + 0]);
                g_oP[row + c0 + 1] = pack_hilo(acc[s2][j][2*half + 1]);
            }
        }
    }
}

// ---------------- launch ------------------------------------------------------
extern "C" void kernel_launch(void* const* d_in, const int* in_sizes, int n_in,
                              void* d_out, int out_size)
{
    const float* x           = (const float*)d_in[0];
    const float* Wq          = (const float*)d_in[1];
    const float* bq          = (const float*)d_in[2];
    const float* Wk          = (const float*)d_in[3];
    const float* bk          = (const float*)d_in[4];
    const float* Wv          = (const float*)d_in[5];
    const float* bv          = (const float*)d_in[6];
    const float* Wo          = (const float*)d_in[7];
    const float* bo          = (const float*)d_in[8];
    const float* log_tau     = (const float*)d_in[9];
    const float* lambda_auto = (const float*)d_in[10];
    const float* beta_lag    = (const float*)d_in[11];
    const float* log_tau_lag = (const float*)d_in[12];
    float* out = (float*)d_out;

    prep_xw_kernel<<<dim3(8, 8, 5), 256>>>(x, Wq, Wk, Wv, Wo);
    gemm_qkv_mma<<<dim3(Bdim*Tdim/128, Ddim/64, 3), 256>>>(bq, bk, bv);
    prep_qk_kernel<<<dim3(BH, 8, 2), 256>>>();
    cov_mma_kernel<<<dim3(33, BH), 256>>>(lambda_auto);
    topk_kernel<<<BH, 32>>>(log_tau_lag, beta_lag);
    att_kernel<<<dim3(NSLOT, BH), 256>>>(log_tau);
    contrib_mma_kernel<<<dim3(Tdim/128, BH), 256>>>();
    gemm_out_mma<<<dim3(Bdim*Tdim/128, Ddim/64), 256>>>(bo, out);
}

// round 16
// speedup vs baseline: 2.8595x; 1.0196x over previous
#include <cuda_runtime.h>
#include <cuda_bf16.h>
#include <math.h>
#include <stdint.h>

// Problem constants (fixed shapes from the reference)
#define Bdim 4
#define Hdim 8
#define Tdim 512
#define Ddim 512
#define DhD  64
#define NL   64     // number of lag candidates
#define KTOP 18     // top-k lags = 2*ceil(log2(512)) = 18
#define NSLOT 19    // 1 (lag 0 / instantaneous) + KTOP
#define BH   (Bdim*Hdim)

// lags for T=512, LMAX=64: step=7 -> 1,8,...,442 then last forced to 511
__device__ __forceinline__ int lag_of(int l) { return (l == NL-1) ? (Tdim-1) : (1 + 7*l); }

// ---------------- mma.sync helpers ------------------------------------------
__device__ __forceinline__ uint32_t smem_u32(const void* p) {
    uint32_t a;
    asm("{ .reg .u64 t; cvta.to.shared.u64 t, %1; cvt.u32.u64 %0, t; }" : "=r"(a) : "l"(p));
    return a;
}
__device__ __forceinline__ void ldsm4(uint32_t r[4], uint32_t addr) {
    asm volatile("ldmatrix.sync.aligned.m8n8.x4.shared.b16 {%0,%1,%2,%3}, [%4];"
        : "=r"(r[0]), "=r"(r[1]), "=r"(r[2]), "=r"(r[3]) : "r"(addr));
}
__device__ __forceinline__ void mma16816(float d[4], const uint32_t a[4], const uint32_t b[2]) {
    asm volatile("mma.sync.aligned.m16n8k16.row.col.f32.bf16.bf16.f32 "
        "{%0,%1,%2,%3},{%4,%5,%6,%7},{%8,%9},{%0,%1,%2,%3};"
        : "+f"(d[0]), "+f"(d[1]), "+f"(d[2]), "+f"(d[3])
        : "r"(a[0]), "r"(a[1]), "r"(a[2]), "r"(a[3]), "r"(b[0]), "r"(b[1]));
}

// ---------------- pack helper: fp32 -> (hi bf16, lo bf16) u32 ----------------
__device__ __forceinline__ uint32_t pack_hilo(float v) {
    __nv_bfloat16 h = __float2bfloat16(v);
    float hf = __bfloat162float(h);
    __nv_bfloat16 l = __float2bfloat16(v - hf);
    return (uint32_t)(*(unsigned short*)&h) | ((uint32_t)(*(unsigned short*)&l) << 16);
}

// ---------------- scratch (static device memory; no runtime allocation) ----
__device__ float g_Q[BH*Tdim*DhD];                 // 4 MB, raw (pre-norm)
__device__ float g_K[BH*Tdim*DhD];                 // 4 MB, raw (pre-norm)
__device__ uint32_t g_VP[BH*Tdim*DhD];             // 4 MB: V packed (hi,lo), head-major
__device__ uint32_t g_xP[Bdim*Tdim*Ddim];          // 4 MB: x packed (hi,lo), row-major
__device__ uint32_t g_WP[4*Ddim*Ddim];             // 4 MB: W^T packed, z = q,k,v,o
__device__ uint32_t g_oP[Bdim*Tdim*Ddim];          // 4 MB: out_h packed (from contrib)
__device__ uint32_t g_Kph[(size_t)BH*4*DhD*1024];  // 33.5 MB: 4 pre-shift phases, doubled
__device__ uint32_t g_QT[(size_t)BH*DhD*512];      // 4.2 MB: [bh][c][t], (hi,lo) packed
__device__ float g_cov[(size_t)BH*(NL+1)*DhD*DhD]; // 34 MB (slot NL = lag 0)
__device__ float g_score[BH*NL];
__device__ int   g_shift[BH*NSLOT];
__device__ float g_wslot[BH*NSLOT];
__device__ int   g_covsel[BH*NSLOT];
__device__ uint32_t g_attwT[(size_t)BH*NSLOT*DhD*DhD]; // 10 MB: [c][d] packed

// ---------------- prep_xw: pack x (z=4) / transpose+pack weights (z=0..3) ----
__global__ void prep_xw_kernel(const float* __restrict__ x,
                               const float* __restrict__ Wq, const float* __restrict__ Wk,
                               const float* __restrict__ Wv, const float* __restrict__ Wo)
{
    const int z = blockIdx.z;
    const int tid = threadIdx.x;
    if (z < 4) {
        __shared__ uint32_t s[64][65];
        const float* W = (z == 0) ? Wq : (z == 1) ? Wk : (z == 2) ? Wv : Wo;
        uint32_t* dst = g_WP + (size_t)z*Ddim*Ddim;
        const int k0 = blockIdx.x * 64, n0 = blockIdx.y * 64;
        #pragma unroll
        for (int p = tid; p < 4096; p += 256) {
            int r = p >> 6, c = p & 63;   // r: k idx, c: n idx
            s[c][r] = pack_hilo(W[(size_t)(k0 + r)*Ddim + n0 + c]);
        }
        __syncthreads();
        #pragma unroll
        for (int p = tid; p < 4096; p += 256) {
            int n = p >> 6, k = p & 63;
            dst[(size_t)(n0 + n)*Ddim + k0 + k] = s[n][k];
        }
    } else {
        int base = (blockIdx.y*8 + blockIdx.x)*16384 + tid*4;
        #pragma unroll
        for (int i = 0; i < 16; i++) {
            int idx = base + i*1024;
            float4 v = *(const float4*)(x + idx);
            uint4 o;
            o.x = pack_hilo(v.x); o.y = pack_hilo(v.y);
            o.z = pack_hilo(v.z); o.w = pack_hilo(v.w);
            *(uint4*)(g_xP + idx) = o;
        }
    }
}

// ---------------- QKV GEMM via HMMA, M=128 tile, pipelined -------------------
#define CSTRIDE 144
__global__ void __launch_bounds__(256) gemm_qkv_mma(const float* __restrict__ bq,
                                                    const float* __restrict__ bk,
                                                    const float* __restrict__ bv)
{
    __shared__ __align__(16) char sA[128*CSTRIDE];  // 18 KB
    __shared__ __align__(16) char sB[64*CSTRIDE];   // 9 KB
    const int z = blockIdx.z;
    const float* bias = (z == 0) ? bq : (z == 1) ? bk : bv;
    float* C          = (z == 0) ? g_Q : g_K;
    const uint32_t* BP = g_WP + (size_t)z*Ddim*Ddim;
    const int m0 = blockIdx.x * 128, n0 = blockIdx.y * 64;
    const int tid = threadIdx.x, wid = tid >> 5, lane = tid & 31;
    const int rowstrip = wid & 3, colhalf = wid >> 2;
    const int mw = rowstrip * 16;

    float acc[2][4][4] = {};

    const int srowA = tid >> 1, ssegA = tid & 1;
    const int srowB = tid >> 2, ssegB = tid & 3;
    const int arow_ld = mw + (lane & 15), acol_ld = (lane >> 4) * 8;
    const uint32_t sAb = smem_u32(sA), sBb = smem_u32(sB);

    const uint32_t* srcA0 = g_xP + (size_t)(m0 + srowA)*Ddim + ssegA*16;
    const uint32_t* srcB0 = BP + (size_t)(n0 + srowB)*Ddim + ssegB*8;
    uint32_t* dstA = (uint32_t*)(sA + srowA*CSTRIDE) + ssegA*16;
    uint32_t* dstB = (uint32_t*)(sB + srowB*CSTRIDE) + ssegB*8;

    uint4 rA[4], rB[2];
    #pragma unroll
    for (int i = 0; i < 4; i++) rA[i] = *(const uint4*)(srcA0 + 4*i);
    #pragma unroll
    for (int i = 0; i < 2; i++) rB[i] = *(const uint4*)(srcB0 + 4*i);

    for (int chunk = 0; chunk < 16; chunk++) {
        #pragma unroll
        for (int i = 0; i < 4; i++) *(uint4*)(dstA + 4*i) = rA[i];
        #pragma unroll
        for (int i = 0; i < 2; i++) *(uint4*)(dstB + 4*i) = rB[i];
        __syncthreads();
        if (chunk < 15) {
            const uint32_t* srcA = srcA0 + (chunk+1)*32;
            const uint32_t* srcB = srcB0 + (chunk+1)*32;
            #pragma unroll
            for (int i = 0; i < 4; i++) rA[i] = *(const uint4*)(srcA + 4*i);
            #pragma unroll
            for (int i = 0; i < 2; i++) rB[i] = *(const uint4*)(srcB + 4*i);
        }
        #pragma unroll
        for (int ks = 0; ks < 4; ks++) {
            const int k0 = ks * 16;
            uint32_t a0[4], a1[4];
            ldsm4(a0, sAb + arow_ld*CSTRIDE + (k0 + acol_ld)*2);
            ldsm4(a1, sAb + (arow_ld + 64)*CSTRIDE + (k0 + acol_ld)*2);
            #pragma unroll
            for (int jt2 = 0; jt2 < 2; jt2++) {
                const int jt = colhalf*2 + jt2;
                const int brow = 16*jt + (lane >> 4)*8 + (lane & 7);
                const int bcol = k0 + ((lane >> 3) & 1)*8;
                uint32_t b4[4];
                ldsm4(b4, sBb + brow*CSTRIDE + bcol*2);
                mma16816(acc[0][2*jt2],   a0, b4);
                mma16816(acc[0][2*jt2+1], a0, b4 + 2);
                mma16816(acc[1][2*jt2],   a1, b4);
                mma16816(acc[1][2*jt2+1], a1, b4 + 2);
                uint32_t bs[4];
                #pragma unroll
                for (int i = 0; i < 4; i++) bs[i] = __byte_perm(b4[i], 0, 0x1032);
                mma16816(acc[0][2*jt2],   a0, bs);
                mma16816(acc[0][2*jt2+1], a0, bs + 2);
                mma16816(acc[1][2*jt2],   a1, bs);
                mma16816(acc[1][2*jt2+1], a1, bs + 2);
            }
        }
        __syncthreads();
    }

    const int g = lane >> 2, tig = lane & 3;
    #pragma unroll
    for (int s2 = 0; s2 < 2; s2++) {
        #pragma unroll
        for (int j = 0; j < 4; j++) {
            const int c0 = colhalf*32 + 8*j + 2*tig;
            #pragma unroll
            for (int half = 0; half < 2; half++) {
                int m = m0 + 64*s2 + mw + g + 8*half;
                int b = m >> 9, t = m & (Tdim-1);
                #pragma unroll
                for (int e = 0; e < 2; e++) {
                    int n = n0 + c0 + e;
                    int h = n >> 6, c = n & (DhD-1);
                    size_t idx = (((size_t)(b*Hdim + h))*Tdim + t)*DhD + c;
                    float v = acc[s2][j][2*half + e] + bias[n];
                    if (z == 2) g_VP[idx] = pack_hilo(v);
                    else        C[idx] = v;
                }
            }
        }
    }
}

// ---------------- output GEMM via HMMA, M=128 tile, pipelined ----------------
__global__ void __launch_bounds__(256) gemm_out_mma(const float* __restrict__ bo,
                                                    float* __restrict__ out)
{
    __shared__ __align__(16) char sA[128*CSTRIDE];
    __shared__ __align__(16) char sB[64*CSTRIDE];
    const uint32_t* BP = g_WP + (size_t)3*Ddim*Ddim;
    const int m0 = blockIdx.x * 128, n0 = blockIdx.y * 64;
    const int tid = threadIdx.x, wid = tid >> 5, lane = tid & 31;
    const int rowstrip = wid & 3, colhalf = wid >> 2;
    const int mw = rowstrip * 16;

    float acc[2][4][4] = {};

    const int srowA = tid >> 1, ssegA = tid & 1;
    const int srowB = tid >> 2, ssegB = tid & 3;
    const int arow_ld = mw + (lane & 15), acol_ld = (lane >> 4) * 8;
    const uint32_t sAb = smem_u32(sA), sBb = smem_u32(sB);

    const uint32_t* srcA0 = g_oP + (size_t)(m0 + srowA)*Ddim + ssegA*16;
    const uint32_t* srcB0 = BP + (size_t)(n0 + srowB)*Ddim + ssegB*8;
    uint32_t* dstA = (uint32_t*)(sA + srowA*CSTRIDE) + ssegA*16;
    uint32_t* dstB = (uint32_t*)(sB + srowB*CSTRIDE) + ssegB*8;

    uint4 rA[4], rB[2];
    #pragma unroll
    for (int i = 0; i < 4; i++) rA[i] = *(const uint4*)(srcA0 + 4*i);
    #pragma unroll
    for (int i = 0; i < 2; i++) rB[i] = *(const uint4*)(srcB0 + 4*i);

    for (int chunk = 0; chunk < 16; chunk++) {
        #pragma unroll
        for (int i = 0; i < 4; i++) *(uint4*)(dstA + 4*i) = rA[i];
        #pragma unroll
        for (int i = 0; i < 2; i++) *(uint4*)(dstB + 4*i) = rB[i];
        __syncthreads();
        if (chunk < 15) {
            const uint32_t* srcA = srcA0 + (chunk+1)*32;
            const uint32_t* srcB = srcB0 + (chunk+1)*32;
            #pragma unroll
            for (int i = 0; i < 4; i++) rA[i] = *(const uint4*)(srcA + 4*i);
            #pragma unroll
            for (int i = 0; i < 2; i++) rB[i] = *(const uint4*)(srcB + 4*i);
        }
        #pragma unroll
        for (int ks = 0; ks < 4; ks++) {
            const int k0 = ks * 16;
            uint32_t a0[4], a1[4];
            ldsm4(a0, sAb + arow_ld*CSTRIDE + (k0 + acol_ld)*2);
            ldsm4(a1, sAb + (arow_ld + 64)*CSTRIDE + (k0 + acol_ld)*2);
            #pragma unroll
            for (int jt2 = 0; jt2 < 2; jt2++) {
                const int jt = colhalf*2 + jt2;
                const int brow = 16*jt + (lane >> 4)*8 + (lane & 7);
                const int bcol = k0 + ((lane >> 3) & 1)*8;
                uint32_t b4[4];
                ldsm4(b4, sBb + brow*CSTRIDE + bcol*2);
                mma16816(acc[0][2*jt2],   a0, b4);
                mma16816(acc[0][2*jt2+1], a0, b4 + 2);
                mma16816(acc[1][2*jt2],   a1, b4);
                mma16816(acc[1][2*jt2+1], a1, b4 + 2);
                uint32_t bs[4];
                #pragma unroll
                for (int i = 0; i < 4; i++) bs[i] = __byte_perm(b4[i], 0, 0x1032);
                mma16816(acc[0][2*jt2],   a0, bs);
                mma16816(acc[0][2*jt2+1], a0, bs + 2);
                mma16816(acc[1][2*jt2],   a1, bs);
                mma16816(acc[1][2*jt2+1], a1, bs + 2);
            }
        }
        __syncthreads();
    }

    const int g = lane >> 2, tig = lane & 3;
    #pragma unroll
    for (int s2 = 0; s2 < 2; s2++) {
        #pragma unroll
        for (int j = 0; j < 4; j++) {
            const int c0 = colhalf*32 + 8*j + 2*tig;
            const int n = n0 + c0;
            const int r0 = m0 + 64*s2 + mw + g, r1 = r0 + 8;
            *(float2*)(out + (size_t)r0*Ddim + n) =
                make_float2(acc[s2][j][0] + bo[n], acc[s2][j][1] + bo[n+1]);
            *(float2*)(out + (size_t)r1*Ddim + n) =
                make_float2(acc[s2][j][2] + bo[n], acc[s2][j][3] + bo[n+1]);
        }
    }
}

// ---------------- prep_qk: fused sumsq + normalize + transpose + pack --------
__global__ void prep_qk_kernel()
{
    __shared__ float part[256];
    __shared__ float sinv[DhD];
    __shared__ uint32_t s[64][65];
    const int bh = blockIdx.x, t0 = blockIdx.y * 64, isK = blockIdx.z;
    const float* src = (isK ? g_K : g_Q) + (size_t)bh*Tdim*DhD;
    const int tid = threadIdx.x;
    const int d = tid & 63, g = tid >> 6;
    float ss = 0.f;
    for (int t = g*128; t < (g+1)*128; t++) {
        float v = src[t*DhD + d]; ss = fmaf(v, v, ss);
    }
    part[tid] = ss;
    __syncthreads();
    if (tid < 64) {
        float tot = part[d] + part[d+64] + part[d+128] + part[d+192];
        sinv[d] = 1.0f / sqrtf(fmaxf(tot, 1e-8f));
    }
    __syncthreads();
    #pragma unroll
    for (int p = tid; p < 4096; p += 256) {
        int r = p >> 6, dd = p & 63;
        s[dd][r] = pack_hilo(src[(t0 + r)*DhD + dd] * sinv[dd]);
    }
    __syncthreads();
    if (!isK) {
        uint32_t* dst = g_QT + (size_t)bh*DhD*512;
        #pragma unroll
        for (int p = tid; p < 4096; p += 256) {
            int dd = p >> 6, t = p & 63;
            dst[(size_t)dd*512 + t0 + t] = s[dd][t];
        }
    } else {
        uint32_t* dst = g_Kph + (size_t)bh*4*DhD*1024;
        #pragma unroll
        for (int ph = 0; ph < 4; ph++) {
            for (int p = tid; p < 4096; p += 256) {
                int dd = p >> 6, t = p & 63;
                uint32_t w = s[dd][t];
                int tp = (t0 + t - ph) & (Tdim - 1);
                uint32_t* row = dst + ((size_t)ph*DhD + dd)*1024;
                row[tp]       = w;
                row[tp + 512] = w;
            }
        }
    }
}

// ---------------- cov via HMMA: 4 lag slots per block (M=256) ----------------
// Warp w: rows [16w,16w+16) (grp0) and [16w+128,16w+144) (grp1), all 64 cols.
__global__ void __launch_bounds__(256, 2) cov_mma_kernel(const float* __restrict__ lam_ptr)
{
    __shared__ __align__(16) char sA[256*CSTRIDE];  // 36 KB
    __shared__ __align__(16) char sB[64*CSTRIDE];   // 9 KB
    __shared__ float s_tot[8][2], s_dia[8][2];

    const int quad = blockIdx.x, bh = blockIdx.y;   // slots 4*quad..4*quad+3
    const int tid = threadIdx.x, wid = tid >> 5, lane = tid & 31;
    const int mw = wid * 16;

    float acc[2][8][4] = {};

    // A staging: warp wid stages rows [32*wid, 32*wid+32) -> slot quadrant wid>>1
    const int slotq = wid >> 1;
    const int slotIdA = 4*quad + slotq;
    const int lagA = (slotIdA >= NL) ? 0 : lag_of(slotIdA);
    const int phA = (Tdim - lagA) & 3;
    const int aseg = lane & 7;                       // 8 segs of 4 u32 per row
    const uint32_t* KBase = g_Kph + ((size_t)bh*4 + phA)*DhD*1024;

    // B staging
    const int srowB = tid >> 2, ssegB = tid & 3;
    const uint32_t* QTr = g_QT + ((size_t)bh*DhD + srowB)*512;
    uint32_t* dstB = (uint32_t*)(sB + srowB*CSTRIDE) + ssegB*8;

    const int arow_ld = mw + (lane & 15), acol_ld = (lane >> 4) * 8;
    const uint32_t sAb = smem_u32(sA), sBb = smem_u32(sB);

    uint4 rB[2];
    {
        const uint32_t* srcB = QTr + ssegB*8;
        rB[0] = *(const uint4*)srcB; rB[1] = *(const uint4*)(srcB + 4);
    }

    for (int chunk = 0; chunk < 16; chunk++) {
        const int t0 = chunk * 32;
        *(uint4*)dstB = rB[0]; *(uint4*)(dstB + 4) = rB[1];
        {
            const int st = (t0 - lagA + Tdim) & (Tdim - 1);
            const int off = (st - phA) + aseg*4;
            #pragma unroll
            for (int p = 0; p < 8; p++) {
                const int row = wid*32 + p*4 + (lane >> 3);
                const int dA = row & 63;
                *(uint4*)(sA + row*CSTRIDE + aseg*16) =
                    *(const uint4*)(KBase + (size_t)dA*1024 + off);
            }
        }
        __syncthreads();
        if (chunk < 15) {
            const uint32_t* srcB = QTr + (chunk+1)*32 + ssegB*8;
            rB[0] = *(const uint4*)srcB; rB[1] = *(const uint4*)(srcB + 4);
        }
        #pragma unroll
        for (int ks = 0; ks < 4; ks++) {
            const int k0 = ks * 16;
            uint32_t a0[4], a1[4];
            ldsm4(a0, sAb + arow_ld*CSTRIDE + (k0 + acol_ld)*2);
            ldsm4(a1, sAb + (arow_ld + 128)*CSTRIDE + (k0 + acol_ld)*2);
            #pragma unroll
            for (int jt = 0; jt < 4; jt++) {
                const int brow = 16*jt + (lane >> 4)*8 + (lane & 7);
                const int bcol = k0 + ((lane >> 3) & 1)*8;
                uint32_t b4[4];
                ldsm4(b4, sBb + brow*CSTRIDE + bcol*2);
                mma16816(acc[0][2*jt],   a0, b4);
                mma16816(acc[0][2*jt+1], a0, b4 + 2);
                mma16816(acc[1][2*jt],   a1, b4);
                mma16816(acc[1][2*jt+1], a1, b4 + 2);
                uint32_t bs[4];
                #pragma unroll
                for (int i = 0; i < 4; i++) bs[i] = __byte_perm(b4[i], 0, 0x1032);
                mma16816(acc[0][2*jt],   a0, bs);
                mma16816(acc[0][2*jt+1], a0, bs + 2);
                mma16816(acc[1][2*jt],   a1, bs);
                mma16816(acc[1][2*jt+1], a1, bs + 2);
            }
        }
        __syncthreads();
    }

    const int g = lane >> 2, tig = lane & 3;
    #pragma unroll
    for (int grp = 0; grp < 2; grp++) {
        const int grow = mw + 128*grp;
        const int slot = 4*quad + (grow >> 6);
        const int d0 = (grow & 63) + g, d1 = d0 + 8;
        float tot = 0.f, dia = 0.f;
        if (slot <= NL) {
            float* covp = g_cov + ((size_t)bh*(NL+1) + slot)*(DhD*DhD);
            #pragma unroll
            for (int j = 0; j < 8; j++) {
                const int c0 = 8*j + 2*tig;
                *(float2*)(covp + d0*DhD + c0) = make_float2(acc[grp][j][0], acc[grp][j][1]);
                *(float2*)(covp + d1*DhD + c0) = make_float2(acc[grp][j][2], acc[grp][j][3]);
                tot += fabsf(acc[grp][j][0]) + fabsf(acc[grp][j][1])
                     + fabsf(acc[grp][j][2]) + fabsf(acc[grp][j][3]);
                if (d0 == c0)     dia += fabsf(acc[grp][j][0]);
                if (d0 == c0 + 1) dia += fabsf(acc[grp][j][1]);
                if (d1 == c0)     dia += fabsf(acc[grp][j][2]);
                if (d1 == c0 + 1) dia += fabsf(acc[grp][j][3]);
            }
        }
        #pragma unroll
        for (int o = 16; o > 0; o >>= 1) {
            tot += __shfl_xor_sync(0xffffffffu, tot, o);
            dia += __shfl_xor_sync(0xffffffffu, dia, o);
        }
        if (lane == 0) { s_tot[wid][grp] = tot; s_dia[wid][grp] = dia; }
    }
    __syncthreads();
    if (tid < 4) {
        const int slot = 4*quad + tid;
        if (slot < NL) {
            const int grp = tid >> 1, wbase = (tid & 1)*4;
            float T = 0.f, D = 0.f;
            #pragma unroll
            for (int i = 0; i < 4; i++) { T += s_tot[wbase+i][grp]; D += s_dia[wbase+i][grp]; }
            float lam = fminf(fmaxf(*lam_ptr, 0.f), 1.f);
            g_score[bh*NL + slot] = lam*D + (1.f - lam)*(T - D);
        }
    }
}

// ---------------- top-18 lag selection: one warp per bh, shuffle argmax ------
__global__ void topk_kernel(const float* __restrict__ lt_lag,
                            const float* __restrict__ beta_ptr)
{
    const int bh = blockIdx.x, l = threadIdx.x; // 32 threads
    float v0 = g_score[bh*NL + l];
    float v1 = g_score[bh*NL + l + 32];
    float selV[KTOP]; int selI[KTOP];
    #pragma unroll
    for (int k = 0; k < KTOP; k++) {
        float bv; int bi;
        if (v0 >= v1) { bv = v0; bi = l; } else { bv = v1; bi = l + 32; }
        #pragma unroll
        for (int o = 16; o > 0; o >>= 1) {
            float ov = __shfl_xor_sync(0xffffffffu, bv, o);
            int   oi = __shfl_xor_sync(0xffffffffu, bi, o);
            if (ov > bv || (ov == bv && oi < bi)) { bv = ov; bi = oi; }
        }
        selV[k] = bv; selI[k] = bi;
        if (bi == l)      v0 = -3.4e38f;
        if (bi == l + 32) v1 = -3.4e38f;
    }
    if (l == 0) {
        float tl = fmaxf(expf(*lt_lag), 1e-4f);
        float mx = selV[0];
        float e[KTOP], esum = 0.f;
        #pragma unroll
        for (int k = 0; k < KTOP; k++) { e[k] = expf((selV[k] - mx)/tl); esum += e[k]; }
        float beta = fminf(fmaxf(*beta_ptr, 0.f), 1.f);
        g_shift[bh*NSLOT]  = 0;
        g_wslot[bh*NSLOT]  = 1.f - beta;
        g_covsel[bh*NSLOT] = NL;
        #pragma unroll
        for (int k = 0; k < KTOP; k++) {
            g_shift[bh*NSLOT + 1 + k]  = lag_of(selI[k]);
            g_wslot[bh*NSLOT + 1 + k]  = beta * e[k] / esum;
            g_covsel[bh*NSLOT + 1 + k] = selI[k];
        }
    }
}

// ---------------- attwT[s][c][d] = pack(weight_s * softmax_c(cov/tau)) -------
__global__ void att_kernel(const float* __restrict__ log_tau_ptr)
{
    __shared__ uint32_t sT[64][65];
    const int s = blockIdx.x, bh = blockIdx.y;
    const int l = g_covsel[bh*NSLOT + s];
    const float w = g_wslot[bh*NSLOT + s];
    const float invtau = 1.0f / fmaxf(expf(*log_tau_ptr), 1e-4f);
    const float* covp = g_cov + ((size_t)bh*(NL+1) + l)*(DhD*DhD);
    uint32_t* outp = g_attwT + ((size_t)bh*NSLOT + s)*(DhD*DhD);
    const int tid = threadIdx.x;
    int warp = tid >> 5, lane = tid & 31;
    for (int d = warp; d < DhD; d += 8) {
        float v0 = covp[d*DhD + lane]      * invtau;
        float v1 = covp[d*DhD + lane + 32] * invtau;
        float m = fmaxf(v0, v1);
        #pragma unroll
        for (int o = 16; o > 0; o >>= 1) m = fmaxf(m, __shfl_xor_sync(0xffffffffu, m, o));
        float e0 = expf(v0 - m), e1 = expf(v1 - m);
        float ss = e0 + e1;
        #pragma unroll
        for (int o = 16; o > 0; o >>= 1) ss += __shfl_xor_sync(0xffffffffu, ss, o);
        float f = w / ss;
        sT[lane][d]      = pack_hilo(e0 * f);
        sT[lane + 32][d] = pack_hilo(e1 * f);
    }
    __syncthreads();
    #pragma unroll
    for (int p = tid; p < 4096; p += 256) {
        outp[p] = sT[p >> 6][p & 63];
    }
}

// ---------------- contrib via HMMA, M=128 t-tile, pipelined ------------------
__global__ void __launch_bounds__(256) contrib_mma_kernel()
{
    __shared__ __align__(16) char sA[128*CSTRIDE];
    __shared__ __align__(16) char sB[64*CSTRIDE];
    const int bh = blockIdx.y, t0 = blockIdx.x * 128;
    const int bb = bh >> 3, hh = bh & 7;
    const int tid = threadIdx.x, wid = tid >> 5, lane = tid & 31;
    const int rowstrip = wid & 3, colhalf = wid >> 2;
    const int mw = rowstrip * 16;

    float acc[2][4][4] = {};

    const int srowA = tid >> 1, ssegA = tid & 1;
    const int srowB = tid >> 2, ssegB = tid & 3;
    const int arow_ld = mw + (lane & 15), acol_ld = (lane >> 4) * 8;
    const uint32_t sAb = smem_u32(sA), sBb = smem_u32(sB);

    const uint32_t* VPb = g_VP + (size_t)bh*Tdim*DhD;
    uint32_t* dstA = (uint32_t*)(sA + srowA*CSTRIDE) + ssegA*16;
    uint32_t* dstB = (uint32_t*)(sB + srowB*CSTRIDE) + ssegB*8;

    uint4 rA[4], rB[2];
    {
        const int shift = g_shift[bh*NSLOT];
        const uint32_t* ap = g_attwT + (size_t)bh*NSLOT*(DhD*DhD);
        const int srcT = (t0 + srowA - shift + Tdim) & (Tdim - 1);
        const uint32_t* srcA = VPb + (size_t)srcT*DhD + ssegA*16;
        const uint32_t* srcB = ap + srowB*DhD + ssegB*8;
        #pragma unroll
        for (int i = 0; i < 4; i++) rA[i] = *(const uint4*)(srcA + 4*i);
        #pragma unroll
        for (int i = 0; i < 2; i++) rB[i] = *(const uint4*)(srcB + 4*i);
    }

    for (int it = 0; it < NSLOT*2; it++) {
        #pragma unroll
        for (int i = 0; i < 4; i++) *(uint4*)(dstA + 4*i) = rA[i];
        #pragma unroll
        for (int i = 0; i < 2; i++) *(uint4*)(dstB + 4*i) = rB[i];
        __syncthreads();
        if (it < NSLOT*2 - 1) {
            const int nit = it + 1;
            const int s = nit >> 1, kh = nit & 1;
            const int shift = g_shift[bh*NSLOT + s];
            const uint32_t* ap = g_attwT + ((size_t)bh*NSLOT + s)*(DhD*DhD);
            const int srcT = (t0 + srowA - shift + Tdim) & (Tdim - 1);
            const uint32_t* srcA = VPb + (size_t)srcT*DhD + kh*32 + ssegA*16;
            const uint32_t* srcB = ap + srowB*DhD + kh*32 + ssegB*8;
            #pragma unroll
            for (int i = 0; i < 4; i++) rA[i] = *(const uint4*)(srcA + 4*i);
            #pragma unroll
            for (int i = 0; i < 2; i++) rB[i] = *(const uint4*)(srcB + 4*i);
        }
        #pragma unroll
        for (int ks = 0; ks < 4; ks++) {
            const int k0 = ks * 16;
            uint32_t a0[4], a1[4];
            ldsm4(a0, sAb + arow_ld*CSTRIDE + (k0 + acol_ld)*2);
            ldsm4(a1, sAb + (arow_ld + 64)*CSTRIDE + (k0 + acol_ld)*2);
            #pragma unroll
            for (int jt2 = 0; jt2 < 2; jt2++) {
                const int jt = colhalf*2 + jt2;
                const int brow = 16*jt + (lane >> 4)*8 + (lane & 7);
                const int bcol = k0 + ((lane >> 3) & 1)*8;
                uint32_t b4[4];
                ldsm4(b4, sBb + brow*CSTRIDE + bcol*2);
                mma16816(acc[0][2*jt2],   a0, b4);
                mma16816(acc[0][2*jt2+1], a0, b4 + 2);
                mma16816(acc[1][2*jt2],   a1, b4);
                mma16816(acc[1][2*jt2+1], a1, b4 + 2);
                uint32_t bs[4];
                #pragma unroll
                for (int i = 0; i < 4; i++) bs[i] = __byte_perm(b4[i], 0, 0x1032);
                mma16816(acc[0][2*jt2],   a0, bs);
                mma16816(acc[0][2*jt2+1], a0, bs + 2);
                mma16816(acc[1][2*jt2],   a1, bs);
                mma16816(acc[1][2*jt2+1], a1, bs + 2);
            }
        }
        __syncthreads();
    }

    const int g = lane >> 2, tig = lane & 3;
    #pragma unroll
    for (int s2 = 0; s2 < 2; s2++) {
        #pragma unroll
        for (int j = 0; j < 4; j++) {
            const int c0 = colhalf*32 + 8*j + 2*tig;
            #pragma unroll
            for (int half = 0; half < 2; half++) {
                int t = t0 + 64*s2 + mw + g + 8*half;
                size_t row = ((size_t)(bb*Tdim + t))*Ddim + hh*DhD;
                g_oP[row + c0]     = pack_hilo(acc[s2][j][2*half + 0]);
                g_oP[row + c0 + 1] = pack_hilo(acc[s2][j][2*half + 1]);
            }
        }
    }
}

// ---------------- launch ------------------------------------------------------
extern "C" void kernel_launch(void* const* d_in, const int* in_sizes, int n_in,
                              void* d_out, int out_size)
{
    const float* x           = (const float*)d_in[0];
    const float* Wq          = (const float*)d_in[1];
    const float* bq          = (const float*)d_in[2];
    const float* Wk          = (const float*)d_in[3];
    const float* bk          = (const float*)d_in[4];
    const float* Wv          = (const float*)d_in[5];
    const float* bv          = (const float*)d_in[6];
    const float* Wo          = (const float*)d_in[7];
    const float* bo          = (const float*)d_in[8];
    const float* log_tau     = (const float*)d_in[9];
    const float* lambda_auto = (const float*)d_in[10];
    const float* beta_lag    = (const float*)d_in[11];
    const float* log_tau_lag = (const float*)d_in[12];
    float* out = (float*)d_out;

    prep_xw_kernel<<<dim3(8, 8, 5), 256>>>(x, Wq, Wk, Wv, Wo);
    gemm_qkv_mma<<<dim3(Bdim*Tdim/128, Ddim/64, 3), 256>>>(bq, bk, bv);
    prep_qk_kernel<<<dim3(BH, 8, 2), 256>>>();
    cov_mma_kernel<<<dim3(17, BH), 256>>>(lambda_auto);
    topk_kernel<<<BH, 32>>>(log_tau_lag, beta_lag);
    att_kernel<<<dim3(NSLOT, BH), 256>>>(log_tau);
    contrib_mma_kernel<<<dim3(Tdim/128, BH), 256>>>();
    gemm_out_mma<<<dim3(Bdim*Tdim/128, Ddim/64), 256>>>(bo, out);
}